// round 4
// baseline (speedup 1.0000x reference)
#include <cuda_runtime.h>
#include <cuda_fp16.h>

// ---------------- problem constants ----------------
#define UN  100000
#define INC 50000
#define NN  150000
#define DD  64
#define KK  128
#define EE  1250000
#define LL  2

typedef unsigned long long u64;

// ---------------- device scratch (static; no allocations) ----------------
__device__ float g_ekA[NN * DD];
__device__ float g_ekB[NN * DD];
__device__ float g_accum[NN * DD];
__device__ int   g_cnt[NN];
__device__ int   g_rowptr[NN + 1];
__device__ int   g_wp[NN];
__device__ int   g_ecol[EE];
__device__ float g_eval[EE];
// packed normalized vectors: per node 16 chunks of 16B; chunk c = {gnn̂[4c..4c+3], itl̂[4c..4c+3]} as fp16
__device__ __half g_nrm[NN * 128];
__device__ int   g_bsum[160];
__device__ int   g_boff[160];

// ---------------- f32x2 packed-math helpers ----------------
__device__ __forceinline__ u64 pk2(float x, float y) {
    u64 r; asm("mov.b64 %0, {%1, %2};" : "=l"(r) : "f"(x), "f"(y)); return r;
}
__device__ __forceinline__ u64 pk1(float x) { return pk2(x, x); }
__device__ __forceinline__ float2 up2(u64 v) {
    float2 r; asm("mov.b64 {%0, %1}, %2;" : "=f"(r.x), "=f"(r.y) : "l"(v)); return r;
}
__device__ __forceinline__ u64 fma2(u64 a, u64 b, u64 c) {
    u64 d; asm("fma.rn.f32x2 %0, %1, %2, %3;" : "=l"(d) : "l"(a), "l"(b), "l"(c)); return d;
}

// ---------------- CSR build ----------------
__global__ void zero_cnt_kernel() {
    int i = blockIdx.x * blockDim.x + threadIdx.x;
    if (i < NN) g_cnt[i] = 0;
}

__global__ void hist_kernel(const int* __restrict__ h) {
    int e = blockIdx.x * blockDim.x + threadIdx.x;
    if (e < EE) atomicAdd(&g_cnt[h[e]], 1);
}

__global__ void reduce_cnt_kernel() {
    __shared__ int s[1024];
    int tid = threadIdx.x;
    int idx = blockIdx.x * 1024 + tid;
    s[tid] = (idx < NN) ? g_cnt[idx] : 0;
    __syncthreads();
    for (int o = 512; o > 0; o >>= 1) {
        if (tid < o) s[tid] += s[tid + o];
        __syncthreads();
    }
    if (tid == 0) g_bsum[blockIdx.x] = s[0];
}

__global__ void scan_bsums_kernel(int nblk) {
    __shared__ int s[160];
    int tid = threadIdx.x;
    if (tid < nblk) s[tid] = g_bsum[tid];
    __syncthreads();
    if (tid == 0) {
        int run = 0;
        for (int i = 0; i < nblk; i++) { int t = s[i]; s[i] = run; run += t; }
    }
    __syncthreads();
    if (tid < nblk) g_boff[tid] = s[tid];
}

__global__ void apply_scan_kernel() {
    __shared__ int s[1024];
    int tid = threadIdx.x;
    int idx = blockIdx.x * 1024 + tid;
    int v = (idx < NN) ? g_cnt[idx] : 0;
    s[tid] = v;
    __syncthreads();
    for (int off = 1; off < 1024; off <<= 1) {
        int t = (tid >= off) ? s[tid - off] : 0;
        __syncthreads();
        s[tid] += t;
        __syncthreads();
    }
    int excl = s[tid] - v + g_boff[blockIdx.x];
    if (idx < NN) { g_rowptr[idx] = excl; g_wp[idx] = excl; }
    if (blockIdx.x == 0 && tid == 0) g_rowptr[NN] = EE;
}

__global__ void scatter_kernel(const int* __restrict__ h, const int* __restrict__ t,
                               const float* __restrict__ adj) {
    int e = blockIdx.x * blockDim.x + threadIdx.x;
    if (e >= EE) return;
    int hn = h[e];
    int p  = atomicAdd(&g_wp[hn], 1);
    g_ecol[p] = t[e];
    g_eval[p] = adj[e];
}

// ---------------- init ----------------
__global__ void init_ek_kernel(const float4* __restrict__ ue, const float4* __restrict__ ie) {
    int i = blockIdx.x * blockDim.x + threadIdx.x;
    const int TOT = NN * DD / 4, UD4 = UN * DD / 4;
    if (i >= TOT) return;
    float4 v = (i < UD4) ? ue[i] : ie[i - UD4];
    ((float4*)g_ekA)[i]   = v;
    ((float4*)g_accum)[i] = v;
}

// ---------------- SpMM: gnn = A @ ek (16-lane group per node); writes gnn + fp16 gnn̂ ----------------
__global__ void __launch_bounds__(256) spmm_gnn_kernel(int layer, float* __restrict__ out) {
    const float* __restrict__ ekIn = layer ? g_ekB : g_ekA;
    int t0 = blockIdx.x * blockDim.x + threadIdx.x;
    int g = t0 >> 4;
    int l = threadIdx.x & 15;
    unsigned m = 0xFFFFu << (threadIdx.x & 16);
    int s = g_rowptr[g], e = g_rowptr[g + 1];
    float4 acc = make_float4(0.f, 0.f, 0.f, 0.f);

    int p = s;
    int   tt = 0; float v = 0.f; float4 x = make_float4(0.f, 0.f, 0.f, 0.f);
    if (p < e) {
        tt = __ldg(g_ecol + p);
        v  = __ldg(g_eval + p);
        x  = *(const float4*)(ekIn + (size_t)tt * DD + l * 4);
    }
    while (p < e) {
        float  cv = v;
        float4 cx = x;
        p++;
        if (p < e) {
            tt = __ldg(g_ecol + p);
            v  = __ldg(g_eval + p);
            x  = *(const float4*)(ekIn + (size_t)tt * DD + l * 4);
        }
        acc.x = fmaf(cv, cx.x, acc.x);
        acc.y = fmaf(cv, cx.y, acc.y);
        acc.z = fmaf(cv, cx.z, acc.z);
        acc.w = fmaf(cv, cx.w, acc.w);
    }
    *(float4*)(out + (size_t)g * DD + l * 4) = acc;
    float sg = acc.x * acc.x + acc.y * acc.y + acc.z * acc.z + acc.w * acc.w;
#pragma unroll
    for (int o = 8; o > 0; o >>= 1) sg += __shfl_xor_sync(m, sg, o);
    float inv = 1.f / fmaxf(sqrtf(sg), 1e-12f);
    __half2 h0 = __floats2half2_rn(acc.x * inv, acc.y * inv);
    __half2 h1 = __floats2half2_rn(acc.z * inv, acc.w * inv);
    uint2 u;
    u.x = *(unsigned*)&h0;
    u.y = *(unsigned*)&h1;
    ((uint2*)g_nrm)[(size_t)g * 32 + l * 2] = u;   // g-part of chunk l
}

// ---------------- fused intent: softmax(ek@W)@W^T per 128-row tile; writes itl + fp16 itl̂ ----------------
#define TM   128
#define ASP2 264            // duplicated A-tile row pitch (floats)
#define BTP  68
#define PSP  132
#define IT_SMEM_FLOATS (64 * ASP2 + 64 * KK + KK * BTP + TM * PSP)
#define IT_SMEM_BYTES  (IT_SMEM_FLOATS * 4)

__global__ void __launch_bounds__(256, 1)
intent_kernel(int layer, const float* __restrict__ W, float* __restrict__ outIntl,
              int nodeBase, int nodeCount) {
    const float* __restrict__ ekIn = layer ? g_ekB : g_ekA;
    extern __shared__ float sm[];
    float* As2 = sm;                   // [64][ASP2] A^T tile, each value duplicated (a,a)
    float* Bs  = As2 + 64 * ASP2;      // [64][128]  W
    float* Bt  = Bs + 64 * KK;         // [128][BTP] W^T
    float* Ps  = Bt + KK * BTP;        // [128][PSP] logits -> probs

    int tid = threadIdx.x;
    int tx = tid & 15, ty = tid >> 4;
    int rowTile = blockIdx.x * TM;

#pragma unroll
    for (int it = 0; it < 8; it++) {
        int i = tid + it * 256;
        float4 v = ((const float4*)W)[i];
        int d = i >> 5;
        int k = (i << 2) & 127;
        *(float4*)(Bs + d * KK + k) = v;
        Bt[(k + 0) * BTP + d] = v.x;
        Bt[(k + 1) * BTP + d] = v.y;
        Bt[(k + 2) * BTP + d] = v.z;
        Bt[(k + 3) * BTP + d] = v.w;
    }
#pragma unroll
    for (int it = 0; it < 8; it++) {
        int i  = tid + it * 256;
        int rr = i >> 4;
        int d0 = (i << 2) & 63;
        float4 v = make_float4(0.f, 0.f, 0.f, 0.f);
        int r = rowTile + rr;
        if (r < nodeCount) v = *(const float4*)(ekIn + (size_t)(nodeBase + r) * DD + d0);
        ((u64*)(As2 + (d0 + 0) * ASP2))[rr] = pk1(v.x);
        ((u64*)(As2 + (d0 + 1) * ASP2))[rr] = pk1(v.y);
        ((u64*)(As2 + (d0 + 2) * ASP2))[rr] = pk1(v.z);
        ((u64*)(As2 + (d0 + 3) * ASP2))[rr] = pk1(v.w);
    }
    __syncthreads();

    const int r0 = ty * 8, k0 = tx * 8;

    // GEMM1 (packed f32x2, broadcast pairs straight from smem)
    u64 acc[8][4];
#pragma unroll
    for (int i = 0; i < 8; i++)
#pragma unroll
        for (int j = 0; j < 4; j++) acc[i][j] = 0ull;

#pragma unroll 4
    for (int d = 0; d < DD; d++) {
        const ulonglong2* a2 = (const ulonglong2*)(As2 + d * ASP2 + r0 * 2);
        ulonglong2 A0 = a2[0], A1 = a2[1], A2 = a2[2], A3 = a2[3];
        const ulonglong2* bb = (const ulonglong2*)(Bs + d * KK + k0);
        ulonglong2 B0 = bb[0], B1 = bb[1];
        u64 av[8] = {A0.x, A0.y, A1.x, A1.y, A2.x, A2.y, A3.x, A3.y};
        u64 bv[4] = {B0.x, B0.y, B1.x, B1.y};
#pragma unroll
        for (int i = 0; i < 8; i++) {
            acc[i][0] = fma2(av[i], bv[0], acc[i][0]);
            acc[i][1] = fma2(av[i], bv[1], acc[i][1]);
            acc[i][2] = fma2(av[i], bv[2], acc[i][2]);
            acc[i][3] = fma2(av[i], bv[3], acc[i][3]);
        }
    }
#pragma unroll
    for (int i = 0; i < 8; i++) {
        u64* pr = (u64*)(Ps + (r0 + i) * PSP + k0);
        pr[0] = acc[i][0]; pr[1] = acc[i][1]; pr[2] = acc[i][2]; pr[3] = acc[i][3];
    }
    __syncthreads();

    // row softmax
    int warp = tid >> 5, lane = tid & 31;
    for (int rr = warp; rr < TM; rr += 8) {
        float4 v = *(float4*)(Ps + rr * PSP + lane * 4);
        float mx = fmaxf(fmaxf(v.x, v.y), fmaxf(v.z, v.w));
#pragma unroll
        for (int o = 16; o > 0; o >>= 1) mx = fmaxf(mx, __shfl_xor_sync(0xffffffffu, mx, o));
        float e0 = __expf(v.x - mx), e1 = __expf(v.y - mx);
        float e2 = __expf(v.z - mx), e3 = __expf(v.w - mx);
        float sum = e0 + e1 + e2 + e3;
#pragma unroll
        for (int o = 16; o > 0; o >>= 1) sum += __shfl_xor_sync(0xffffffffu, sum, o);
        float inv = 1.0f / sum;
        *(float4*)(Ps + rr * PSP + lane * 4) = make_float4(e0 * inv, e1 * inv, e2 * inv, e3 * inv);
    }
    __syncthreads();

    // GEMM2 (packed f32x2)
    u64 acc2[8][2];
#pragma unroll
    for (int i = 0; i < 8; i++) { acc2[i][0] = 0ull; acc2[i][1] = 0ull; }
    const int d0o = tx * 4;
#pragma unroll 2
    for (int k = 0; k < KK; k += 4) {
        float4 p[8];
#pragma unroll
        for (int i = 0; i < 8; i++) p[i] = *(const float4*)(Ps + (r0 + i) * PSP + k);
        ulonglong2 C0 = *(const ulonglong2*)(Bt + (k + 0) * BTP + d0o);
        ulonglong2 C1 = *(const ulonglong2*)(Bt + (k + 1) * BTP + d0o);
        ulonglong2 C2 = *(const ulonglong2*)(Bt + (k + 2) * BTP + d0o);
        ulonglong2 C3 = *(const ulonglong2*)(Bt + (k + 3) * BTP + d0o);
#pragma unroll
        for (int i = 0; i < 8; i++) {
            u64 t;
            t = pk1(p[i].x); acc2[i][0] = fma2(t, C0.x, acc2[i][0]); acc2[i][1] = fma2(t, C0.y, acc2[i][1]);
            t = pk1(p[i].y); acc2[i][0] = fma2(t, C1.x, acc2[i][0]); acc2[i][1] = fma2(t, C1.y, acc2[i][1]);
            t = pk1(p[i].z); acc2[i][0] = fma2(t, C2.x, acc2[i][0]); acc2[i][1] = fma2(t, C2.y, acc2[i][1]);
            t = pk1(p[i].w); acc2[i][0] = fma2(t, C3.x, acc2[i][0]); acc2[i][1] = fma2(t, C3.y, acc2[i][1]);
        }
    }
    // epilogue: store + itl̂ fp16 write
#pragma unroll
    for (int i = 0; i < 8; i++) {
        float2 lo = up2(acc2[i][0]);
        float2 hi = up2(acc2[i][1]);
        float4 o = make_float4(lo.x, lo.y, hi.x, hi.y);
        int r = rowTile + r0 + i;
        bool ok = (r < nodeCount);
        if (ok) *(float4*)(outIntl + (size_t)(nodeBase + r) * DD + d0o) = o;
        float ns = o.x * o.x + o.y * o.y + o.z * o.z + o.w * o.w;
#pragma unroll
        for (int off = 8; off > 0; off >>= 1) ns += __shfl_xor_sync(0xffffffffu, ns, off);
        float inv = 1.f / fmaxf(sqrtf(ns), 1e-12f);
        if (ok) {
            __half2 h0 = __floats2half2_rn(o.x * inv, o.y * inv);
            __half2 h1 = __floats2half2_rn(o.z * inv, o.w * inv);
            uint2 u;
            u.x = *(unsigned*)&h0;
            u.y = *(unsigned*)&h1;
            ((uint2*)g_nrm)[(size_t)(nodeBase + r) * 32 + tx * 2 + 1] = u;  // i-part of chunk tx
        }
    }
}

// ---------------- fused alpha + spmm2 + combine (16-lane group per node) ----------------
__global__ void __launch_bounds__(256)
fused_alpha_kernel(int layer,
                   const float* __restrict__ gnn, const float* __restrict__ itl,
                   float* __restrict__ gaa, float* __restrict__ iaa,
                   float* __restrict__ finalOut) {
    const float* __restrict__ ekIn  = layer ? g_ekB : g_ekA;
    float*       __restrict__ ekOut = layer ? g_ekA : g_ekB;
    int t0 = blockIdx.x * blockDim.x + threadIdx.x;
    int g = t0 >> 4;
    int l = threadIdx.x & 15;
    unsigned m = 0xFFFFu << (threadIdx.x & 16);
    size_t ro = (size_t)g * DD + l * 4;
    const uint4* __restrict__ nrm4 = (const uint4*)g_nrm;

    uint4 hn = nrm4[(size_t)g * 16 + l];
    float2 hg01 = __half22float2(*(__half2*)&hn.x);
    float2 hg23 = __half22float2(*(__half2*)&hn.y);
    float2 hi01 = __half22float2(*(__half2*)&hn.z);
    float2 hi23 = __half22float2(*(__half2*)&hn.w);

    float4 AG = make_float4(0.f, 0.f, 0.f, 0.f);
    float4 AI = make_float4(0.f, 0.f, 0.f, 0.f);
    float rsg = 0.f, rsi = 0.f;

    int s = g_rowptr[g], e = g_rowptr[g + 1];
    int p = s;
    uint4 tn = make_uint4(0, 0, 0, 0);
    float4 tk = make_float4(0.f, 0.f, 0.f, 0.f);
    if (p < e) {
        int tt = __ldg(g_ecol + p);
        tn = nrm4[(size_t)tt * 16 + l];
        tk = *(const float4*)(ekIn + (size_t)tt * DD + l * 4);
    }
    while (p < e) {
        uint4  cn = tn;
        float4 ck = tk;
        p++;
        if (p < e) {
            int tt = __ldg(g_ecol + p);
            tn = nrm4[(size_t)tt * 16 + l];
            tk = *(const float4*)(ekIn + (size_t)tt * DD + l * 4);
        }
        float2 tg01 = __half22float2(*(__half2*)&cn.x);
        float2 tg23 = __half22float2(*(__half2*)&cn.y);
        float2 ti01 = __half22float2(*(__half2*)&cn.z);
        float2 ti23 = __half22float2(*(__half2*)&cn.w);
        float dg = hg01.x * tg01.x + hg01.y * tg01.y + hg23.x * tg23.x + hg23.y * tg23.y;
        float di = hi01.x * ti01.x + hi01.y * ti01.y + hi23.x * ti23.x + hi23.y * ti23.y;
#pragma unroll
        for (int o = 8; o > 0; o >>= 1) {
            dg += __shfl_xor_sync(m, dg, o);
            di += __shfl_xor_sync(m, di, o);
        }
        float ag = (dg + 1.f) * 0.5f;
        float ai = (di + 1.f) * 0.5f;
        AG.x = fmaf(ag, ck.x, AG.x); AG.y = fmaf(ag, ck.y, AG.y);
        AG.z = fmaf(ag, ck.z, AG.z); AG.w = fmaf(ag, ck.w, AG.w);
        AI.x = fmaf(ai, ck.x, AI.x); AI.y = fmaf(ai, ck.y, AI.y);
        AI.z = fmaf(ai, ck.z, AI.z); AI.w = fmaf(ai, ck.w, AI.w);
        rsg += ag;
        rsi += ai;
    }
    float dg_inv = rsg > 0.f ? 1.f / rsg : 0.f;
    float di_inv = rsi > 0.f ? 1.f / rsi : 0.f;
    float4 gv = make_float4(AG.x * dg_inv, AG.y * dg_inv, AG.z * dg_inv, AG.w * dg_inv);
    float4 iv = make_float4(AI.x * di_inv, AI.y * di_inv, AI.z * di_inv, AI.w * di_inv);
    *(float4*)(gaa + ro) = gv;
    *(float4*)(iaa + ro) = iv;

    float4 hg0 = *(const float4*)(gnn + ro);
    float4 hi0 = *(const float4*)(itl + ro);
    float4 ekv = *(const float4*)(ekIn + ro);
    float4 en;
    en.x = hg0.x + hi0.x + gv.x + iv.x + ekv.x;
    en.y = hg0.y + hi0.y + gv.y + iv.y + ekv.y;
    en.z = hg0.z + hi0.z + gv.z + iv.z + ekv.z;
    en.w = hg0.w + hi0.w + gv.w + iv.w + ekv.w;
    float4 ac = *(const float4*)(g_accum + ro);
    ac.x += en.x; ac.y += en.y; ac.z += en.z; ac.w += en.w;
    if (finalOut) {
        *(float4*)(finalOut + ro) = ac;      // last layer: ekOut/accum never read again
    } else {
        *(float4*)(ekOut + ro) = en;
        *(float4*)(g_accum + ro) = ac;
    }
}

// ---------------- launch ----------------
extern "C" void kernel_launch(void* const* d_in, const int* in_sizes, int n_in,
                              void* d_out, int out_size) {
    const float* user_emb = (const float*)d_in[0];
    const float* item_emb = (const float*)d_in[1];
    const float* Wu       = (const float*)d_in[2];
    const float* Wi       = (const float*)d_in[3];
    const float* adj      = (const float*)d_in[4];
    const int*   h        = (const int*)d_in[5];
    const int*   t        = (const int*)d_in[6];
    (void)in_sizes; (void)n_in; (void)out_size;

    float* out = (float*)d_out;
    const size_t ND = (size_t)NN * DD;
    float* out_ua  = out;                    // [N*D] = ua | ia
    float* out_gnn = out + ND;               // [L][N][D]
    float* out_int = out_gnn + (size_t)LL * ND;
    float* out_gaa = out_int + (size_t)LL * ND;
    float* out_iaa = out_gaa + (size_t)LL * ND;

    // one-time resources (no device memory)
    static cudaStream_t s1 = nullptr, s2 = nullptr;
    static cudaEvent_t evF = nullptr, ev1 = nullptr, ev2 = nullptr, evI = nullptr;
    if (!s1) {
        cudaStreamCreateWithFlags(&s1, cudaStreamNonBlocking);
        cudaStreamCreateWithFlags(&s2, cudaStreamNonBlocking);
        cudaEventCreateWithFlags(&evF, cudaEventDisableTiming);
        cudaEventCreateWithFlags(&ev1, cudaEventDisableTiming);
        cudaEventCreateWithFlags(&ev2, cudaEventDisableTiming);
        cudaEventCreateWithFlags(&evI, cudaEventDisableTiming);
        cudaFuncSetAttribute(intent_kernel, cudaFuncAttributeMaxDynamicSharedMemorySize, IT_SMEM_BYTES);
    }

    const int TPB = 256;
    const int SCAN_NB = (NN + 1023) / 1024;  // 147

    // fork: init_ek on s1, CSR build on default
    cudaEventRecord(evF, 0);
    cudaStreamWaitEvent(s1, evF, 0);
    init_ek_kernel<<<(NN * DD / 4 + TPB - 1) / TPB, TPB, 0, s1>>>((const float4*)user_emb,
                                                                  (const float4*)item_emb);
    cudaEventRecord(evI, s1);

    zero_cnt_kernel<<<(NN + TPB - 1) / TPB, TPB>>>();
    hist_kernel<<<(EE + TPB - 1) / TPB, TPB>>>(h);
    reduce_cnt_kernel<<<SCAN_NB, 1024>>>();
    scan_bsums_kernel<<<1, 256>>>(SCAN_NB);
    apply_scan_kernel<<<SCAN_NB, 1024>>>();
    scatter_kernel<<<(EE + TPB - 1) / TPB, TPB>>>(h, t, adj);
    cudaStreamWaitEvent(0, evI, 0);          // join init_ek

    const int NODE_BLOCKS = (NN * 16 + TPB - 1) / TPB;   // 16-lane group per node
    for (int l = 0; l < LL; l++) {
        float* gnn = out_gnn + (size_t)l * ND;
        float* itl = out_int + (size_t)l * ND;
        float* gaa = out_gaa + (size_t)l * ND;
        float* iaa = out_iaa + (size_t)l * ND;

        // fork: spmm on default, intents on s1/s2
        cudaEventRecord(evF, 0);
        cudaStreamWaitEvent(s1, evF, 0);
        cudaStreamWaitEvent(s2, evF, 0);

        spmm_gnn_kernel<<<NODE_BLOCKS, TPB>>>(l, gnn);
        intent_kernel<<<(UN + TM - 1) / TM, 256, IT_SMEM_BYTES, s1>>>(l, Wu, itl, 0, UN);
        intent_kernel<<<(INC + TM - 1) / TM, 256, IT_SMEM_BYTES, s2>>>(l, Wi, itl, UN, INC);
        cudaEventRecord(ev1, s1);
        cudaEventRecord(ev2, s2);
        cudaStreamWaitEvent(0, ev1, 0);
        cudaStreamWaitEvent(0, ev2, 0);

        fused_alpha_kernel<<<NODE_BLOCKS, TPB>>>(l, gnn, itl, gaa, iaa,
                                                 (l == LL - 1) ? out_ua : nullptr);
    }
}

// round 5
// speedup vs baseline: 1.0544x; 1.0544x over previous
#include <cuda_runtime.h>
#include <cuda_fp16.h>

// ---------------- problem constants ----------------
#define UN  100000
#define INC 50000
#define NN  150000
#define DD  64
#define KK  128
#define EE  1250000
#define LL  2

typedef unsigned long long u64;

// ---------------- device scratch (static; no allocations) ----------------
__device__ float g_ekA[NN * DD];
__device__ float g_ekB[NN * DD];
__device__ float g_accum[NN * DD];
__device__ int   g_cnt[NN];
__device__ int   g_rowptr[NN + 1];
__device__ int   g_wp[NN];
__device__ int   g_ecol[EE];
__device__ float g_eval[EE];
// packed normalized vectors: per node 16 chunks of 16B; chunk c = {gnn̂[4c..4c+3], itl̂[4c..4c+3]} as fp16
__device__ __half g_nrm[NN * 128];
__device__ int   g_bsum[160];
__device__ int   g_boff[160];

// ---------------- f32x2 packed-math helpers ----------------
__device__ __forceinline__ u64 pk2(float x, float y) {
    u64 r; asm("mov.b64 %0, {%1, %2};" : "=l"(r) : "f"(x), "f"(y)); return r;
}
__device__ __forceinline__ u64 pk1(float x) { return pk2(x, x); }
__device__ __forceinline__ float2 up2(u64 v) {
    float2 r; asm("mov.b64 {%0, %1}, %2;" : "=f"(r.x), "=f"(r.y) : "l"(v)); return r;
}
__device__ __forceinline__ u64 fma2(u64 a, u64 b, u64 c) {
    u64 d; asm("fma.rn.f32x2 %0, %1, %2, %3;" : "=l"(d) : "l"(a), "l"(b), "l"(c)); return d;
}

// ---------------- CSR build ----------------
__global__ void zero_cnt_kernel() {
    int i = blockIdx.x * blockDim.x + threadIdx.x;
    if (i < NN) g_cnt[i] = 0;
}

__global__ void hist_kernel(const int* __restrict__ h) {
    int e = blockIdx.x * blockDim.x + threadIdx.x;
    if (e < EE) atomicAdd(&g_cnt[h[e]], 1);
}

__global__ void reduce_cnt_kernel() {
    __shared__ int s[1024];
    int tid = threadIdx.x;
    int idx = blockIdx.x * 1024 + tid;
    s[tid] = (idx < NN) ? g_cnt[idx] : 0;
    __syncthreads();
    for (int o = 512; o > 0; o >>= 1) {
        if (tid < o) s[tid] += s[tid + o];
        __syncthreads();
    }
    if (tid == 0) g_bsum[blockIdx.x] = s[0];
}

__global__ void scan_bsums_kernel(int nblk) {
    __shared__ int s[160];
    int tid = threadIdx.x;
    if (tid < nblk) s[tid] = g_bsum[tid];
    __syncthreads();
    if (tid == 0) {
        int run = 0;
        for (int i = 0; i < nblk; i++) { int t = s[i]; s[i] = run; run += t; }
    }
    __syncthreads();
    if (tid < nblk) g_boff[tid] = s[tid];
}

__global__ void apply_scan_kernel() {
    __shared__ int s[1024];
    int tid = threadIdx.x;
    int idx = blockIdx.x * 1024 + tid;
    int v = (idx < NN) ? g_cnt[idx] : 0;
    s[tid] = v;
    __syncthreads();
    for (int off = 1; off < 1024; off <<= 1) {
        int t = (tid >= off) ? s[tid - off] : 0;
        __syncthreads();
        s[tid] += t;
        __syncthreads();
    }
    int excl = s[tid] - v + g_boff[blockIdx.x];
    if (idx < NN) { g_rowptr[idx] = excl; g_wp[idx] = excl; }
    if (blockIdx.x == 0 && tid == 0) g_rowptr[NN] = EE;
}

__global__ void scatter_kernel(const int* __restrict__ h, const int* __restrict__ t,
                               const float* __restrict__ adj) {
    int e = blockIdx.x * blockDim.x + threadIdx.x;
    if (e >= EE) return;
    int hn = h[e];
    int p  = atomicAdd(&g_wp[hn], 1);
    g_ecol[p] = t[e];
    g_eval[p] = adj[e];
}

// ---------------- init ----------------
__global__ void init_ek_kernel(const float4* __restrict__ ue, const float4* __restrict__ ie) {
    int i = blockIdx.x * blockDim.x + threadIdx.x;
    const int TOT = NN * DD / 4, UD4 = UN * DD / 4;
    if (i >= TOT) return;
    float4 v = (i < UD4) ? ue[i] : ie[i - UD4];
    ((float4*)g_ekA)[i]   = v;
    ((float4*)g_accum)[i] = v;
}

// ---------------- SpMM: gnn = A @ ek (16-lane group per node); writes gnn + fp16 gnn̂ ----------------
__global__ void __launch_bounds__(256) spmm_gnn_kernel(int layer, float* __restrict__ out) {
    const float* __restrict__ ekIn = layer ? g_ekB : g_ekA;
    int t0 = blockIdx.x * blockDim.x + threadIdx.x;
    int g = t0 >> 4;
    int l = threadIdx.x & 15;
    unsigned m = 0xFFFFu << (threadIdx.x & 16);
    int s = g_rowptr[g], e = g_rowptr[g + 1];
    float4 acc = make_float4(0.f, 0.f, 0.f, 0.f);

    int p = s;
    // unroll-by-2: both edges' loads in flight together
    for (; p + 1 < e; p += 2) {
        int   ta = __ldg(g_ecol + p);
        int   tb = __ldg(g_ecol + p + 1);
        float va = __ldg(g_eval + p);
        float vb = __ldg(g_eval + p + 1);
        float4 xa = *(const float4*)(ekIn + (size_t)ta * DD + l * 4);
        float4 xb = *(const float4*)(ekIn + (size_t)tb * DD + l * 4);
        acc.x = fmaf(va, xa.x, acc.x);
        acc.y = fmaf(va, xa.y, acc.y);
        acc.z = fmaf(va, xa.z, acc.z);
        acc.w = fmaf(va, xa.w, acc.w);
        acc.x = fmaf(vb, xb.x, acc.x);
        acc.y = fmaf(vb, xb.y, acc.y);
        acc.z = fmaf(vb, xb.z, acc.z);
        acc.w = fmaf(vb, xb.w, acc.w);
    }
    if (p < e) {
        int   ta = __ldg(g_ecol + p);
        float va = __ldg(g_eval + p);
        float4 xa = *(const float4*)(ekIn + (size_t)ta * DD + l * 4);
        acc.x = fmaf(va, xa.x, acc.x);
        acc.y = fmaf(va, xa.y, acc.y);
        acc.z = fmaf(va, xa.z, acc.z);
        acc.w = fmaf(va, xa.w, acc.w);
    }
    *(float4*)(out + (size_t)g * DD + l * 4) = acc;
    float sg = acc.x * acc.x + acc.y * acc.y + acc.z * acc.z + acc.w * acc.w;
#pragma unroll
    for (int o = 8; o > 0; o >>= 1) sg += __shfl_xor_sync(m, sg, o);
    float inv = 1.f / fmaxf(sqrtf(sg), 1e-12f);
    __half2 h0 = __floats2half2_rn(acc.x * inv, acc.y * inv);
    __half2 h1 = __floats2half2_rn(acc.z * inv, acc.w * inv);
    uint2 u;
    u.x = *(unsigned*)&h0;
    u.y = *(unsigned*)&h1;
    ((uint2*)g_nrm)[(size_t)g * 32 + l * 2] = u;   // g-part of chunk l
}

// ---------------- fused intent: softmax(ek@W)@W^T per 128-row tile; writes itl + fp16 itl̂ ----------------
#define TM   128
#define ASP2 264            // duplicated A-tile row pitch (floats)
#define BTP  68
#define PSP  132
#define IT_SMEM_FLOATS (64 * ASP2 + 64 * KK + KK * BTP + TM * PSP)
#define IT_SMEM_BYTES  (IT_SMEM_FLOATS * 4)

__global__ void __launch_bounds__(256, 1)
intent_kernel(int layer, const float* __restrict__ W, float* __restrict__ outIntl,
              int nodeBase, int nodeCount) {
    const float* __restrict__ ekIn = layer ? g_ekB : g_ekA;
    extern __shared__ float sm[];
    float* As2 = sm;                   // [64][ASP2] A^T tile, each value duplicated (a,a)
    float* Bs  = As2 + 64 * ASP2;      // [64][128]  W
    float* Bt  = Bs + 64 * KK;         // [128][BTP] W^T
    float* Ps  = Bt + KK * BTP;        // [128][PSP] logits -> probs

    int tid = threadIdx.x;
    int tx = tid & 15, ty = tid >> 4;
    int rowTile = blockIdx.x * TM;

#pragma unroll
    for (int it = 0; it < 8; it++) {
        int i = tid + it * 256;
        float4 v = ((const float4*)W)[i];
        int d = i >> 5;
        int k = (i << 2) & 127;
        *(float4*)(Bs + d * KK + k) = v;
        Bt[(k + 0) * BTP + d] = v.x;
        Bt[(k + 1) * BTP + d] = v.y;
        Bt[(k + 2) * BTP + d] = v.z;
        Bt[(k + 3) * BTP + d] = v.w;
    }
#pragma unroll
    for (int it = 0; it < 8; it++) {
        int i  = tid + it * 256;
        int rr = i >> 4;
        int d0 = (i << 2) & 63;
        float4 v = make_float4(0.f, 0.f, 0.f, 0.f);
        int r = rowTile + rr;
        if (r < nodeCount) v = *(const float4*)(ekIn + (size_t)(nodeBase + r) * DD + d0);
        ((u64*)(As2 + (d0 + 0) * ASP2))[rr] = pk1(v.x);
        ((u64*)(As2 + (d0 + 1) * ASP2))[rr] = pk1(v.y);
        ((u64*)(As2 + (d0 + 2) * ASP2))[rr] = pk1(v.z);
        ((u64*)(As2 + (d0 + 3) * ASP2))[rr] = pk1(v.w);
    }
    __syncthreads();

    const int r0 = ty * 8, k0 = tx * 8;

    // GEMM1 (packed f32x2, broadcast pairs straight from smem)
    u64 acc[8][4];
#pragma unroll
    for (int i = 0; i < 8; i++)
#pragma unroll
        for (int j = 0; j < 4; j++) acc[i][j] = 0ull;

#pragma unroll 4
    for (int d = 0; d < DD; d++) {
        const ulonglong2* a2 = (const ulonglong2*)(As2 + d * ASP2 + r0 * 2);
        ulonglong2 A0 = a2[0], A1 = a2[1], A2 = a2[2], A3 = a2[3];
        const ulonglong2* bb = (const ulonglong2*)(Bs + d * KK + k0);
        ulonglong2 B0 = bb[0], B1 = bb[1];
        u64 av[8] = {A0.x, A0.y, A1.x, A1.y, A2.x, A2.y, A3.x, A3.y};
        u64 bv[4] = {B0.x, B0.y, B1.x, B1.y};
#pragma unroll
        for (int i = 0; i < 8; i++) {
            acc[i][0] = fma2(av[i], bv[0], acc[i][0]);
            acc[i][1] = fma2(av[i], bv[1], acc[i][1]);
            acc[i][2] = fma2(av[i], bv[2], acc[i][2]);
            acc[i][3] = fma2(av[i], bv[3], acc[i][3]);
        }
    }
#pragma unroll
    for (int i = 0; i < 8; i++) {
        u64* pr = (u64*)(Ps + (r0 + i) * PSP + k0);
        pr[0] = acc[i][0]; pr[1] = acc[i][1]; pr[2] = acc[i][2]; pr[3] = acc[i][3];
    }
    __syncthreads();

    // row softmax
    int warp = tid >> 5, lane = tid & 31;
    for (int rr = warp; rr < TM; rr += 8) {
        float4 v = *(float4*)(Ps + rr * PSP + lane * 4);
        float mx = fmaxf(fmaxf(v.x, v.y), fmaxf(v.z, v.w));
#pragma unroll
        for (int o = 16; o > 0; o >>= 1) mx = fmaxf(mx, __shfl_xor_sync(0xffffffffu, mx, o));
        float e0 = __expf(v.x - mx), e1 = __expf(v.y - mx);
        float e2 = __expf(v.z - mx), e3 = __expf(v.w - mx);
        float sum = e0 + e1 + e2 + e3;
#pragma unroll
        for (int o = 16; o > 0; o >>= 1) sum += __shfl_xor_sync(0xffffffffu, sum, o);
        float inv = 1.0f / sum;
        *(float4*)(Ps + rr * PSP + lane * 4) = make_float4(e0 * inv, e1 * inv, e2 * inv, e3 * inv);
    }
    __syncthreads();

    // GEMM2 (packed f32x2)
    u64 acc2[8][2];
#pragma unroll
    for (int i = 0; i < 8; i++) { acc2[i][0] = 0ull; acc2[i][1] = 0ull; }
    const int d0o = tx * 4;
#pragma unroll 2
    for (int k = 0; k < KK; k += 4) {
        float4 p[8];
#pragma unroll
        for (int i = 0; i < 8; i++) p[i] = *(const float4*)(Ps + (r0 + i) * PSP + k);
        ulonglong2 C0 = *(const ulonglong2*)(Bt + (k + 0) * BTP + d0o);
        ulonglong2 C1 = *(const ulonglong2*)(Bt + (k + 1) * BTP + d0o);
        ulonglong2 C2 = *(const ulonglong2*)(Bt + (k + 2) * BTP + d0o);
        ulonglong2 C3 = *(const ulonglong2*)(Bt + (k + 3) * BTP + d0o);
#pragma unroll
        for (int i = 0; i < 8; i++) {
            u64 t;
            t = pk1(p[i].x); acc2[i][0] = fma2(t, C0.x, acc2[i][0]); acc2[i][1] = fma2(t, C0.y, acc2[i][1]);
            t = pk1(p[i].y); acc2[i][0] = fma2(t, C1.x, acc2[i][0]); acc2[i][1] = fma2(t, C1.y, acc2[i][1]);
            t = pk1(p[i].z); acc2[i][0] = fma2(t, C2.x, acc2[i][0]); acc2[i][1] = fma2(t, C2.y, acc2[i][1]);
            t = pk1(p[i].w); acc2[i][0] = fma2(t, C3.x, acc2[i][0]); acc2[i][1] = fma2(t, C3.y, acc2[i][1]);
        }
    }
    // epilogue: store + itl̂ fp16 write
#pragma unroll
    for (int i = 0; i < 8; i++) {
        float2 lo = up2(acc2[i][0]);
        float2 hi = up2(acc2[i][1]);
        float4 o = make_float4(lo.x, lo.y, hi.x, hi.y);
        int r = rowTile + r0 + i;
        bool ok = (r < nodeCount);
        if (ok) *(float4*)(outIntl + (size_t)(nodeBase + r) * DD + d0o) = o;
        float ns = o.x * o.x + o.y * o.y + o.z * o.z + o.w * o.w;
#pragma unroll
        for (int off = 8; off > 0; off >>= 1) ns += __shfl_xor_sync(0xffffffffu, ns, off);
        float inv = 1.f / fmaxf(sqrtf(ns), 1e-12f);
        if (ok) {
            __half2 h0 = __floats2half2_rn(o.x * inv, o.y * inv);
            __half2 h1 = __floats2half2_rn(o.z * inv, o.w * inv);
            uint2 u;
            u.x = *(unsigned*)&h0;
            u.y = *(unsigned*)&h1;
            ((uint2*)g_nrm)[(size_t)(nodeBase + r) * 32 + tx * 2 + 1] = u;  // i-part of chunk tx
        }
    }
}

// ---------------- fused alpha + spmm2 + combine (16-lane group per node) ----------------
__global__ void __launch_bounds__(256)
fused_alpha_kernel(int layer,
                   const float* __restrict__ gnn, const float* __restrict__ itl,
                   float* __restrict__ gaa, float* __restrict__ iaa,
                   float* __restrict__ finalOut) {
    const float* __restrict__ ekIn  = layer ? g_ekB : g_ekA;
    float*       __restrict__ ekOut = layer ? g_ekA : g_ekB;
    int t0 = blockIdx.x * blockDim.x + threadIdx.x;
    int g = t0 >> 4;
    int l = threadIdx.x & 15;
    unsigned m = 0xFFFFu << (threadIdx.x & 16);
    size_t ro = (size_t)g * DD + l * 4;
    const uint4* __restrict__ nrm4 = (const uint4*)g_nrm;

    uint4 hn = nrm4[(size_t)g * 16 + l];
    float2 hg01 = __half22float2(*(__half2*)&hn.x);
    float2 hg23 = __half22float2(*(__half2*)&hn.y);
    float2 hi01 = __half22float2(*(__half2*)&hn.z);
    float2 hi23 = __half22float2(*(__half2*)&hn.w);

    float4 AG = make_float4(0.f, 0.f, 0.f, 0.f);
    float4 AI = make_float4(0.f, 0.f, 0.f, 0.f);
    float rsg = 0.f, rsi = 0.f;

    int s = g_rowptr[g], e = g_rowptr[g + 1];
    int p = s;
    // unroll-by-2: two edges' gathers + 4 interleaved shuffle chains
    for (; p + 1 < e; p += 2) {
        int ta = __ldg(g_ecol + p);
        int tb = __ldg(g_ecol + p + 1);
        uint4  na = nrm4[(size_t)ta * 16 + l];
        uint4  nb = nrm4[(size_t)tb * 16 + l];
        float4 ka = *(const float4*)(ekIn + (size_t)ta * DD + l * 4);
        float4 kb = *(const float4*)(ekIn + (size_t)tb * DD + l * 4);

        float2 ag01 = __half22float2(*(__half2*)&na.x);
        float2 ag23 = __half22float2(*(__half2*)&na.y);
        float2 ai01 = __half22float2(*(__half2*)&na.z);
        float2 ai23 = __half22float2(*(__half2*)&na.w);
        float2 bg01 = __half22float2(*(__half2*)&nb.x);
        float2 bg23 = __half22float2(*(__half2*)&nb.y);
        float2 bi01 = __half22float2(*(__half2*)&nb.z);
        float2 bi23 = __half22float2(*(__half2*)&nb.w);

        float dga = hg01.x * ag01.x + hg01.y * ag01.y + hg23.x * ag23.x + hg23.y * ag23.y;
        float dia = hi01.x * ai01.x + hi01.y * ai01.y + hi23.x * ai23.x + hi23.y * ai23.y;
        float dgb = hg01.x * bg01.x + hg01.y * bg01.y + hg23.x * bg23.x + hg23.y * bg23.y;
        float dib = hi01.x * bi01.x + hi01.y * bi01.y + hi23.x * bi23.x + hi23.y * bi23.y;
#pragma unroll
        for (int o = 8; o > 0; o >>= 1) {
            dga += __shfl_xor_sync(m, dga, o);
            dia += __shfl_xor_sync(m, dia, o);
            dgb += __shfl_xor_sync(m, dgb, o);
            dib += __shfl_xor_sync(m, dib, o);
        }
        float aga = (dga + 1.f) * 0.5f;
        float aia = (dia + 1.f) * 0.5f;
        float agb = (dgb + 1.f) * 0.5f;
        float aib = (dib + 1.f) * 0.5f;
        AG.x = fmaf(aga, ka.x, AG.x); AG.y = fmaf(aga, ka.y, AG.y);
        AG.z = fmaf(aga, ka.z, AG.z); AG.w = fmaf(aga, ka.w, AG.w);
        AI.x = fmaf(aia, ka.x, AI.x); AI.y = fmaf(aia, ka.y, AI.y);
        AI.z = fmaf(aia, ka.z, AI.z); AI.w = fmaf(aia, ka.w, AI.w);
        AG.x = fmaf(agb, kb.x, AG.x); AG.y = fmaf(agb, kb.y, AG.y);
        AG.z = fmaf(agb, kb.z, AG.z); AG.w = fmaf(agb, kb.w, AG.w);
        AI.x = fmaf(aib, kb.x, AI.x); AI.y = fmaf(aib, kb.y, AI.y);
        AI.z = fmaf(aib, kb.z, AI.z); AI.w = fmaf(aib, kb.w, AI.w);
        rsg += aga + agb;
        rsi += aia + aib;
    }
    if (p < e) {
        int ta = __ldg(g_ecol + p);
        uint4  na = nrm4[(size_t)ta * 16 + l];
        float4 ka = *(const float4*)(ekIn + (size_t)ta * DD + l * 4);
        float2 ag01 = __half22float2(*(__half2*)&na.x);
        float2 ag23 = __half22float2(*(__half2*)&na.y);
        float2 ai01 = __half22float2(*(__half2*)&na.z);
        float2 ai23 = __half22float2(*(__half2*)&na.w);
        float dga = hg01.x * ag01.x + hg01.y * ag01.y + hg23.x * ag23.x + hg23.y * ag23.y;
        float dia = hi01.x * ai01.x + hi01.y * ai01.y + hi23.x * ai23.x + hi23.y * ai23.y;
#pragma unroll
        for (int o = 8; o > 0; o >>= 1) {
            dga += __shfl_xor_sync(m, dga, o);
            dia += __shfl_xor_sync(m, dia, o);
        }
        float aga = (dga + 1.f) * 0.5f;
        float aia = (dia + 1.f) * 0.5f;
        AG.x = fmaf(aga, ka.x, AG.x); AG.y = fmaf(aga, ka.y, AG.y);
        AG.z = fmaf(aga, ka.z, AG.z); AG.w = fmaf(aga, ka.w, AG.w);
        AI.x = fmaf(aia, ka.x, AI.x); AI.y = fmaf(aia, ka.y, AI.y);
        AI.z = fmaf(aia, ka.z, AI.z); AI.w = fmaf(aia, ka.w, AI.w);
        rsg += aga;
        rsi += aia;
    }
    float dg_inv = rsg > 0.f ? 1.f / rsg : 0.f;
    float di_inv = rsi > 0.f ? 1.f / rsi : 0.f;
    float4 gv = make_float4(AG.x * dg_inv, AG.y * dg_inv, AG.z * dg_inv, AG.w * dg_inv);
    float4 iv = make_float4(AI.x * di_inv, AI.y * di_inv, AI.z * di_inv, AI.w * di_inv);
    *(float4*)(gaa + ro) = gv;
    *(float4*)(iaa + ro) = iv;

    float4 hg0 = *(const float4*)(gnn + ro);
    float4 hi0 = *(const float4*)(itl + ro);
    float4 ekv = *(const float4*)(ekIn + ro);
    float4 en;
    en.x = hg0.x + hi0.x + gv.x + iv.x + ekv.x;
    en.y = hg0.y + hi0.y + gv.y + iv.y + ekv.y;
    en.z = hg0.z + hi0.z + gv.z + iv.z + ekv.z;
    en.w = hg0.w + hi0.w + gv.w + iv.w + ekv.w;
    float4 ac = *(const float4*)(g_accum + ro);
    ac.x += en.x; ac.y += en.y; ac.z += en.z; ac.w += en.w;
    if (finalOut) {
        *(float4*)(finalOut + ro) = ac;      // last layer: ekOut/accum never read again
    } else {
        *(float4*)(ekOut + ro) = en;
        *(float4*)(g_accum + ro) = ac;
    }
}

// ---------------- launch ----------------
extern "C" void kernel_launch(void* const* d_in, const int* in_sizes, int n_in,
                              void* d_out, int out_size) {
    const float* user_emb = (const float*)d_in[0];
    const float* item_emb = (const float*)d_in[1];
    const float* Wu       = (const float*)d_in[2];
    const float* Wi       = (const float*)d_in[3];
    const float* adj      = (const float*)d_in[4];
    const int*   h        = (const int*)d_in[5];
    const int*   t        = (const int*)d_in[6];
    (void)in_sizes; (void)n_in; (void)out_size;

    float* out = (float*)d_out;
    const size_t ND = (size_t)NN * DD;
    float* out_ua  = out;                    // [N*D] = ua | ia
    float* out_gnn = out + ND;               // [L][N][D]
    float* out_int = out_gnn + (size_t)LL * ND;
    float* out_gaa = out_int + (size_t)LL * ND;
    float* out_iaa = out_gaa + (size_t)LL * ND;

    cudaFuncSetAttribute(intent_kernel, cudaFuncAttributeMaxDynamicSharedMemorySize, IT_SMEM_BYTES);

    const int TPB = 256;
    const int SCAN_NB = (NN + 1023) / 1024;  // 147
    init_ek_kernel<<<(NN * DD / 4 + TPB - 1) / TPB, TPB>>>((const float4*)user_emb,
                                                           (const float4*)item_emb);
    zero_cnt_kernel<<<(NN + TPB - 1) / TPB, TPB>>>();
    hist_kernel<<<(EE + TPB - 1) / TPB, TPB>>>(h);
    reduce_cnt_kernel<<<SCAN_NB, 1024>>>();
    scan_bsums_kernel<<<1, 256>>>(SCAN_NB);
    apply_scan_kernel<<<SCAN_NB, 1024>>>();
    scatter_kernel<<<(EE + TPB - 1) / TPB, TPB>>>(h, t, adj);

    const int NODE_BLOCKS = (NN * 16 + TPB - 1) / TPB;   // 16-lane group per node
    for (int l = 0; l < LL; l++) {
        float* gnn = out_gnn + (size_t)l * ND;
        float* itl = out_int + (size_t)l * ND;
        float* gaa = out_gaa + (size_t)l * ND;
        float* iaa = out_iaa + (size_t)l * ND;

        spmm_gnn_kernel<<<NODE_BLOCKS, TPB>>>(l, gnn);
        intent_kernel<<<(UN + TM - 1) / TM, 256, IT_SMEM_BYTES>>>(l, Wu, itl, 0, UN);
        intent_kernel<<<(INC + TM - 1) / TM, 256, IT_SMEM_BYTES>>>(l, Wi, itl, UN, INC);
        fused_alpha_kernel<<<NODE_BLOCKS, TPB>>>(l, gnn, itl, gaa, iaa,
                                                 (l == LL - 1) ? out_ua : nullptr);
    }
}

// round 6
// speedup vs baseline: 1.1086x; 1.0514x over previous
#include <cuda_runtime.h>
#include <cuda_fp16.h>

// ---------------- problem constants ----------------
#define UN  100000
#define INC 50000
#define NN  150000
#define DD  64
#define KK  128
#define EE  1250000
#define LL  2

typedef unsigned long long u64;

// ---------------- device scratch (static; no allocations) ----------------
__device__ float g_ekA[NN * DD];
__device__ float g_ekB[NN * DD];
__device__ __half g_ekhA[NN * DD];
__device__ __half g_ekhB[NN * DD];
__device__ float g_accum[NN * DD];
__device__ int   g_cnt[NN];
__device__ int   g_rowptr[NN + 1];
__device__ int   g_wp[NN];
__device__ int   g_ecol[EE];
__device__ float g_eval[EE];
// packed normalized vectors: per node 16 chunks of 16B; chunk c = {gnn̂[4c..4c+3], itl̂[4c..4c+3]} fp16
__device__ __half g_nrm[NN * 128];
__device__ int   g_bsum[160];
__device__ int   g_boff[160];

// ---------------- f32x2 packed-math helpers ----------------
__device__ __forceinline__ u64 pk2(float x, float y) {
    u64 r; asm("mov.b64 %0, {%1, %2};" : "=l"(r) : "f"(x), "f"(y)); return r;
}
__device__ __forceinline__ u64 pk1(float x) { return pk2(x, x); }
__device__ __forceinline__ float2 up2(u64 v) {
    float2 r; asm("mov.b64 {%0, %1}, %2;" : "=f"(r.x), "=f"(r.y) : "l"(v)); return r;
}
__device__ __forceinline__ u64 fma2(u64 a, u64 b, u64 c) {
    u64 d; asm("fma.rn.f32x2 %0, %1, %2, %3;" : "=l"(d) : "l"(a), "l"(b), "l"(c)); return d;
}

// ---------------- CSR build ----------------
__global__ void zero_cnt_kernel() {
    int i = blockIdx.x * blockDim.x + threadIdx.x;
    if (i < NN) g_cnt[i] = 0;
}

__global__ void hist_kernel(const int* __restrict__ h) {
    int e = blockIdx.x * blockDim.x + threadIdx.x;
    if (e < EE) atomicAdd(&g_cnt[h[e]], 1);
}

__global__ void reduce_cnt_kernel() {
    __shared__ int s[1024];
    int tid = threadIdx.x;
    int idx = blockIdx.x * 1024 + tid;
    s[tid] = (idx < NN) ? g_cnt[idx] : 0;
    __syncthreads();
    for (int o = 512; o > 0; o >>= 1) {
        if (tid < o) s[tid] += s[tid + o];
        __syncthreads();
    }
    if (tid == 0) g_bsum[blockIdx.x] = s[0];
}

__global__ void scan_bsums_kernel(int nblk) {
    __shared__ int s[160];
    int tid = threadIdx.x;
    if (tid < nblk) s[tid] = g_bsum[tid];
    __syncthreads();
    if (tid == 0) {
        int run = 0;
        for (int i = 0; i < nblk; i++) { int t = s[i]; s[i] = run; run += t; }
    }
    __syncthreads();
    if (tid < nblk) g_boff[tid] = s[tid];
}

__global__ void apply_scan_kernel() {
    __shared__ int s[1024];
    int tid = threadIdx.x;
    int idx = blockIdx.x * 1024 + tid;
    int v = (idx < NN) ? g_cnt[idx] : 0;
    s[tid] = v;
    __syncthreads();
    for (int off = 1; off < 1024; off <<= 1) {
        int t = (tid >= off) ? s[tid - off] : 0;
        __syncthreads();
        s[tid] += t;
        __syncthreads();
    }
    int excl = s[tid] - v + g_boff[blockIdx.x];
    if (idx < NN) { g_rowptr[idx] = excl; g_wp[idx] = excl; }
    if (blockIdx.x == 0 && tid == 0) g_rowptr[NN] = EE;
}

__global__ void scatter_kernel(const int* __restrict__ h, const int* __restrict__ t,
                               const float* __restrict__ adj) {
    int e = blockIdx.x * blockDim.x + threadIdx.x;
    if (e >= EE) return;
    int hn = h[e];
    int p  = atomicAdd(&g_wp[hn], 1);
    g_ecol[p] = t[e];
    g_eval[p] = adj[e];
}

// ---------------- init (also fp16 copy of ek) ----------------
__global__ void init_ek_kernel(const float4* __restrict__ ue, const float4* __restrict__ ie) {
    int i = blockIdx.x * blockDim.x + threadIdx.x;
    const int TOT = NN * DD / 4, UD4 = UN * DD / 4;
    if (i >= TOT) return;
    float4 v = (i < UD4) ? ue[i] : ie[i - UD4];
    ((float4*)g_ekA)[i]   = v;
    ((float4*)g_accum)[i] = v;
    __half2 h0 = __floats2half2_rn(v.x, v.y);
    __half2 h1 = __floats2half2_rn(v.z, v.w);
    uint2 u; u.x = *(unsigned*)&h0; u.y = *(unsigned*)&h1;
    ((uint2*)g_ekhA)[i] = u;
}

// ---------------- smem layout for intent (Ps overlays As+Bs) ----------------
#define TM   128
#define ASP  136
#define BTP  68
#define PSP  132
#define IT_SMEM_FLOATS (64 * ASP + 64 * KK + KK * BTP)   // 25600
#define IT_SMEM_BYTES  (IT_SMEM_FLOATS * 4)              // 102400

// ---------------- spmm body (16-lane group per node); gnn + fp16 gnn̂ ----------------
__device__ __forceinline__ void spmm_body(int layer, float* __restrict__ out, int bx) {
    const float* __restrict__ ekIn = layer ? g_ekB : g_ekA;
    int t0 = bx * 256 + threadIdx.x;
    int g = t0 >> 4;
    int l = threadIdx.x & 15;
    unsigned m = 0xFFFFu << (threadIdx.x & 16);
    int s = g_rowptr[g], e = g_rowptr[g + 1];
    float4 acc = make_float4(0.f, 0.f, 0.f, 0.f);

    int p = s;
    for (; p + 1 < e; p += 2) {
        int   ta = __ldg(g_ecol + p);
        int   tb = __ldg(g_ecol + p + 1);
        float va = __ldg(g_eval + p);
        float vb = __ldg(g_eval + p + 1);
        float4 xa = *(const float4*)(ekIn + (size_t)ta * DD + l * 4);
        float4 xb = *(const float4*)(ekIn + (size_t)tb * DD + l * 4);
        acc.x = fmaf(va, xa.x, acc.x);
        acc.y = fmaf(va, xa.y, acc.y);
        acc.z = fmaf(va, xa.z, acc.z);
        acc.w = fmaf(va, xa.w, acc.w);
        acc.x = fmaf(vb, xb.x, acc.x);
        acc.y = fmaf(vb, xb.y, acc.y);
        acc.z = fmaf(vb, xb.z, acc.z);
        acc.w = fmaf(vb, xb.w, acc.w);
    }
    if (p < e) {
        int   ta = __ldg(g_ecol + p);
        float va = __ldg(g_eval + p);
        float4 xa = *(const float4*)(ekIn + (size_t)ta * DD + l * 4);
        acc.x = fmaf(va, xa.x, acc.x);
        acc.y = fmaf(va, xa.y, acc.y);
        acc.z = fmaf(va, xa.z, acc.z);
        acc.w = fmaf(va, xa.w, acc.w);
    }
    *(float4*)(out + (size_t)g * DD + l * 4) = acc;
    float sg = acc.x * acc.x + acc.y * acc.y + acc.z * acc.z + acc.w * acc.w;
#pragma unroll
    for (int o = 8; o > 0; o >>= 1) sg += __shfl_xor_sync(m, sg, o);
    float inv = 1.f / fmaxf(sqrtf(sg), 1e-12f);
    __half2 h0 = __floats2half2_rn(acc.x * inv, acc.y * inv);
    __half2 h1 = __floats2half2_rn(acc.z * inv, acc.w * inv);
    uint2 u;
    u.x = *(unsigned*)&h0;
    u.y = *(unsigned*)&h1;
    ((uint2*)g_nrm)[(size_t)g * 32 + l * 2] = u;   // g-part of chunk l
}

// ---------------- intent body: softmax(ek@W)@W^T per 128-row tile; itl + fp16 itl̂ ----------------
__device__ __forceinline__ void intent_body(int layer, const float* __restrict__ W,
                                            float* __restrict__ outIntl,
                                            int nodeBase, int nodeCount, int bx) {
    const float* __restrict__ ekIn = layer ? g_ekB : g_ekA;
    extern __shared__ float sm[];
    float* As = sm;                  // [64][ASP]   live through GEMM1
    float* Bs = sm + 64 * ASP;       // [64][128]   live through GEMM1
    float* Ps = sm;                  // [128][PSP]  live after GEMM1 (overlays As+Bs)
    float* Bt = sm + 64 * ASP + 64 * KK;  // [128][BTP]

    int tid = threadIdx.x;
    int tx = tid & 15, ty = tid >> 4;
    int rowTile = bx * TM;

#pragma unroll
    for (int it = 0; it < 8; it++) {
        int i = tid + it * 256;
        float4 v = ((const float4*)W)[i];
        int d = i >> 5;
        int k = (i << 2) & 127;
        *(float4*)(Bs + d * KK + k) = v;
        Bt[(k + 0) * BTP + d] = v.x;
        Bt[(k + 1) * BTP + d] = v.y;
        Bt[(k + 2) * BTP + d] = v.z;
        Bt[(k + 3) * BTP + d] = v.w;
    }
#pragma unroll
    for (int it = 0; it < 8; it++) {
        int i  = tid + it * 256;
        int rr = i >> 4;
        int d0 = (i << 2) & 63;
        float4 v = make_float4(0.f, 0.f, 0.f, 0.f);
        int r = rowTile + rr;
        if (r < nodeCount) v = *(const float4*)(ekIn + (size_t)(nodeBase + r) * DD + d0);
        As[(d0 + 0) * ASP + rr] = v.x;
        As[(d0 + 1) * ASP + rr] = v.y;
        As[(d0 + 2) * ASP + rr] = v.z;
        As[(d0 + 3) * ASP + rr] = v.w;
    }
    __syncthreads();

    const int r0 = ty * 8, k0 = tx * 8;

    // GEMM1 (packed f32x2), acc kept in registers
    u64 acc[8][4];
#pragma unroll
    for (int i = 0; i < 8; i++)
#pragma unroll
        for (int j = 0; j < 4; j++) acc[i][j] = 0ull;

#pragma unroll 4
    for (int d = 0; d < DD; d++) {
        float4 a0 = *(const float4*)(As + d * ASP + r0);
        float4 a1 = *(const float4*)(As + d * ASP + r0 + 4);
        const ulonglong2* bb = (const ulonglong2*)(Bs + d * KK + k0);
        ulonglong2 B0 = bb[0], B1 = bb[1];
        u64 av[8] = {pk1(a0.x), pk1(a0.y), pk1(a0.z), pk1(a0.w),
                     pk1(a1.x), pk1(a1.y), pk1(a1.z), pk1(a1.w)};
        u64 bv[4] = {B0.x, B0.y, B1.x, B1.y};
#pragma unroll
        for (int i = 0; i < 8; i++) {
            acc[i][0] = fma2(av[i], bv[0], acc[i][0]);
            acc[i][1] = fma2(av[i], bv[1], acc[i][1]);
            acc[i][2] = fma2(av[i], bv[2], acc[i][2]);
            acc[i][3] = fma2(av[i], bv[3], acc[i][3]);
        }
    }
    __syncthreads();                         // all As/Bs reads done before Ps overlay
#pragma unroll
    for (int i = 0; i < 8; i++) {
        u64* pr = (u64*)(Ps + (r0 + i) * PSP + k0);
        pr[0] = acc[i][0]; pr[1] = acc[i][1]; pr[2] = acc[i][2]; pr[3] = acc[i][3];
    }
    __syncthreads();

    // row softmax
    int warp = tid >> 5, lane = tid & 31;
    for (int rr = warp; rr < TM; rr += 8) {
        float4 v = *(float4*)(Ps + rr * PSP + lane * 4);
        float mx = fmaxf(fmaxf(v.x, v.y), fmaxf(v.z, v.w));
#pragma unroll
        for (int o = 16; o > 0; o >>= 1) mx = fmaxf(mx, __shfl_xor_sync(0xffffffffu, mx, o));
        float e0 = __expf(v.x - mx), e1 = __expf(v.y - mx);
        float e2 = __expf(v.z - mx), e3 = __expf(v.w - mx);
        float sum = e0 + e1 + e2 + e3;
#pragma unroll
        for (int o = 16; o > 0; o >>= 1) sum += __shfl_xor_sync(0xffffffffu, sum, o);
        float inv = 1.0f / sum;
        *(float4*)(Ps + rr * PSP + lane * 4) = make_float4(e0 * inv, e1 * inv, e2 * inv, e3 * inv);
    }
    __syncthreads();

    // GEMM2 (packed f32x2)
    u64 acc2[8][2];
#pragma unroll
    for (int i = 0; i < 8; i++) { acc2[i][0] = 0ull; acc2[i][1] = 0ull; }
    const int d0o = tx * 4;
#pragma unroll 2
    for (int k = 0; k < KK; k += 4) {
        float4 p[8];
#pragma unroll
        for (int i = 0; i < 8; i++) p[i] = *(const float4*)(Ps + (r0 + i) * PSP + k);
        ulonglong2 C0 = *(const ulonglong2*)(Bt + (k + 0) * BTP + d0o);
        ulonglong2 C1 = *(const ulonglong2*)(Bt + (k + 1) * BTP + d0o);
        ulonglong2 C2 = *(const ulonglong2*)(Bt + (k + 2) * BTP + d0o);
        ulonglong2 C3 = *(const ulonglong2*)(Bt + (k + 3) * BTP + d0o);
#pragma unroll
        for (int i = 0; i < 8; i++) {
            u64 t;
            t = pk1(p[i].x); acc2[i][0] = fma2(t, C0.x, acc2[i][0]); acc2[i][1] = fma2(t, C0.y, acc2[i][1]);
            t = pk1(p[i].y); acc2[i][0] = fma2(t, C1.x, acc2[i][0]); acc2[i][1] = fma2(t, C1.y, acc2[i][1]);
            t = pk1(p[i].z); acc2[i][0] = fma2(t, C2.x, acc2[i][0]); acc2[i][1] = fma2(t, C2.y, acc2[i][1]);
            t = pk1(p[i].w); acc2[i][0] = fma2(t, C3.x, acc2[i][0]); acc2[i][1] = fma2(t, C3.y, acc2[i][1]);
        }
    }
    // epilogue: store + itl̂ fp16 write
#pragma unroll
    for (int i = 0; i < 8; i++) {
        float2 lo = up2(acc2[i][0]);
        float2 hi = up2(acc2[i][1]);
        float4 o = make_float4(lo.x, lo.y, hi.x, hi.y);
        int r = rowTile + r0 + i;
        bool ok = (r < nodeCount);
        if (ok) *(float4*)(outIntl + (size_t)(nodeBase + r) * DD + d0o) = o;
        float ns = o.x * o.x + o.y * o.y + o.z * o.z + o.w * o.w;
#pragma unroll
        for (int off = 8; off > 0; off >>= 1) ns += __shfl_xor_sync(0xffffffffu, ns, off);
        float inv = 1.f / fmaxf(sqrtf(ns), 1e-12f);
        if (ok) {
            __half2 h0 = __floats2half2_rn(o.x * inv, o.y * inv);
            __half2 h1 = __floats2half2_rn(o.z * inv, o.w * inv);
            uint2 u;
            u.x = *(unsigned*)&h0;
            u.y = *(unsigned*)&h1;
            ((uint2*)g_nrm)[(size_t)(nodeBase + r) * 32 + tx * 2 + 1] = u;  // i-part of chunk tx
        }
    }
}

// ---------------- merged phase-1 kernel: intentU ∥ intentI ∥ spmm ----------------
#define NB_IU ((UN + TM - 1) / TM)      // 782
#define NB_II ((INC + TM - 1) / TM)     // 391
#define NB_SP (NN * 16 / 256)           // 9375

__global__ void __launch_bounds__(256, 2)
phase1_kernel(int layer, const float* __restrict__ Wu, const float* __restrict__ Wi,
              float* __restrict__ gnn, float* __restrict__ itl) {
    int bx = blockIdx.x;
    if (bx < NB_IU)              intent_body(layer, Wu, itl, 0, UN, bx);
    else if (bx < NB_IU + NB_II) intent_body(layer, Wi, itl, UN, INC, bx - NB_IU);
    else                         spmm_body(layer, gnn, bx - NB_IU - NB_II);
}

// ---------------- fused alpha + spmm2 + combine (16-lane group per node) ----------------
__global__ void __launch_bounds__(256)
fused_alpha_kernel(int layer,
                   const float* __restrict__ gnn, const float* __restrict__ itl,
                   float* __restrict__ gaa, float* __restrict__ iaa,
                   float* __restrict__ finalOut) {
    const float*  __restrict__ ekIn   = layer ? g_ekB : g_ekA;
    const __half* __restrict__ ekhIn  = layer ? g_ekhB : g_ekhA;
    float*        __restrict__ ekOut  = layer ? g_ekA : g_ekB;
    __half*       __restrict__ ekhOut = layer ? g_ekhA : g_ekhB;
    int t0 = blockIdx.x * blockDim.x + threadIdx.x;
    int g = t0 >> 4;
    int l = threadIdx.x & 15;
    unsigned m = 0xFFFFu << (threadIdx.x & 16);
    size_t ro = (size_t)g * DD + l * 4;
    const uint4* __restrict__ nrm4 = (const uint4*)g_nrm;
    const uint2* __restrict__ ekh2 = (const uint2*)ekhIn;

    uint4 hn = nrm4[(size_t)g * 16 + l];
    float2 hg01 = __half22float2(*(__half2*)&hn.x);
    float2 hg23 = __half22float2(*(__half2*)&hn.y);
    float2 hi01 = __half22float2(*(__half2*)&hn.z);
    float2 hi23 = __half22float2(*(__half2*)&hn.w);

    float4 AG = make_float4(0.f, 0.f, 0.f, 0.f);
    float4 AI = make_float4(0.f, 0.f, 0.f, 0.f);
    float rsg = 0.f, rsi = 0.f;

    int s = g_rowptr[g], e = g_rowptr[g + 1];
    int p = s;
    for (; p + 1 < e; p += 2) {
        int ta = __ldg(g_ecol + p);
        int tb = __ldg(g_ecol + p + 1);
        uint4 na = nrm4[(size_t)ta * 16 + l];
        uint4 nb = nrm4[(size_t)tb * 16 + l];
        uint2 ea = ekh2[(size_t)ta * 16 + l];
        uint2 eb = ekh2[(size_t)tb * 16 + l];

        float2 ag01 = __half22float2(*(__half2*)&na.x);
        float2 ag23 = __half22float2(*(__half2*)&na.y);
        float2 ai01 = __half22float2(*(__half2*)&na.z);
        float2 ai23 = __half22float2(*(__half2*)&na.w);
        float2 bg01 = __half22float2(*(__half2*)&nb.x);
        float2 bg23 = __half22float2(*(__half2*)&nb.y);
        float2 bi01 = __half22float2(*(__half2*)&nb.z);
        float2 bi23 = __half22float2(*(__half2*)&nb.w);

        float dga = hg01.x * ag01.x + hg01.y * ag01.y + hg23.x * ag23.x + hg23.y * ag23.y;
        float dia = hi01.x * ai01.x + hi01.y * ai01.y + hi23.x * ai23.x + hi23.y * ai23.y;
        float dgb = hg01.x * bg01.x + hg01.y * bg01.y + hg23.x * bg23.x + hg23.y * bg23.y;
        float dib = hi01.x * bi01.x + hi01.y * bi01.y + hi23.x * bi23.x + hi23.y * bi23.y;
#pragma unroll
        for (int o = 8; o > 0; o >>= 1) {
            dga += __shfl_xor_sync(m, dga, o);
            dia += __shfl_xor_sync(m, dia, o);
            dgb += __shfl_xor_sync(m, dgb, o);
            dib += __shfl_xor_sync(m, dib, o);
        }
        float aga = (dga + 1.f) * 0.5f;
        float aia = (dia + 1.f) * 0.5f;
        float agb = (dgb + 1.f) * 0.5f;
        float aib = (dib + 1.f) * 0.5f;
        float2 ka01 = __half22float2(*(__half2*)&ea.x);
        float2 ka23 = __half22float2(*(__half2*)&ea.y);
        float2 kb01 = __half22float2(*(__half2*)&eb.x);
        float2 kb23 = __half22float2(*(__half2*)&eb.y);
        AG.x = fmaf(aga, ka01.x, AG.x); AG.y = fmaf(aga, ka01.y, AG.y);
        AG.z = fmaf(aga, ka23.x, AG.z); AG.w = fmaf(aga, ka23.y, AG.w);
        AI.x = fmaf(aia, ka01.x, AI.x); AI.y = fmaf(aia, ka01.y, AI.y);
        AI.z = fmaf(aia, ka23.x, AI.z); AI.w = fmaf(aia, ka23.y, AI.w);
        AG.x = fmaf(agb, kb01.x, AG.x); AG.y = fmaf(agb, kb01.y, AG.y);
        AG.z = fmaf(agb, kb23.x, AG.z); AG.w = fmaf(agb, kb23.y, AG.w);
        AI.x = fmaf(aib, kb01.x, AI.x); AI.y = fmaf(aib, kb01.y, AI.y);
        AI.z = fmaf(aib, kb23.x, AI.z); AI.w = fmaf(aib, kb23.y, AI.w);
        rsg += aga + agb;
        rsi += aia + aib;
    }
    if (p < e) {
        int ta = __ldg(g_ecol + p);
        uint4 na = nrm4[(size_t)ta * 16 + l];
        uint2 ea = ekh2[(size_t)ta * 16 + l];
        float2 ag01 = __half22float2(*(__half2*)&na.x);
        float2 ag23 = __half22float2(*(__half2*)&na.y);
        float2 ai01 = __half22float2(*(__half2*)&na.z);
        float2 ai23 = __half22float2(*(__half2*)&na.w);
        float dga = hg01.x * ag01.x + hg01.y * ag01.y + hg23.x * ag23.x + hg23.y * ag23.y;
        float dia = hi01.x * ai01.x + hi01.y * ai01.y + hi23.x * ai23.x + hi23.y * ai23.y;
#pragma unroll
        for (int o = 8; o > 0; o >>= 1) {
            dga += __shfl_xor_sync(m, dga, o);
            dia += __shfl_xor_sync(m, dia, o);
        }
        float aga = (dga + 1.f) * 0.5f;
        float aia = (dia + 1.f) * 0.5f;
        float2 ka01 = __half22float2(*(__half2*)&ea.x);
        float2 ka23 = __half22float2(*(__half2*)&ea.y);
        AG.x = fmaf(aga, ka01.x, AG.x); AG.y = fmaf(aga, ka01.y, AG.y);
        AG.z = fmaf(aga, ka23.x, AG.z); AG.w = fmaf(aga, ka23.y, AG.w);
        AI.x = fmaf(aia, ka01.x, AI.x); AI.y = fmaf(aia, ka01.y, AI.y);
        AI.z = fmaf(aia, ka23.x, AI.z); AI.w = fmaf(aia, ka23.y, AI.w);
        rsg += aga;
        rsi += aia;
    }
    float dg_inv = rsg > 0.f ? 1.f / rsg : 0.f;
    float di_inv = rsi > 0.f ? 1.f / rsi : 0.f;
    float4 gv = make_float4(AG.x * dg_inv, AG.y * dg_inv, AG.z * dg_inv, AG.w * dg_inv);
    float4 iv = make_float4(AI.x * di_inv, AI.y * di_inv, AI.z * di_inv, AI.w * di_inv);
    *(float4*)(gaa + ro) = gv;
    *(float4*)(iaa + ro) = iv;

    float4 hg0 = *(const float4*)(gnn + ro);
    float4 hi0 = *(const float4*)(itl + ro);
    float4 ekv = *(const float4*)(ekIn + ro);
    float4 en;
    en.x = hg0.x + hi0.x + gv.x + iv.x + ekv.x;
    en.y = hg0.y + hi0.y + gv.y + iv.y + ekv.y;
    en.z = hg0.z + hi0.z + gv.z + iv.z + ekv.z;
    en.w = hg0.w + hi0.w + gv.w + iv.w + ekv.w;
    float4 ac = *(const float4*)(g_accum + ro);
    ac.x += en.x; ac.y += en.y; ac.z += en.z; ac.w += en.w;
    if (finalOut) {
        *(float4*)(finalOut + ro) = ac;      // last layer: ekOut/accum never read again
    } else {
        *(float4*)(ekOut + ro) = en;
        __half2 h0 = __floats2half2_rn(en.x, en.y);
        __half2 h1 = __floats2half2_rn(en.z, en.w);
        uint2 u; u.x = *(unsigned*)&h0; u.y = *(unsigned*)&h1;
        ((uint2*)ekhOut)[(size_t)g * 16 + l] = u;
        *(float4*)(g_accum + ro) = ac;
    }
}

// ---------------- launch ----------------
extern "C" void kernel_launch(void* const* d_in, const int* in_sizes, int n_in,
                              void* d_out, int out_size) {
    const float* user_emb = (const float*)d_in[0];
    const float* item_emb = (const float*)d_in[1];
    const float* Wu       = (const float*)d_in[2];
    const float* Wi       = (const float*)d_in[3];
    const float* adj      = (const float*)d_in[4];
    const int*   h        = (const int*)d_in[5];
    const int*   t        = (const int*)d_in[6];
    (void)in_sizes; (void)n_in; (void)out_size;

    float* out = (float*)d_out;
    const size_t ND = (size_t)NN * DD;
    float* out_ua  = out;                    // [N*D] = ua | ia
    float* out_gnn = out + ND;               // [L][N][D]
    float* out_int = out_gnn + (size_t)LL * ND;
    float* out_gaa = out_int + (size_t)LL * ND;
    float* out_iaa = out_gaa + (size_t)LL * ND;

    cudaFuncSetAttribute(phase1_kernel, cudaFuncAttributeMaxDynamicSharedMemorySize, IT_SMEM_BYTES);

    const int TPB = 256;
    const int SCAN_NB = (NN + 1023) / 1024;  // 147
    init_ek_kernel<<<(NN * DD / 4 + TPB - 1) / TPB, TPB>>>((const float4*)user_emb,
                                                           (const float4*)item_emb);
    zero_cnt_kernel<<<(NN + TPB - 1) / TPB, TPB>>>();
    hist_kernel<<<(EE + TPB - 1) / TPB, TPB>>>(h);
    reduce_cnt_kernel<<<SCAN_NB, 1024>>>();
    scan_bsums_kernel<<<1, 256>>>(SCAN_NB);
    apply_scan_kernel<<<SCAN_NB, 1024>>>();
    scatter_kernel<<<(EE + TPB - 1) / TPB, TPB>>>(h, t, adj);

    const int NODE_BLOCKS = NN * 16 / TPB;   // 9375
    for (int l = 0; l < LL; l++) {
        float* gnn = out_gnn + (size_t)l * ND;
        float* itl = out_int + (size_t)l * ND;
        float* gaa = out_gaa + (size_t)l * ND;
        float* iaa = out_iaa + (size_t)l * ND;

        phase1_kernel<<<NB_IU + NB_II + NB_SP, TPB, IT_SMEM_BYTES>>>(l, Wu, Wi, gnn, itl);
        fused_alpha_kernel<<<NODE_BLOCKS, TPB>>>(l, gnn, itl, gaa, iaa,
                                                 (l == LL - 1) ? out_ua : nullptr);
    }
}

// round 7
// speedup vs baseline: 1.1531x; 1.0402x over previous
#include <cuda_runtime.h>
#include <cuda_fp16.h>

// ---------------- problem constants ----------------
#define UN  100000
#define INC 50000
#define NN  150000
#define DD  64
#define KK  128
#define EE  1250000
#define LL  2

typedef unsigned long long u64;

// ---------------- device scratch (static; no allocations) ----------------
__device__ float g_ekA[NN * DD];
__device__ float g_ekB[NN * DD];
__device__ __half g_ekhA[NN * DD];
__device__ __half g_ekhB[NN * DD];
__device__ float g_accum[NN * DD];
__device__ int   g_cnt[NN];
__device__ int   g_rowptr[NN + 1];
__device__ int   g_wp[NN];
__device__ int2  g_edge[EE];        // {tail, adj-as-int} in CSR order
// packed normalized vectors: per node 16 chunks of 16B; chunk c = {gnn̂[4c..4c+3], itl̂[4c..4c+3]} fp16
__device__ __half g_nrm[NN * 128];
__device__ int   g_bsum[160];
__device__ int   g_boff[160];

// ---------------- f32x2 packed-math helpers ----------------
__device__ __forceinline__ u64 pk2(float x, float y) {
    u64 r; asm("mov.b64 %0, {%1, %2};" : "=l"(r) : "f"(x), "f"(y)); return r;
}
__device__ __forceinline__ u64 pk1(float x) { return pk2(x, x); }
__device__ __forceinline__ float2 up2(u64 v) {
    float2 r; asm("mov.b64 {%0, %1}, %2;" : "=f"(r.x), "=f"(r.y) : "l"(v)); return r;
}
__device__ __forceinline__ u64 fma2(u64 a, u64 b, u64 c) {
    u64 d; asm("fma.rn.f32x2 %0, %1, %2, %3;" : "=l"(d) : "l"(a), "l"(b), "l"(c)); return d;
}

// ---------------- CSR build ----------------
__global__ void zero_cnt_kernel() {
    int i = blockIdx.x * blockDim.x + threadIdx.x;
    if (i < NN) g_cnt[i] = 0;
}

__global__ void hist_kernel(const int* __restrict__ h) {
    int e = blockIdx.x * blockDim.x + threadIdx.x;
    if (e < EE) atomicAdd(&g_cnt[h[e]], 1);
}

__global__ void reduce_cnt_kernel() {
    __shared__ int s[1024];
    int tid = threadIdx.x;
    int idx = blockIdx.x * 1024 + tid;
    s[tid] = (idx < NN) ? g_cnt[idx] : 0;
    __syncthreads();
    for (int o = 512; o > 0; o >>= 1) {
        if (tid < o) s[tid] += s[tid + o];
        __syncthreads();
    }
    if (tid == 0) g_bsum[blockIdx.x] = s[0];
}

__global__ void scan_bsums_kernel(int nblk) {
    __shared__ int s[160];
    int tid = threadIdx.x;
    if (tid < nblk) s[tid] = g_bsum[tid];
    __syncthreads();
    if (tid == 0) {
        int run = 0;
        for (int i = 0; i < nblk; i++) { int t = s[i]; s[i] = run; run += t; }
    }
    __syncthreads();
    if (tid < nblk) g_boff[tid] = s[tid];
}

__global__ void apply_scan_kernel() {
    __shared__ int s[1024];
    int tid = threadIdx.x;
    int idx = blockIdx.x * 1024 + tid;
    int v = (idx < NN) ? g_cnt[idx] : 0;
    s[tid] = v;
    __syncthreads();
    for (int off = 1; off < 1024; off <<= 1) {
        int t = (tid >= off) ? s[tid - off] : 0;
        __syncthreads();
        s[tid] += t;
        __syncthreads();
    }
    int excl = s[tid] - v + g_boff[blockIdx.x];
    if (idx < NN) { g_rowptr[idx] = excl; g_wp[idx] = excl; }
    if (blockIdx.x == 0 && tid == 0) g_rowptr[NN] = EE;
}

__global__ void scatter_kernel(const int* __restrict__ h, const int* __restrict__ t,
                               const float* __restrict__ adj) {
    int e = blockIdx.x * blockDim.x + threadIdx.x;
    if (e >= EE) return;
    int hn = h[e];
    int p  = atomicAdd(&g_wp[hn], 1);
    g_edge[p] = make_int2(t[e], __float_as_int(adj[e]));
}

// ---------------- init (also fp16 copy of ek) ----------------
__global__ void init_ek_kernel(const float4* __restrict__ ue, const float4* __restrict__ ie) {
    int i = blockIdx.x * blockDim.x + threadIdx.x;
    const int TOT = NN * DD / 4, UD4 = UN * DD / 4;
    if (i >= TOT) return;
    float4 v = (i < UD4) ? ue[i] : ie[i - UD4];
    ((float4*)g_ekA)[i]   = v;
    ((float4*)g_accum)[i] = v;
    __half2 h0 = __floats2half2_rn(v.x, v.y);
    __half2 h1 = __floats2half2_rn(v.z, v.w);
    uint2 u; u.x = *(unsigned*)&h0; u.y = *(unsigned*)&h1;
    ((uint2*)g_ekhA)[i] = u;
}

// ---------------- smem layout for intent (Ps overlays As+Bs) ----------------
#define TM   128
#define ASP  136
#define BTP  68
#define PSP  132
#define IT_SMEM_FLOATS (64 * ASP + 64 * KK + KK * BTP)   // 25600
#define IT_SMEM_BYTES  (IT_SMEM_FLOATS * 4)              // 102400

// ---------------- spmm body (16-lane group per node); gnn + fp16 gnn̂ ----------------
__device__ __forceinline__ void spmm_body(int layer, float* __restrict__ out, int bx) {
    const float* __restrict__ ekIn = layer ? g_ekB : g_ekA;
    int t0 = bx * 256 + threadIdx.x;
    int g = t0 >> 4;
    int l = threadIdx.x & 15;
    unsigned m = 0xFFFFu << (threadIdx.x & 16);
    int s = g_rowptr[g], e = g_rowptr[g + 1];
    float4 acc = make_float4(0.f, 0.f, 0.f, 0.f);

    int p = s;
    for (; p + 3 < e; p += 4) {
        int2 e0 = __ldg(g_edge + p);
        int2 e1 = __ldg(g_edge + p + 1);
        int2 e2 = __ldg(g_edge + p + 2);
        int2 e3 = __ldg(g_edge + p + 3);
        float4 x0 = *(const float4*)(ekIn + (size_t)e0.x * DD + l * 4);
        float4 x1 = *(const float4*)(ekIn + (size_t)e1.x * DD + l * 4);
        float4 x2 = *(const float4*)(ekIn + (size_t)e2.x * DD + l * 4);
        float4 x3 = *(const float4*)(ekIn + (size_t)e3.x * DD + l * 4);
        float v0 = __int_as_float(e0.y), v1 = __int_as_float(e1.y);
        float v2 = __int_as_float(e2.y), v3 = __int_as_float(e3.y);
        acc.x = fmaf(v0, x0.x, acc.x); acc.y = fmaf(v0, x0.y, acc.y);
        acc.z = fmaf(v0, x0.z, acc.z); acc.w = fmaf(v0, x0.w, acc.w);
        acc.x = fmaf(v1, x1.x, acc.x); acc.y = fmaf(v1, x1.y, acc.y);
        acc.z = fmaf(v1, x1.z, acc.z); acc.w = fmaf(v1, x1.w, acc.w);
        acc.x = fmaf(v2, x2.x, acc.x); acc.y = fmaf(v2, x2.y, acc.y);
        acc.z = fmaf(v2, x2.z, acc.z); acc.w = fmaf(v2, x2.w, acc.w);
        acc.x = fmaf(v3, x3.x, acc.x); acc.y = fmaf(v3, x3.y, acc.y);
        acc.z = fmaf(v3, x3.z, acc.z); acc.w = fmaf(v3, x3.w, acc.w);
    }
    for (; p < e; p++) {
        int2 e0 = __ldg(g_edge + p);
        float4 x0 = *(const float4*)(ekIn + (size_t)e0.x * DD + l * 4);
        float v0 = __int_as_float(e0.y);
        acc.x = fmaf(v0, x0.x, acc.x); acc.y = fmaf(v0, x0.y, acc.y);
        acc.z = fmaf(v0, x0.z, acc.z); acc.w = fmaf(v0, x0.w, acc.w);
    }
    *(float4*)(out + (size_t)g * DD + l * 4) = acc;
    float sg = acc.x * acc.x + acc.y * acc.y + acc.z * acc.z + acc.w * acc.w;
#pragma unroll
    for (int o = 8; o > 0; o >>= 1) sg += __shfl_xor_sync(m, sg, o);
    float inv = 1.f / fmaxf(sqrtf(sg), 1e-12f);
    __half2 h0 = __floats2half2_rn(acc.x * inv, acc.y * inv);
    __half2 h1 = __floats2half2_rn(acc.z * inv, acc.w * inv);
    uint2 u;
    u.x = *(unsigned*)&h0;
    u.y = *(unsigned*)&h1;
    ((uint2*)g_nrm)[(size_t)g * 32 + l * 2] = u;   // g-part of chunk l
}

// ---------------- intent body: softmax(ek@W)@W^T per 128-row tile; itl + fp16 itl̂ ----------------
__device__ __forceinline__ void intent_body(int layer, const float* __restrict__ W,
                                            float* __restrict__ outIntl,
                                            int nodeBase, int nodeCount, int bx) {
    const float* __restrict__ ekIn = layer ? g_ekB : g_ekA;
    extern __shared__ float sm[];
    float* As = sm;                  // [64][ASP]   live through GEMM1
    float* Bs = sm + 64 * ASP;       // [64][128]   live through GEMM1
    float* Ps = sm;                  // [128][PSP]  live after GEMM1 (overlays As+Bs)
    float* Bt = sm + 64 * ASP + 64 * KK;  // [128][BTP]

    int tid = threadIdx.x;
    int tx = tid & 15, ty = tid >> 4;
    int rowTile = bx * TM;

#pragma unroll
    for (int it = 0; it < 8; it++) {
        int i = tid + it * 256;
        float4 v = ((const float4*)W)[i];
        int d = i >> 5;
        int k = (i << 2) & 127;
        *(float4*)(Bs + d * KK + k) = v;
        Bt[(k + 0) * BTP + d] = v.x;
        Bt[(k + 1) * BTP + d] = v.y;
        Bt[(k + 2) * BTP + d] = v.z;
        Bt[(k + 3) * BTP + d] = v.w;
    }
#pragma unroll
    for (int it = 0; it < 8; it++) {
        int i  = tid + it * 256;
        int rr = i >> 4;
        int d0 = (i << 2) & 63;
        float4 v = make_float4(0.f, 0.f, 0.f, 0.f);
        int r = rowTile + rr;
        if (r < nodeCount) v = *(const float4*)(ekIn + (size_t)(nodeBase + r) * DD + d0);
        As[(d0 + 0) * ASP + rr] = v.x;
        As[(d0 + 1) * ASP + rr] = v.y;
        As[(d0 + 2) * ASP + rr] = v.z;
        As[(d0 + 3) * ASP + rr] = v.w;
    }
    __syncthreads();

    const int r0 = ty * 8, k0 = tx * 8;

    // GEMM1 (packed f32x2), acc kept in registers
    u64 acc[8][4];
#pragma unroll
    for (int i = 0; i < 8; i++)
#pragma unroll
        for (int j = 0; j < 4; j++) acc[i][j] = 0ull;

#pragma unroll 4
    for (int d = 0; d < DD; d++) {
        float4 a0 = *(const float4*)(As + d * ASP + r0);
        float4 a1 = *(const float4*)(As + d * ASP + r0 + 4);
        const ulonglong2* bb = (const ulonglong2*)(Bs + d * KK + k0);
        ulonglong2 B0 = bb[0], B1 = bb[1];
        u64 av[8] = {pk1(a0.x), pk1(a0.y), pk1(a0.z), pk1(a0.w),
                     pk1(a1.x), pk1(a1.y), pk1(a1.z), pk1(a1.w)};
        u64 bv[4] = {B0.x, B0.y, B1.x, B1.y};
#pragma unroll
        for (int i = 0; i < 8; i++) {
            acc[i][0] = fma2(av[i], bv[0], acc[i][0]);
            acc[i][1] = fma2(av[i], bv[1], acc[i][1]);
            acc[i][2] = fma2(av[i], bv[2], acc[i][2]);
            acc[i][3] = fma2(av[i], bv[3], acc[i][3]);
        }
    }
    __syncthreads();                         // all As/Bs reads done before Ps overlay
#pragma unroll
    for (int i = 0; i < 8; i++) {
        u64* pr = (u64*)(Ps + (r0 + i) * PSP + k0);
        pr[0] = acc[i][0]; pr[1] = acc[i][1]; pr[2] = acc[i][2]; pr[3] = acc[i][3];
    }
    __syncthreads();

    // row softmax
    int warp = tid >> 5, lane = tid & 31;
    for (int rr = warp; rr < TM; rr += 8) {
        float4 v = *(float4*)(Ps + rr * PSP + lane * 4);
        float mx = fmaxf(fmaxf(v.x, v.y), fmaxf(v.z, v.w));
#pragma unroll
        for (int o = 16; o > 0; o >>= 1) mx = fmaxf(mx, __shfl_xor_sync(0xffffffffu, mx, o));
        float e0 = __expf(v.x - mx), e1 = __expf(v.y - mx);
        float e2 = __expf(v.z - mx), e3 = __expf(v.w - mx);
        float sum = e0 + e1 + e2 + e3;
#pragma unroll
        for (int o = 16; o > 0; o >>= 1) sum += __shfl_xor_sync(0xffffffffu, sum, o);
        float inv = 1.0f / sum;
        *(float4*)(Ps + rr * PSP + lane * 4) = make_float4(e0 * inv, e1 * inv, e2 * inv, e3 * inv);
    }
    __syncthreads();

    // GEMM2 (packed f32x2)
    u64 acc2[8][2];
#pragma unroll
    for (int i = 0; i < 8; i++) { acc2[i][0] = 0ull; acc2[i][1] = 0ull; }
    const int d0o = tx * 4;
#pragma unroll 2
    for (int k = 0; k < KK; k += 4) {
        float4 p[8];
#pragma unroll
        for (int i = 0; i < 8; i++) p[i] = *(const float4*)(Ps + (r0 + i) * PSP + k);
        ulonglong2 C0 = *(const ulonglong2*)(Bt + (k + 0) * BTP + d0o);
        ulonglong2 C1 = *(const ulonglong2*)(Bt + (k + 1) * BTP + d0o);
        ulonglong2 C2 = *(const ulonglong2*)(Bt + (k + 2) * BTP + d0o);
        ulonglong2 C3 = *(const ulonglong2*)(Bt + (k + 3) * BTP + d0o);
#pragma unroll
        for (int i = 0; i < 8; i++) {
            u64 t;
            t = pk1(p[i].x); acc2[i][0] = fma2(t, C0.x, acc2[i][0]); acc2[i][1] = fma2(t, C0.y, acc2[i][1]);
            t = pk1(p[i].y); acc2[i][0] = fma2(t, C1.x, acc2[i][0]); acc2[i][1] = fma2(t, C1.y, acc2[i][1]);
            t = pk1(p[i].z); acc2[i][0] = fma2(t, C2.x, acc2[i][0]); acc2[i][1] = fma2(t, C2.y, acc2[i][1]);
            t = pk1(p[i].w); acc2[i][0] = fma2(t, C3.x, acc2[i][0]); acc2[i][1] = fma2(t, C3.y, acc2[i][1]);
        }
    }
    // epilogue: store + itl̂ fp16 write
#pragma unroll
    for (int i = 0; i < 8; i++) {
        float2 lo = up2(acc2[i][0]);
        float2 hi = up2(acc2[i][1]);
        float4 o = make_float4(lo.x, lo.y, hi.x, hi.y);
        int r = rowTile + r0 + i;
        bool ok = (r < nodeCount);
        if (ok) *(float4*)(outIntl + (size_t)(nodeBase + r) * DD + d0o) = o;
        float ns = o.x * o.x + o.y * o.y + o.z * o.z + o.w * o.w;
#pragma unroll
        for (int off = 8; off > 0; off >>= 1) ns += __shfl_xor_sync(0xffffffffu, ns, off);
        float inv = 1.f / fmaxf(sqrtf(ns), 1e-12f);
        if (ok) {
            __half2 h0 = __floats2half2_rn(o.x * inv, o.y * inv);
            __half2 h1 = __floats2half2_rn(o.z * inv, o.w * inv);
            uint2 u;
            u.x = *(unsigned*)&h0;
            u.y = *(unsigned*)&h1;
            ((uint2*)g_nrm)[(size_t)(nodeBase + r) * 32 + tx * 2 + 1] = u;  // i-part of chunk tx
        }
    }
}

// ---------------- merged phase-1 kernel: interleaved intent/spmm dispatch ----------------
#define NB_IU ((UN + TM - 1) / TM)      // 782
#define NB_II ((INC + TM - 1) / TM)     // 391
#define NB_I  (NB_IU + NB_II)           // 1173
#define NB_SP (NN * 16 / 256)           // 9375

__global__ void __launch_bounds__(256, 2)
phase1_kernel(int layer, const float* __restrict__ Wu, const float* __restrict__ Wi,
              float* __restrict__ gnn, float* __restrict__ itl) {
    int bx = blockIdx.x;
    int k = bx >> 3;
    if ((bx & 7) == 0 && k < NB_I) {
        if (k < NB_IU) intent_body(layer, Wu, itl, 0, UN, k);
        else           intent_body(layer, Wi, itl, UN, INC, k - NB_IU);
    } else {
        int before = (bx + 7) >> 3;
        if (before > NB_I) before = NB_I;
        spmm_body(layer, gnn, bx - before);
    }
}

// ---------------- fused alpha + spmm2 + combine (16-lane group per node) ----------------
__global__ void __launch_bounds__(256)
fused_alpha_kernel(int layer,
                   const float* __restrict__ gnn, const float* __restrict__ itl,
                   float* __restrict__ gaa, float* __restrict__ iaa,
                   float* __restrict__ finalOut) {
    const float*  __restrict__ ekIn   = layer ? g_ekB : g_ekA;
    const __half* __restrict__ ekhIn  = layer ? g_ekhB : g_ekhA;
    float*        __restrict__ ekOut  = layer ? g_ekA : g_ekB;
    __half*       __restrict__ ekhOut = layer ? g_ekhA : g_ekhB;
    int t0 = blockIdx.x * blockDim.x + threadIdx.x;
    int g = t0 >> 4;
    int l = threadIdx.x & 15;
    unsigned m = 0xFFFFu << (threadIdx.x & 16);
    size_t ro = (size_t)g * DD + l * 4;
    const uint4* __restrict__ nrm4 = (const uint4*)g_nrm;
    const uint2* __restrict__ ekh2 = (const uint2*)ekhIn;

    uint4 hn = nrm4[(size_t)g * 16 + l];
    float2 hg01 = __half22float2(*(__half2*)&hn.x);
    float2 hg23 = __half22float2(*(__half2*)&hn.y);
    float2 hi01 = __half22float2(*(__half2*)&hn.z);
    float2 hi23 = __half22float2(*(__half2*)&hn.w);

    float4 AG = make_float4(0.f, 0.f, 0.f, 0.f);
    float4 AI = make_float4(0.f, 0.f, 0.f, 0.f);
    float rsg = 0.f, rsi = 0.f;

    int s = g_rowptr[g], e = g_rowptr[g + 1];
    int p = s;
    for (; p + 1 < e; p += 2) {
        int ta = __ldg(&g_edge[p].x);
        int tb = __ldg(&g_edge[p + 1].x);
        uint4 na = nrm4[(size_t)ta * 16 + l];
        uint4 nb = nrm4[(size_t)tb * 16 + l];
        uint2 ea = ekh2[(size_t)ta * 16 + l];
        uint2 eb = ekh2[(size_t)tb * 16 + l];

        float2 ag01 = __half22float2(*(__half2*)&na.x);
        float2 ag23 = __half22float2(*(__half2*)&na.y);
        float2 ai01 = __half22float2(*(__half2*)&na.z);
        float2 ai23 = __half22float2(*(__half2*)&na.w);
        float2 bg01 = __half22float2(*(__half2*)&nb.x);
        float2 bg23 = __half22float2(*(__half2*)&nb.y);
        float2 bi01 = __half22float2(*(__half2*)&nb.z);
        float2 bi23 = __half22float2(*(__half2*)&nb.w);

        float dga = hg01.x * ag01.x + hg01.y * ag01.y + hg23.x * ag23.x + hg23.y * ag23.y;
        float dia = hi01.x * ai01.x + hi01.y * ai01.y + hi23.x * ai23.x + hi23.y * ai23.y;
        float dgb = hg01.x * bg01.x + hg01.y * bg01.y + hg23.x * bg23.x + hg23.y * bg23.y;
        float dib = hi01.x * bi01.x + hi01.y * bi01.y + hi23.x * bi23.x + hi23.y * bi23.y;
#pragma unroll
        for (int o = 8; o > 0; o >>= 1) {
            dga += __shfl_xor_sync(m, dga, o);
            dia += __shfl_xor_sync(m, dia, o);
            dgb += __shfl_xor_sync(m, dgb, o);
            dib += __shfl_xor_sync(m, dib, o);
        }
        float aga = (dga + 1.f) * 0.5f;
        float aia = (dia + 1.f) * 0.5f;
        float agb = (dgb + 1.f) * 0.5f;
        float aib = (dib + 1.f) * 0.5f;
        float2 ka01 = __half22float2(*(__half2*)&ea.x);
        float2 ka23 = __half22float2(*(__half2*)&ea.y);
        float2 kb01 = __half22float2(*(__half2*)&eb.x);
        float2 kb23 = __half22float2(*(__half2*)&eb.y);
        AG.x = fmaf(aga, ka01.x, AG.x); AG.y = fmaf(aga, ka01.y, AG.y);
        AG.z = fmaf(aga, ka23.x, AG.z); AG.w = fmaf(aga, ka23.y, AG.w);
        AI.x = fmaf(aia, ka01.x, AI.x); AI.y = fmaf(aia, ka01.y, AI.y);
        AI.z = fmaf(aia, ka23.x, AI.z); AI.w = fmaf(aia, ka23.y, AI.w);
        AG.x = fmaf(agb, kb01.x, AG.x); AG.y = fmaf(agb, kb01.y, AG.y);
        AG.z = fmaf(agb, kb23.x, AG.z); AG.w = fmaf(agb, kb23.y, AG.w);
        AI.x = fmaf(aib, kb01.x, AI.x); AI.y = fmaf(aib, kb01.y, AI.y);
        AI.z = fmaf(aib, kb23.x, AI.z); AI.w = fmaf(aib, kb23.y, AI.w);
        rsg += aga + agb;
        rsi += aia + aib;
    }
    if (p < e) {
        int ta = __ldg(&g_edge[p].x);
        uint4 na = nrm4[(size_t)ta * 16 + l];
        uint2 ea = ekh2[(size_t)ta * 16 + l];
        float2 ag01 = __half22float2(*(__half2*)&na.x);
        float2 ag23 = __half22float2(*(__half2*)&na.y);
        float2 ai01 = __half22float2(*(__half2*)&na.z);
        float2 ai23 = __half22float2(*(__half2*)&na.w);
        float dga = hg01.x * ag01.x + hg01.y * ag01.y + hg23.x * ag23.x + hg23.y * ag23.y;
        float dia = hi01.x * ai01.x + hi01.y * ai01.y + hi23.x * ai23.x + hi23.y * ai23.y;
#pragma unroll
        for (int o = 8; o > 0; o >>= 1) {
            dga += __shfl_xor_sync(m, dga, o);
            dia += __shfl_xor_sync(m, dia, o);
        }
        float aga = (dga + 1.f) * 0.5f;
        float aia = (dia + 1.f) * 0.5f;
        float2 ka01 = __half22float2(*(__half2*)&ea.x);
        float2 ka23 = __half22float2(*(__half2*)&ea.y);
        AG.x = fmaf(aga, ka01.x, AG.x); AG.y = fmaf(aga, ka01.y, AG.y);
        AG.z = fmaf(aga, ka23.x, AG.z); AG.w = fmaf(aga, ka23.y, AG.w);
        AI.x = fmaf(aia, ka01.x, AI.x); AI.y = fmaf(aia, ka01.y, AI.y);
        AI.z = fmaf(aia, ka23.x, AI.z); AI.w = fmaf(aia, ka23.y, AI.w);
        rsg += aga;
        rsi += aia;
    }
    float dg_inv = rsg > 0.f ? 1.f / rsg : 0.f;
    float di_inv = rsi > 0.f ? 1.f / rsi : 0.f;
    float4 gv = make_float4(AG.x * dg_inv, AG.y * dg_inv, AG.z * dg_inv, AG.w * dg_inv);
    float4 iv = make_float4(AI.x * di_inv, AI.y * di_inv, AI.z * di_inv, AI.w * di_inv);
    *(float4*)(gaa + ro) = gv;
    *(float4*)(iaa + ro) = iv;

    float4 hg0 = *(const float4*)(gnn + ro);
    float4 hi0 = *(const float4*)(itl + ro);
    float4 ekv = *(const float4*)(ekIn + ro);
    float4 en;
    en.x = hg0.x + hi0.x + gv.x + iv.x + ekv.x;
    en.y = hg0.y + hi0.y + gv.y + iv.y + ekv.y;
    en.z = hg0.z + hi0.z + gv.z + iv.z + ekv.z;
    en.w = hg0.w + hi0.w + gv.w + iv.w + ekv.w;
    float4 ac = *(const float4*)(g_accum + ro);
    ac.x += en.x; ac.y += en.y; ac.z += en.z; ac.w += en.w;
    if (finalOut) {
        *(float4*)(finalOut + ro) = ac;      // last layer: ekOut/accum never read again
    } else {
        *(float4*)(ekOut + ro) = en;
        __half2 h0 = __floats2half2_rn(en.x, en.y);
        __half2 h1 = __floats2half2_rn(en.z, en.w);
        uint2 u; u.x = *(unsigned*)&h0; u.y = *(unsigned*)&h1;
        ((uint2*)ekhOut)[(size_t)g * 16 + l] = u;
        *(float4*)(g_accum + ro) = ac;
    }
}

// ---------------- launch ----------------
extern "C" void kernel_launch(void* const* d_in, const int* in_sizes, int n_in,
                              void* d_out, int out_size) {
    const float* user_emb = (const float*)d_in[0];
    const float* item_emb = (const float*)d_in[1];
    const float* Wu       = (const float*)d_in[2];
    const float* Wi       = (const float*)d_in[3];
    const float* adj      = (const float*)d_in[4];
    const int*   h        = (const int*)d_in[5];
    const int*   t        = (const int*)d_in[6];
    (void)in_sizes; (void)n_in; (void)out_size;

    float* out = (float*)d_out;
    const size_t ND = (size_t)NN * DD;
    float* out_ua  = out;                    // [N*D] = ua | ia
    float* out_gnn = out + ND;               // [L][N][D]
    float* out_int = out_gnn + (size_t)LL * ND;
    float* out_gaa = out_int + (size_t)LL * ND;
    float* out_iaa = out_gaa + (size_t)LL * ND;

    cudaFuncSetAttribute(phase1_kernel, cudaFuncAttributeMaxDynamicSharedMemorySize, IT_SMEM_BYTES);

    const int TPB = 256;
    const int SCAN_NB = (NN + 1023) / 1024;  // 147
    init_ek_kernel<<<(NN * DD / 4 + TPB - 1) / TPB, TPB>>>((const float4*)user_emb,
                                                           (const float4*)item_emb);
    zero_cnt_kernel<<<(NN + TPB - 1) / TPB, TPB>>>();
    hist_kernel<<<(EE + TPB - 1) / TPB, TPB>>>(h);
    reduce_cnt_kernel<<<SCAN_NB, 1024>>>();
    scan_bsums_kernel<<<1, 256>>>(SCAN_NB);
    apply_scan_kernel<<<SCAN_NB, 1024>>>();
    scatter_kernel<<<(EE + TPB - 1) / TPB, TPB>>>(h, t, adj);

    const int NODE_BLOCKS = NN * 16 / TPB;   // 9375
    for (int l = 0; l < LL; l++) {
        float* gnn = out_gnn + (size_t)l * ND;
        float* itl = out_int + (size_t)l * ND;
        float* gaa = out_gaa + (size_t)l * ND;
        float* iaa = out_iaa + (size_t)l * ND;

        phase1_kernel<<<NB_I + NB_SP, TPB, IT_SMEM_BYTES>>>(l, Wu, Wi, gnn, itl);
        fused_alpha_kernel<<<NODE_BLOCKS, TPB>>>(l, gnn, itl, gaa, iaa,
                                                 (l == LL - 1) ? out_ua : nullptr);
    }
}

// round 8
// speedup vs baseline: 1.1600x; 1.0059x over previous
#include <cuda_runtime.h>
#include <cuda_fp16.h>

// ---------------- problem constants ----------------
#define UN  100000
#define INC 50000
#define NN  150000
#define DD  64
#define KK  128
#define EE  1250000
#define LL  2

typedef unsigned long long u64;

// ---------------- device scratch (static; no allocations) ----------------
__device__ float g_ekA[NN * DD];
__device__ float g_ekB[NN * DD];
__device__ __half g_ekhA[NN * DD];
__device__ __half g_ekhB[NN * DD];
__device__ float g_accum[NN * DD];
__device__ int   g_cnt[NN];
__device__ int   g_rowptr[NN + 1];
__device__ int   g_wp[NN];
__device__ int2  g_edge[EE];        // {tail, adj-as-int} in CSR order
// packed normalized vectors: per node 16 chunks of 16B; chunk c = {gnn̂[4c..4c+3], itl̂[4c..4c+3]} fp16
__device__ __half g_nrm[NN * 128];
__device__ int   g_bsum[160];
__device__ int   g_boff[160];
__device__ int   g_done;

// ---------------- f32x2 packed-math helpers ----------------
__device__ __forceinline__ u64 pk2(float x, float y) {
    u64 r; asm("mov.b64 %0, {%1, %2};" : "=l"(r) : "f"(x), "f"(y)); return r;
}
__device__ __forceinline__ u64 pk1(float x) { return pk2(x, x); }
__device__ __forceinline__ float2 up2(u64 v) {
    float2 r; asm("mov.b64 {%0, %1}, %2;" : "=f"(r.x), "=f"(r.y) : "l"(v)); return r;
}
__device__ __forceinline__ u64 fma2(u64 a, u64 b, u64 c) {
    u64 d; asm("fma.rn.f32x2 %0, %1, %2, %3;" : "=l"(d) : "l"(a), "l"(b), "l"(c)); return d;
}

// ---------------- init (ek fp32+fp16, accum, cnt=0, done=0) ----------------
__global__ void init_ek_kernel(const float4* __restrict__ ue, const float4* __restrict__ ie) {
    int i = blockIdx.x * blockDim.x + threadIdx.x;
    const int TOT = NN * DD / 4, UD4 = UN * DD / 4;
    if (i == 0) g_done = 0;
    if (i < NN) g_cnt[i] = 0;
    if (i >= TOT) return;
    float4 v = (i < UD4) ? ue[i] : ie[i - UD4];
    ((float4*)g_ekA)[i]   = v;
    ((float4*)g_accum)[i] = v;
    __half2 h0 = __floats2half2_rn(v.x, v.y);
    __half2 h1 = __floats2half2_rn(v.z, v.w);
    uint2 u; u.x = *(unsigned*)&h0; u.y = *(unsigned*)&h1;
    ((uint2*)g_ekhA)[i] = u;
}

// ---------------- CSR build ----------------
__global__ void hist_kernel(const int* __restrict__ h) {
    int e = blockIdx.x * blockDim.x + threadIdx.x;
    if (e < EE) atomicAdd(&g_cnt[h[e]], 1);
}

// block-reduce cnt; LAST finishing block scans the block sums into g_boff
__global__ void reduce_scan_kernel() {
    __shared__ int s[1024];
    __shared__ bool amLast;
    int tid = threadIdx.x;
    int idx = blockIdx.x * 1024 + tid;
    s[tid] = (idx < NN) ? g_cnt[idx] : 0;
    __syncthreads();
    for (int o = 512; o > 0; o >>= 1) {
        if (tid < o) s[tid] += s[tid + o];
        __syncthreads();
    }
    if (tid == 0) {
        g_bsum[blockIdx.x] = s[0];
        __threadfence();
        amLast = (atomicAdd(&g_done, 1) == gridDim.x - 1);
    }
    __syncthreads();
    if (amLast) {
        int nblk = gridDim.x;
        int v = (tid < nblk) ? g_bsum[tid] : 0;
        s[tid] = v;
        __syncthreads();
        for (int off = 1; off < 1024; off <<= 1) {
            int t = (tid >= off) ? s[tid - off] : 0;
            __syncthreads();
            s[tid] += t;
            __syncthreads();
        }
        if (tid < nblk) g_boff[tid] = s[tid] - v;   // exclusive
    }
}

__global__ void apply_scan_kernel() {
    __shared__ int s[1024];
    int tid = threadIdx.x;
    int idx = blockIdx.x * 1024 + tid;
    int v = (idx < NN) ? g_cnt[idx] : 0;
    s[tid] = v;
    __syncthreads();
    for (int off = 1; off < 1024; off <<= 1) {
        int t = (tid >= off) ? s[tid - off] : 0;
        __syncthreads();
        s[tid] += t;
        __syncthreads();
    }
    int excl = s[tid] - v + g_boff[blockIdx.x];
    if (idx < NN) { g_rowptr[idx] = excl; g_wp[idx] = excl; }
    if (blockIdx.x == 0 && tid == 0) g_rowptr[NN] = EE;
}

__global__ void scatter_kernel(const int* __restrict__ h, const int* __restrict__ t,
                               const float* __restrict__ adj) {
    int e = blockIdx.x * blockDim.x + threadIdx.x;
    if (e >= EE) return;
    int hn = h[e];
    int p  = atomicAdd(&g_wp[hn], 1);
    g_edge[p] = make_int2(t[e], __float_as_int(adj[e]));
}

// ---------------- smem layout for intent (Ps overlays As+Bs) ----------------
#define TM   128
#define ASP  136
#define BTP  68
#define PSP  132
#define IT_SMEM_FLOATS (64 * ASP + 64 * KK + KK * BTP)   // 25600
#define IT_SMEM_BYTES  (IT_SMEM_FLOATS * 4)              // 102400

// ---------------- spmm body (16-lane group per node); gnn + fp16 gnn̂ ----------------
__device__ __forceinline__ void spmm_body(int layer, float* __restrict__ out, int bx) {
    const float* __restrict__ ekIn = layer ? g_ekB : g_ekA;
    int t0 = bx * 256 + threadIdx.x;
    int g = t0 >> 4;
    int l = threadIdx.x & 15;
    unsigned m = 0xFFFFu << (threadIdx.x & 16);
    int s = g_rowptr[g], e = g_rowptr[g + 1];
    float4 acc = make_float4(0.f, 0.f, 0.f, 0.f);

    int p = s;
    for (; p + 3 < e; p += 4) {
        int2 e0 = __ldg(g_edge + p);
        int2 e1 = __ldg(g_edge + p + 1);
        int2 e2 = __ldg(g_edge + p + 2);
        int2 e3 = __ldg(g_edge + p + 3);
        float4 x0 = *(const float4*)(ekIn + (size_t)e0.x * DD + l * 4);
        float4 x1 = *(const float4*)(ekIn + (size_t)e1.x * DD + l * 4);
        float4 x2 = *(const float4*)(ekIn + (size_t)e2.x * DD + l * 4);
        float4 x3 = *(const float4*)(ekIn + (size_t)e3.x * DD + l * 4);
        float v0 = __int_as_float(e0.y), v1 = __int_as_float(e1.y);
        float v2 = __int_as_float(e2.y), v3 = __int_as_float(e3.y);
        acc.x = fmaf(v0, x0.x, acc.x); acc.y = fmaf(v0, x0.y, acc.y);
        acc.z = fmaf(v0, x0.z, acc.z); acc.w = fmaf(v0, x0.w, acc.w);
        acc.x = fmaf(v1, x1.x, acc.x); acc.y = fmaf(v1, x1.y, acc.y);
        acc.z = fmaf(v1, x1.z, acc.z); acc.w = fmaf(v1, x1.w, acc.w);
        acc.x = fmaf(v2, x2.x, acc.x); acc.y = fmaf(v2, x2.y, acc.y);
        acc.z = fmaf(v2, x2.z, acc.z); acc.w = fmaf(v2, x2.w, acc.w);
        acc.x = fmaf(v3, x3.x, acc.x); acc.y = fmaf(v3, x3.y, acc.y);
        acc.z = fmaf(v3, x3.z, acc.z); acc.w = fmaf(v3, x3.w, acc.w);
    }
    for (; p < e; p++) {
        int2 e0 = __ldg(g_edge + p);
        float4 x0 = *(const float4*)(ekIn + (size_t)e0.x * DD + l * 4);
        float v0 = __int_as_float(e0.y);
        acc.x = fmaf(v0, x0.x, acc.x); acc.y = fmaf(v0, x0.y, acc.y);
        acc.z = fmaf(v0, x0.z, acc.z); acc.w = fmaf(v0, x0.w, acc.w);
    }
    *(float4*)(out + (size_t)g * DD + l * 4) = acc;
    float sg = acc.x * acc.x + acc.y * acc.y + acc.z * acc.z + acc.w * acc.w;
#pragma unroll
    for (int o = 8; o > 0; o >>= 1) sg += __shfl_xor_sync(m, sg, o);
    float inv = 1.f / fmaxf(sqrtf(sg), 1e-12f);
    __half2 h0 = __floats2half2_rn(acc.x * inv, acc.y * inv);
    __half2 h1 = __floats2half2_rn(acc.z * inv, acc.w * inv);
    uint2 u;
    u.x = *(unsigned*)&h0;
    u.y = *(unsigned*)&h1;
    ((uint2*)g_nrm)[(size_t)g * 32 + l * 2] = u;   // g-part of chunk l
}

// ---------------- intent body: softmax(ek@W)@W^T per 128-row tile; itl + fp16 itl̂ ----------------
__device__ __forceinline__ void intent_body(int layer, const float* __restrict__ W,
                                            float* __restrict__ outIntl,
                                            int nodeBase, int nodeCount, int bx) {
    const float* __restrict__ ekIn = layer ? g_ekB : g_ekA;
    extern __shared__ float sm[];
    float* As = sm;                  // [64][ASP]   live through GEMM1
    float* Bs = sm + 64 * ASP;       // [64][128]   live through GEMM1
    float* Ps = sm;                  // [128][PSP]  live after GEMM1 (overlays As+Bs)
    float* Bt = sm + 64 * ASP + 64 * KK;  // [128][BTP]

    int tid = threadIdx.x;
    int tx = tid & 15, ty = tid >> 4;
    int rowTile = bx * TM;

#pragma unroll
    for (int it = 0; it < 8; it++) {
        int i = tid + it * 256;
        float4 v = ((const float4*)W)[i];
        int d = i >> 5;
        int k = (i << 2) & 127;
        *(float4*)(Bs + d * KK + k) = v;
        Bt[(k + 0) * BTP + d] = v.x;
        Bt[(k + 1) * BTP + d] = v.y;
        Bt[(k + 2) * BTP + d] = v.z;
        Bt[(k + 3) * BTP + d] = v.w;
    }
#pragma unroll
    for (int it = 0; it < 8; it++) {
        int i  = tid + it * 256;
        int rr = i >> 4;
        int d0 = (i << 2) & 63;
        float4 v = make_float4(0.f, 0.f, 0.f, 0.f);
        int r = rowTile + rr;
        if (r < nodeCount) v = *(const float4*)(ekIn + (size_t)(nodeBase + r) * DD + d0);
        As[(d0 + 0) * ASP + rr] = v.x;
        As[(d0 + 1) * ASP + rr] = v.y;
        As[(d0 + 2) * ASP + rr] = v.z;
        As[(d0 + 3) * ASP + rr] = v.w;
    }
    __syncthreads();

    const int r0 = ty * 8, k0 = tx * 8;

    // GEMM1 (packed f32x2), acc kept in registers
    u64 acc[8][4];
#pragma unroll
    for (int i = 0; i < 8; i++)
#pragma unroll
        for (int j = 0; j < 4; j++) acc[i][j] = 0ull;

#pragma unroll 4
    for (int d = 0; d < DD; d++) {
        float4 a0 = *(const float4*)(As + d * ASP + r0);
        float4 a1 = *(const float4*)(As + d * ASP + r0 + 4);
        const ulonglong2* bb = (const ulonglong2*)(Bs + d * KK + k0);
        ulonglong2 B0 = bb[0], B1 = bb[1];
        u64 av[8] = {pk1(a0.x), pk1(a0.y), pk1(a0.z), pk1(a0.w),
                     pk1(a1.x), pk1(a1.y), pk1(a1.z), pk1(a1.w)};
        u64 bv[4] = {B0.x, B0.y, B1.x, B1.y};
#pragma unroll
        for (int i = 0; i < 8; i++) {
            acc[i][0] = fma2(av[i], bv[0], acc[i][0]);
            acc[i][1] = fma2(av[i], bv[1], acc[i][1]);
            acc[i][2] = fma2(av[i], bv[2], acc[i][2]);
            acc[i][3] = fma2(av[i], bv[3], acc[i][3]);
        }
    }
    __syncthreads();                         // all As/Bs reads done before Ps overlay
#pragma unroll
    for (int i = 0; i < 8; i++) {
        u64* pr = (u64*)(Ps + (r0 + i) * PSP + k0);
        pr[0] = acc[i][0]; pr[1] = acc[i][1]; pr[2] = acc[i][2]; pr[3] = acc[i][3];
    }
    __syncthreads();

    // row softmax
    int warp = tid >> 5, lane = tid & 31;
    for (int rr = warp; rr < TM; rr += 8) {
        float4 v = *(float4*)(Ps + rr * PSP + lane * 4);
        float mx = fmaxf(fmaxf(v.x, v.y), fmaxf(v.z, v.w));
#pragma unroll
        for (int o = 16; o > 0; o >>= 1) mx = fmaxf(mx, __shfl_xor_sync(0xffffffffu, mx, o));
        float e0 = __expf(v.x - mx), e1 = __expf(v.y - mx);
        float e2 = __expf(v.z - mx), e3 = __expf(v.w - mx);
        float sum = e0 + e1 + e2 + e3;
#pragma unroll
        for (int o = 16; o > 0; o >>= 1) sum += __shfl_xor_sync(0xffffffffu, sum, o);
        float inv = 1.0f / sum;
        *(float4*)(Ps + rr * PSP + lane * 4) = make_float4(e0 * inv, e1 * inv, e2 * inv, e3 * inv);
    }
    __syncthreads();

    // GEMM2 (packed f32x2)
    u64 acc2[8][2];
#pragma unroll
    for (int i = 0; i < 8; i++) { acc2[i][0] = 0ull; acc2[i][1] = 0ull; }
    const int d0o = tx * 4;
#pragma unroll 2
    for (int k = 0; k < KK; k += 4) {
        float4 p[8];
#pragma unroll
        for (int i = 0; i < 8; i++) p[i] = *(const float4*)(Ps + (r0 + i) * PSP + k);
        ulonglong2 C0 = *(const ulonglong2*)(Bt + (k + 0) * BTP + d0o);
        ulonglong2 C1 = *(const ulonglong2*)(Bt + (k + 1) * BTP + d0o);
        ulonglong2 C2 = *(const ulonglong2*)(Bt + (k + 2) * BTP + d0o);
        ulonglong2 C3 = *(const ulonglong2*)(Bt + (k + 3) * BTP + d0o);
#pragma unroll
        for (int i = 0; i < 8; i++) {
            u64 t;
            t = pk1(p[i].x); acc2[i][0] = fma2(t, C0.x, acc2[i][0]); acc2[i][1] = fma2(t, C0.y, acc2[i][1]);
            t = pk1(p[i].y); acc2[i][0] = fma2(t, C1.x, acc2[i][0]); acc2[i][1] = fma2(t, C1.y, acc2[i][1]);
            t = pk1(p[i].z); acc2[i][0] = fma2(t, C2.x, acc2[i][0]); acc2[i][1] = fma2(t, C2.y, acc2[i][1]);
            t = pk1(p[i].w); acc2[i][0] = fma2(t, C3.x, acc2[i][0]); acc2[i][1] = fma2(t, C3.y, acc2[i][1]);
        }
    }
    // epilogue: store + itl̂ fp16 write
#pragma unroll
    for (int i = 0; i < 8; i++) {
        float2 lo = up2(acc2[i][0]);
        float2 hi = up2(acc2[i][1]);
        float4 o = make_float4(lo.x, lo.y, hi.x, hi.y);
        int r = rowTile + r0 + i;
        bool ok = (r < nodeCount);
        if (ok) *(float4*)(outIntl + (size_t)(nodeBase + r) * DD + d0o) = o;
        float ns = o.x * o.x + o.y * o.y + o.z * o.z + o.w * o.w;
#pragma unroll
        for (int off = 8; off > 0; off >>= 1) ns += __shfl_xor_sync(0xffffffffu, ns, off);
        float inv = 1.f / fmaxf(sqrtf(ns), 1e-12f);
        if (ok) {
            __half2 h0 = __floats2half2_rn(o.x * inv, o.y * inv);
            __half2 h1 = __floats2half2_rn(o.z * inv, o.w * inv);
            uint2 u;
            u.x = *(unsigned*)&h0;
            u.y = *(unsigned*)&h1;
            ((uint2*)g_nrm)[(size_t)(nodeBase + r) * 32 + tx * 2 + 1] = u;  // i-part of chunk tx
        }
    }
}

// ---------------- merged phase-1 kernel: interleaved intent/spmm dispatch ----------------
#define NB_IU ((UN + TM - 1) / TM)      // 782
#define NB_II ((INC + TM - 1) / TM)     // 391
#define NB_I  (NB_IU + NB_II)           // 1173
#define NB_SP (NN * 16 / 256)           // 9375

__global__ void __launch_bounds__(256, 2)
phase1_kernel(int layer, const float* __restrict__ Wu, const float* __restrict__ Wi,
              float* __restrict__ gnn, float* __restrict__ itl) {
    int bx = blockIdx.x;
    int k = bx >> 3;
    if ((bx & 7) == 0 && k < NB_I) {
        if (k < NB_IU) intent_body(layer, Wu, itl, 0, UN, k);
        else           intent_body(layer, Wi, itl, UN, INC, k - NB_IU);
    } else {
        int before = (bx + 7) >> 3;
        if (before > NB_I) before = NB_I;
        spmm_body(layer, gnn, bx - before);
    }
}

// ---------------- fused alpha + spmm2 + combine (16-lane group per node) ----------------
// per-edge alpha via half2 dots with head kept in half2 registers
#define EDGE_DOT(na_, dg_, di_)                                               \
    {                                                                         \
        __half2 pg = __hfma2(hgy, *(__half2*)&(na_).y,                        \
                             __hmul2(hgx, *(__half2*)&(na_).x));              \
        __half2 pi = __hfma2(hiy, *(__half2*)&(na_).w,                        \
                             __hmul2(hix, *(__half2*)&(na_).z));              \
        float2 pgf = __half22float2(pg);                                      \
        float2 pif = __half22float2(pi);                                      \
        dg_ = pgf.x + pgf.y;                                                  \
        di_ = pif.x + pif.y;                                                  \
    }

#define EDGE_ACC(ea_, a_g, a_i)                                               \
    {                                                                         \
        float2 k01 = __half22float2(*(__half2*)&(ea_).x);                     \
        float2 k23 = __half22float2(*(__half2*)&(ea_).y);                     \
        AG.x = fmaf(a_g, k01.x, AG.x); AG.y = fmaf(a_g, k01.y, AG.y);         \
        AG.z = fmaf(a_g, k23.x, AG.z); AG.w = fmaf(a_g, k23.y, AG.w);         \
        AI.x = fmaf(a_i, k01.x, AI.x); AI.y = fmaf(a_i, k01.y, AI.y);         \
        AI.z = fmaf(a_i, k23.x, AI.z); AI.w = fmaf(a_i, k23.y, AI.w);         \
        rsg += a_g; rsi += a_i;                                               \
    }

__global__ void __launch_bounds__(256)
fused_alpha_kernel(int layer,
                   const float* __restrict__ gnn, const float* __restrict__ itl,
                   float* __restrict__ gaa, float* __restrict__ iaa,
                   float* __restrict__ finalOut) {
    const float*  __restrict__ ekIn   = layer ? g_ekB : g_ekA;
    const __half* __restrict__ ekhIn  = layer ? g_ekhB : g_ekhA;
    float*        __restrict__ ekOut  = layer ? g_ekA : g_ekB;
    __half*       __restrict__ ekhOut = layer ? g_ekhA : g_ekhB;
    int t0 = blockIdx.x * blockDim.x + threadIdx.x;
    int g = t0 >> 4;
    int l = threadIdx.x & 15;
    unsigned m = 0xFFFFu << (threadIdx.x & 16);
    size_t ro = (size_t)g * DD + l * 4;
    const uint4* __restrict__ nrm4 = (const uint4*)g_nrm;
    const uint2* __restrict__ ekh2 = (const uint2*)ekhIn;

    uint4 hn = nrm4[(size_t)g * 16 + l];
    __half2 hgx = *(__half2*)&hn.x, hgy = *(__half2*)&hn.y;
    __half2 hix = *(__half2*)&hn.z, hiy = *(__half2*)&hn.w;

    float4 AG = make_float4(0.f, 0.f, 0.f, 0.f);
    float4 AI = make_float4(0.f, 0.f, 0.f, 0.f);
    float rsg = 0.f, rsi = 0.f;

    int s = g_rowptr[g], e = g_rowptr[g + 1];
    int p = s;
    for (; p + 3 < e; p += 4) {
        int ta = __ldg(&g_edge[p].x);
        int tb = __ldg(&g_edge[p + 1].x);
        int tc = __ldg(&g_edge[p + 2].x);
        int td = __ldg(&g_edge[p + 3].x);
        uint4 na = nrm4[(size_t)ta * 16 + l];
        uint4 nb = nrm4[(size_t)tb * 16 + l];
        uint4 nc = nrm4[(size_t)tc * 16 + l];
        uint4 nd = nrm4[(size_t)td * 16 + l];
        uint2 ea = ekh2[(size_t)ta * 16 + l];
        uint2 eb = ekh2[(size_t)tb * 16 + l];
        uint2 ec = ekh2[(size_t)tc * 16 + l];
        uint2 ed = ekh2[(size_t)td * 16 + l];

        float dga, dia, dgb, dib, dgc, dic, dgd, did;
        EDGE_DOT(na, dga, dia);
        EDGE_DOT(nb, dgb, dib);
        EDGE_DOT(nc, dgc, dic);
        EDGE_DOT(nd, dgd, did);
#pragma unroll
        for (int o = 8; o > 0; o >>= 1) {
            dga += __shfl_xor_sync(m, dga, o);
            dia += __shfl_xor_sync(m, dia, o);
            dgb += __shfl_xor_sync(m, dgb, o);
            dib += __shfl_xor_sync(m, dib, o);
            dgc += __shfl_xor_sync(m, dgc, o);
            dic += __shfl_xor_sync(m, dic, o);
            dgd += __shfl_xor_sync(m, dgd, o);
            did += __shfl_xor_sync(m, did, o);
        }
        float aga = (dga + 1.f) * 0.5f, aia = (dia + 1.f) * 0.5f;
        float agb = (dgb + 1.f) * 0.5f, aib = (dib + 1.f) * 0.5f;
        float agc = (dgc + 1.f) * 0.5f, aic = (dic + 1.f) * 0.5f;
        float agd = (dgd + 1.f) * 0.5f, aid = (did + 1.f) * 0.5f;
        EDGE_ACC(ea, aga, aia);
        EDGE_ACC(eb, agb, aib);
        EDGE_ACC(ec, agc, aic);
        EDGE_ACC(ed, agd, aid);
    }
    for (; p < e; p++) {
        int ta = __ldg(&g_edge[p].x);
        uint4 na = nrm4[(size_t)ta * 16 + l];
        uint2 ea = ekh2[(size_t)ta * 16 + l];
        float dga, dia;
        EDGE_DOT(na, dga, dia);
#pragma unroll
        for (int o = 8; o > 0; o >>= 1) {
            dga += __shfl_xor_sync(m, dga, o);
            dia += __shfl_xor_sync(m, dia, o);
        }
        float aga = (dga + 1.f) * 0.5f, aia = (dia + 1.f) * 0.5f;
        EDGE_ACC(ea, aga, aia);
    }
    float dg_inv = rsg > 0.f ? 1.f / rsg : 0.f;
    float di_inv = rsi > 0.f ? 1.f / rsi : 0.f;
    float4 gv = make_float4(AG.x * dg_inv, AG.y * dg_inv, AG.z * dg_inv, AG.w * dg_inv);
    float4 iv = make_float4(AI.x * di_inv, AI.y * di_inv, AI.z * di_inv, AI.w * di_inv);
    *(float4*)(gaa + ro) = gv;
    *(float4*)(iaa + ro) = iv;

    float4 hg0 = *(const float4*)(gnn + ro);
    float4 hi0 = *(const float4*)(itl + ro);
    float4 ekv = *(const float4*)(ekIn + ro);
    float4 en;
    en.x = hg0.x + hi0.x + gv.x + iv.x + ekv.x;
    en.y = hg0.y + hi0.y + gv.y + iv.y + ekv.y;
    en.z = hg0.z + hi0.z + gv.z + iv.z + ekv.z;
    en.w = hg0.w + hi0.w + gv.w + iv.w + ekv.w;
    float4 ac = *(const float4*)(g_accum + ro);
    ac.x += en.x; ac.y += en.y; ac.z += en.z; ac.w += en.w;
    if (finalOut) {
        *(float4*)(finalOut + ro) = ac;      // last layer: ekOut/accum never read again
    } else {
        *(float4*)(ekOut + ro) = en;
        __half2 h0 = __floats2half2_rn(en.x, en.y);
        __half2 h1 = __floats2half2_rn(en.z, en.w);
        uint2 u; u.x = *(unsigned*)&h0; u.y = *(unsigned*)&h1;
        ((uint2*)ekhOut)[(size_t)g * 16 + l] = u;
        *(float4*)(g_accum + ro) = ac;
    }
}

// ---------------- launch ----------------
extern "C" void kernel_launch(void* const* d_in, const int* in_sizes, int n_in,
                              void* d_out, int out_size) {
    const float* user_emb = (const float*)d_in[0];
    const float* item_emb = (const float*)d_in[1];
    const float* Wu       = (const float*)d_in[2];
    const float* Wi       = (const float*)d_in[3];
    const float* adj      = (const float*)d_in[4];
    const int*   h        = (const int*)d_in[5];
    const int*   t        = (const int*)d_in[6];
    (void)in_sizes; (void)n_in; (void)out_size;

    float* out = (float*)d_out;
    const size_t ND = (size_t)NN * DD;
    float* out_ua  = out;                    // [N*D] = ua | ia
    float* out_gnn = out + ND;               // [L][N][D]
    float* out_int = out_gnn + (size_t)LL * ND;
    float* out_gaa = out_int + (size_t)LL * ND;
    float* out_iaa = out_gaa + (size_t)LL * ND;

    cudaFuncSetAttribute(phase1_kernel, cudaFuncAttributeMaxDynamicSharedMemorySize, IT_SMEM_BYTES);

    const int TPB = 256;
    const int SCAN_NB = (NN + 1023) / 1024;  // 147
    init_ek_kernel<<<(NN * DD / 4 + TPB - 1) / TPB, TPB>>>((const float4*)user_emb,
                                                           (const float4*)item_emb);
    hist_kernel<<<(EE + TPB - 1) / TPB, TPB>>>(h);
    reduce_scan_kernel<<<SCAN_NB, 1024>>>();
    apply_scan_kernel<<<SCAN_NB, 1024>>>();
    scatter_kernel<<<(EE + TPB - 1) / TPB, TPB>>>(h, t, adj);

    const int NODE_BLOCKS = NN * 16 / TPB;   // 9375
    for (int l = 0; l < LL; l++) {
        float* gnn = out_gnn + (size_t)l * ND;
        float* itl = out_int + (size_t)l * ND;
        float* gaa = out_gaa + (size_t)l * ND;
        float* iaa = out_iaa + (size_t)l * ND;

        phase1_kernel<<<NB_I + NB_SP, TPB, IT_SMEM_BYTES>>>(l, Wu, Wi, gnn, itl);
        fused_alpha_kernel<<<NODE_BLOCKS, TPB>>>(l, gnn, itl, gaa, iaa,
                                                 (l == LL - 1) ? out_ua : nullptr);
    }
}

// round 9
// speedup vs baseline: 1.6870x; 1.4543x over previous
#include <cuda_runtime.h>
#include <cuda_fp16.h>
#include <mma.h>

using namespace nvcuda;

// ---------------- problem constants ----------------
#define UN  100000
#define INC 50000
#define NN  150000
#define DD  64
#define KK  128
#define EE  1250000
#define LL  2

typedef unsigned long long u64;

// ---------------- device scratch (static; no allocations) ----------------
__device__ float g_ekA[NN * DD];
__device__ float g_ekB[NN * DD];
__device__ __half g_ekhA[NN * DD];
__device__ __half g_ekhB[NN * DD];
__device__ float g_accum[NN * DD];
__device__ int   g_cnt[NN];
__device__ int   g_rowptr[NN + 1];
__device__ int   g_wp[NN];
__device__ int2  g_edge[EE];        // {tail, adj-as-int} in CSR order
// packed normalized vectors: per node 16 chunks of 16B; chunk c = {gnn̂[4c..4c+3], itl̂[4c..4c+3]} fp16
__device__ __half g_nrm[NN * 128];
__device__ int   g_bsum[160];
__device__ int   g_boff[160];
__device__ int   g_done;

// ---------------- init (ek fp32+fp16, accum, cnt=0, done=0) ----------------
__global__ void init_ek_kernel(const float4* __restrict__ ue, const float4* __restrict__ ie) {
    int i = blockIdx.x * blockDim.x + threadIdx.x;
    const int TOT = NN * DD / 4, UD4 = UN * DD / 4;
    if (i == 0) g_done = 0;
    if (i < NN) g_cnt[i] = 0;
    if (i >= TOT) return;
    float4 v = (i < UD4) ? ue[i] : ie[i - UD4];
    ((float4*)g_ekA)[i]   = v;
    ((float4*)g_accum)[i] = v;
    __half2 h0 = __floats2half2_rn(v.x, v.y);
    __half2 h1 = __floats2half2_rn(v.z, v.w);
    uint2 u; u.x = *(unsigned*)&h0; u.y = *(unsigned*)&h1;
    ((uint2*)g_ekhA)[i] = u;
}

// ---------------- CSR build ----------------
__global__ void hist_kernel(const int* __restrict__ h) {
    int e = blockIdx.x * blockDim.x + threadIdx.x;
    if (e < EE) atomicAdd(&g_cnt[h[e]], 1);
}

__global__ void reduce_scan_kernel() {
    __shared__ int s[1024];
    __shared__ bool amLast;
    int tid = threadIdx.x;
    int idx = blockIdx.x * 1024 + tid;
    s[tid] = (idx < NN) ? g_cnt[idx] : 0;
    __syncthreads();
    for (int o = 512; o > 0; o >>= 1) {
        if (tid < o) s[tid] += s[tid + o];
        __syncthreads();
    }
    if (tid == 0) {
        g_bsum[blockIdx.x] = s[0];
        __threadfence();
        amLast = (atomicAdd(&g_done, 1) == gridDim.x - 1);
    }
    __syncthreads();
    if (amLast) {
        int nblk = gridDim.x;
        int v = (tid < nblk) ? g_bsum[tid] : 0;
        s[tid] = v;
        __syncthreads();
        for (int off = 1; off < 1024; off <<= 1) {
            int t = (tid >= off) ? s[tid - off] : 0;
            __syncthreads();
            s[tid] += t;
            __syncthreads();
        }
        if (tid < nblk) g_boff[tid] = s[tid] - v;   // exclusive
    }
}

__global__ void apply_scan_kernel() {
    __shared__ int s[1024];
    int tid = threadIdx.x;
    int idx = blockIdx.x * 1024 + tid;
    int v = (idx < NN) ? g_cnt[idx] : 0;
    s[tid] = v;
    __syncthreads();
    for (int off = 1; off < 1024; off <<= 1) {
        int t = (tid >= off) ? s[tid - off] : 0;
        __syncthreads();
        s[tid] += t;
        __syncthreads();
    }
    int excl = s[tid] - v + g_boff[blockIdx.x];
    if (idx < NN) { g_rowptr[idx] = excl; g_wp[idx] = excl; }
    if (blockIdx.x == 0 && tid == 0) g_rowptr[NN] = EE;
}

__global__ void scatter_kernel(const int* __restrict__ h, const int* __restrict__ t,
                               const float* __restrict__ adj) {
    int e = blockIdx.x * blockDim.x + threadIdx.x;
    if (e >= EE) return;
    int hn = h[e];
    int p  = atomicAdd(&g_wp[hn], 1);
    g_edge[p] = make_int2(t[e], __float_as_int(adj[e]));
}

// ---------------- smem layout for tensor-core intent (TM=64) ----------------
// [Wh  : half 64x136 = 17408 B]
// [Ah/Ph (overlay): half region 17408 B]  Ah = 64x72, Ph = 64x136
// [Ps  : float 64x132 = 33792 B]
#define TM 64
#define WH_LD 136
#define AH_LD 72
#define PH_LD 136
#define PS_LD 132
#define IT_SMEM_BYTES (17408 + 17408 + 33792)   // 68608

// ---------------- spmm body (16-lane group per node); gnn + fp16 gnn̂ ----------------
__device__ __forceinline__ void spmm_body(int layer, float* __restrict__ out, int bx) {
    const float* __restrict__ ekIn = layer ? g_ekB : g_ekA;
    int t0 = bx * 256 + threadIdx.x;
    int g = t0 >> 4;
    int l = threadIdx.x & 15;
    unsigned m = 0xFFFFu << (threadIdx.x & 16);
    int s = g_rowptr[g], e = g_rowptr[g + 1];
    float4 acc = make_float4(0.f, 0.f, 0.f, 0.f);

    int p = s;
    for (; p + 3 < e; p += 4) {
        int2 e0 = __ldg(g_edge + p);
        int2 e1 = __ldg(g_edge + p + 1);
        int2 e2 = __ldg(g_edge + p + 2);
        int2 e3 = __ldg(g_edge + p + 3);
        float4 x0 = *(const float4*)(ekIn + (size_t)e0.x * DD + l * 4);
        float4 x1 = *(const float4*)(ekIn + (size_t)e1.x * DD + l * 4);
        float4 x2 = *(const float4*)(ekIn + (size_t)e2.x * DD + l * 4);
        float4 x3 = *(const float4*)(ekIn + (size_t)e3.x * DD + l * 4);
        float v0 = __int_as_float(e0.y), v1 = __int_as_float(e1.y);
        float v2 = __int_as_float(e2.y), v3 = __int_as_float(e3.y);
        acc.x = fmaf(v0, x0.x, acc.x); acc.y = fmaf(v0, x0.y, acc.y);
        acc.z = fmaf(v0, x0.z, acc.z); acc.w = fmaf(v0, x0.w, acc.w);
        acc.x = fmaf(v1, x1.x, acc.x); acc.y = fmaf(v1, x1.y, acc.y);
        acc.z = fmaf(v1, x1.z, acc.z); acc.w = fmaf(v1, x1.w, acc.w);
        acc.x = fmaf(v2, x2.x, acc.x); acc.y = fmaf(v2, x2.y, acc.y);
        acc.z = fmaf(v2, x2.z, acc.z); acc.w = fmaf(v2, x2.w, acc.w);
        acc.x = fmaf(v3, x3.x, acc.x); acc.y = fmaf(v3, x3.y, acc.y);
        acc.z = fmaf(v3, x3.z, acc.z); acc.w = fmaf(v3, x3.w, acc.w);
    }
    for (; p < e; p++) {
        int2 e0 = __ldg(g_edge + p);
        float4 x0 = *(const float4*)(ekIn + (size_t)e0.x * DD + l * 4);
        float v0 = __int_as_float(e0.y);
        acc.x = fmaf(v0, x0.x, acc.x); acc.y = fmaf(v0, x0.y, acc.y);
        acc.z = fmaf(v0, x0.z, acc.z); acc.w = fmaf(v0, x0.w, acc.w);
    }
    *(float4*)(out + (size_t)g * DD + l * 4) = acc;
    float sg = acc.x * acc.x + acc.y * acc.y + acc.z * acc.z + acc.w * acc.w;
#pragma unroll
    for (int o = 8; o > 0; o >>= 1) sg += __shfl_xor_sync(m, sg, o);
    float inv = 1.f / fmaxf(sqrtf(sg), 1e-12f);
    __half2 h0 = __floats2half2_rn(acc.x * inv, acc.y * inv);
    __half2 h1 = __floats2half2_rn(acc.z * inv, acc.w * inv);
    uint2 u;
    u.x = *(unsigned*)&h0;
    u.y = *(unsigned*)&h1;
    ((uint2*)g_nrm)[(size_t)g * 32 + l * 2] = u;   // g-part of chunk l
}

// ---------------- intent body (tensor cores): softmax(ek@W)@W^T per 64-row tile ----------------
__device__ __forceinline__ void intent_body(int layer, const float* __restrict__ W,
                                            float* __restrict__ outIntl,
                                            int nodeBase, int nodeCount, int bx) {
    const __half* __restrict__ ekhIn = layer ? g_ekhB : g_ekhA;
    extern __shared__ char smc[];
    __half* Wh = (__half*)smc;                  // [64][136]
    __half* Ah = (__half*)(smc + 17408);        // [64][72]  (dead after GEMM1)
    __half* Ph = (__half*)(smc + 17408);        // [64][136] (overlays Ah)
    float*  Ps = (float*)(smc + 34816);         // [64][132]

    int tid = threadIdx.x;
    int warp = tid >> 5, lane = tid & 31;
    int rowTile = bx * TM;

    // load W (fp32 -> fp16) into Wh: 2048 float4s, 8 per thread
#pragma unroll
    for (int it = 0; it < 8; it++) {
        int i = tid + it * 256;                  // float4 index
        float4 v = __ldg((const float4*)W + i);
        int d  = i >> 5;
        int k4 = (i & 31) * 4;
        __half2 h0 = __floats2half2_rn(v.x, v.y);
        __half2 h1 = __floats2half2_rn(v.z, v.w);
        uint2 u; u.x = *(unsigned*)&h0; u.y = *(unsigned*)&h1;
        *(uint2*)(Wh + d * WH_LD + k4) = u;
    }
    // load A rows from fp16 ek: 64 rows x 128B; 4 threads per row, 32B each
    {
        int row = tid >> 2;
        int seg = tid & 3;
        uint4 z0 = make_uint4(0, 0, 0, 0), z1 = make_uint4(0, 0, 0, 0);
        int r = rowTile + row;
        if (r < nodeCount) {
            const uint4* src = (const uint4*)(ekhIn + (size_t)(nodeBase + r) * DD) + seg * 2;
            z0 = src[0]; z1 = src[1];
        }
        uint4* dst = (uint4*)(Ah + row * AH_LD + seg * 16);
        dst[0] = z0; dst[1] = z1;
    }
    __syncthreads();

    // GEMM1: logits[64][128] = A[64][64] @ W[64][128]   (warp grid 4M x 2N)
    {
        int wm = warp >> 1, wn = warp & 1;
        wmma::fragment<wmma::matrix_a, 16, 16, 16, __half, wmma::row_major> a[4];
#pragma unroll
        for (int kt = 0; kt < 4; kt++)
            wmma::load_matrix_sync(a[kt], Ah + wm * 16 * AH_LD + kt * 16, AH_LD);
#pragma unroll
        for (int nt = 0; nt < 4; nt++) {
            wmma::fragment<wmma::accumulator, 16, 16, 16, float> c;
            wmma::fill_fragment(c, 0.f);
#pragma unroll
            for (int kt = 0; kt < 4; kt++) {
                wmma::fragment<wmma::matrix_b, 16, 16, 16, __half, wmma::row_major> b;
                wmma::load_matrix_sync(b, Wh + kt * 16 * WH_LD + wn * 64 + nt * 16, WH_LD);
                wmma::mma_sync(c, a[kt], b, c);
            }
            wmma::store_matrix_sync(Ps + wm * 16 * PS_LD + wn * 64 + nt * 16, c, PS_LD,
                                    wmma::mem_row_major);
        }
    }
    __syncthreads();

    // row softmax on Ps (fp32), write probs fp16 to Ph
    for (int rr = warp; rr < TM; rr += 8) {
        float4 v = *(float4*)(Ps + rr * PS_LD + lane * 4);
        float mx = fmaxf(fmaxf(v.x, v.y), fmaxf(v.z, v.w));
#pragma unroll
        for (int o = 16; o > 0; o >>= 1) mx = fmaxf(mx, __shfl_xor_sync(0xffffffffu, mx, o));
        float e0 = __expf(v.x - mx), e1 = __expf(v.y - mx);
        float e2 = __expf(v.z - mx), e3 = __expf(v.w - mx);
        float sum = e0 + e1 + e2 + e3;
#pragma unroll
        for (int o = 16; o > 0; o >>= 1) sum += __shfl_xor_sync(0xffffffffu, sum, o);
        float inv = 1.0f / sum;
        __half2 h0 = __floats2half2_rn(e0 * inv, e1 * inv);
        __half2 h1 = __floats2half2_rn(e2 * inv, e3 * inv);
        uint2 u; u.x = *(unsigned*)&h0; u.y = *(unsigned*)&h1;
        *(uint2*)(Ph + rr * PH_LD + lane * 4) = u;
    }
    __syncthreads();

    // GEMM2: out[64][64] = P[64][128] @ W^T[128][64]  (B = Wh col-major; warp grid 4M x 2N)
    {
        int wm = warp >> 1, wn = warp & 1;
#pragma unroll
        for (int nt = 0; nt < 2; nt++) {
            wmma::fragment<wmma::accumulator, 16, 16, 16, float> c;
            wmma::fill_fragment(c, 0.f);
#pragma unroll
            for (int kt = 0; kt < 8; kt++) {
                wmma::fragment<wmma::matrix_a, 16, 16, 16, __half, wmma::row_major> a;
                wmma::fragment<wmma::matrix_b, 16, 16, 16, __half, wmma::col_major> b;
                wmma::load_matrix_sync(a, Ph + wm * 16 * PH_LD + kt * 16, PH_LD);
                wmma::load_matrix_sync(b, Wh + (wn * 32 + nt * 16) * WH_LD + kt * 16, WH_LD);
                wmma::mma_sync(c, a, b, c);
            }
            wmma::store_matrix_sync(Ps + wm * 16 * PS_LD + wn * 32 + nt * 16, c, PS_LD,
                                    wmma::mem_row_major);
        }
    }
    __syncthreads();

    // epilogue: store itl (fp32) + row norms + g_nrm i-part (fp16)
    for (int rr = warp; rr < TM; rr += 8) {
        float2 v = *(float2*)(Ps + rr * PS_LD + lane * 2);
        float ns = v.x * v.x + v.y * v.y;
#pragma unroll
        for (int o = 16; o > 0; o >>= 1) ns += __shfl_xor_sync(0xffffffffu, ns, o);
        float inv = 1.f / fmaxf(sqrtf(ns), 1e-12f);
        __half2 hv = __floats2half2_rn(v.x * inv, v.y * inv);
        unsigned lo = *(unsigned*)&hv;
        unsigned hi = __shfl_down_sync(0xffffffffu, lo, 1);
        int r = rowTile + rr;
        if (r < nodeCount) {
            *(float2*)(outIntl + (size_t)(nodeBase + r) * DD + lane * 2) = v;
            if ((lane & 1) == 0) {
                uint2 u; u.x = lo; u.y = hi;
                ((uint2*)g_nrm)[(size_t)(nodeBase + r) * 32 + (lane >> 1) * 2 + 1] = u;
            }
        }
    }
}

// ---------------- merged phase-1 kernel: interleaved intent/spmm dispatch ----------------
#define NB_IU ((UN + TM - 1) / TM)      // 1563
#define NB_II ((INC + TM - 1) / TM)     // 782
#define NB_I  (NB_IU + NB_II)           // 2345
#define NB_SP (NN * 16 / 256)           // 9375

__global__ void __launch_bounds__(256)
phase1_kernel(int layer, const float* __restrict__ Wu, const float* __restrict__ Wi,
              float* __restrict__ gnn, float* __restrict__ itl) {
    int bx = blockIdx.x;
    int k = bx >> 2;
    if ((bx & 3) == 0 && k < NB_I) {
        if (k < NB_IU) intent_body(layer, Wu, itl, 0, UN, k);
        else           intent_body(layer, Wi, itl, UN, INC, k - NB_IU);
    } else {
        int before = (bx >> 2) + 1;
        if (before > NB_I) before = NB_I;
        spmm_body(layer, gnn, bx - before);
    }
}

// ---------------- fused alpha + spmm2 + combine (16-lane group per node) ----------------
#define EDGE_DOT(na_, dg_, di_)                                               \
    {                                                                         \
        __half2 pg = __hfma2(hgy, *(__half2*)&(na_).y,                        \
                             __hmul2(hgx, *(__half2*)&(na_).x));              \
        __half2 pi = __hfma2(hiy, *(__half2*)&(na_).w,                        \
                             __hmul2(hix, *(__half2*)&(na_).z));              \
        float2 pgf = __half22float2(pg);                                      \
        float2 pif = __half22float2(pi);                                      \
        dg_ = pgf.x + pgf.y;                                                  \
        di_ = pif.x + pif.y;                                                  \
    }

#define EDGE_ACC(ea_, a_g, a_i)                                               \
    {                                                                         \
        float2 k01 = __half22float2(*(__half2*)&(ea_).x);                     \
        float2 k23 = __half22float2(*(__half2*)&(ea_).y);                     \
        AG.x = fmaf(a_g, k01.x, AG.x); AG.y = fmaf(a_g, k01.y, AG.y);         \
        AG.z = fmaf(a_g, k23.x, AG.z); AG.w = fmaf(a_g, k23.y, AG.w);         \
        AI.x = fmaf(a_i, k01.x, AI.x); AI.y = fmaf(a_i, k01.y, AI.y);         \
        AI.z = fmaf(a_i, k23.x, AI.z); AI.w = fmaf(a_i, k23.y, AI.w);         \
        rsg += a_g; rsi += a_i;                                               \
    }

__global__ void __launch_bounds__(256)
fused_alpha_kernel(int layer,
                   const float* __restrict__ gnn, const float* __restrict__ itl,
                   float* __restrict__ gaa, float* __restrict__ iaa,
                   float* __restrict__ finalOut) {
    const float*  __restrict__ ekIn   = layer ? g_ekB : g_ekA;
    const __half* __restrict__ ekhIn  = layer ? g_ekhB : g_ekhA;
    float*        __restrict__ ekOut  = layer ? g_ekA : g_ekB;
    __half*       __restrict__ ekhOut = layer ? g_ekhA : g_ekhB;
    int t0 = blockIdx.x * blockDim.x + threadIdx.x;
    int g = t0 >> 4;
    int l = threadIdx.x & 15;
    unsigned m = 0xFFFFu << (threadIdx.x & 16);
    size_t ro = (size_t)g * DD + l * 4;
    const uint4* __restrict__ nrm4 = (const uint4*)g_nrm;
    const uint2* __restrict__ ekh2 = (const uint2*)ekhIn;

    uint4 hn = nrm4[(size_t)g * 16 + l];
    __half2 hgx = *(__half2*)&hn.x, hgy = *(__half2*)&hn.y;
    __half2 hix = *(__half2*)&hn.z, hiy = *(__half2*)&hn.w;

    float4 AG = make_float4(0.f, 0.f, 0.f, 0.f);
    float4 AI = make_float4(0.f, 0.f, 0.f, 0.f);
    float rsg = 0.f, rsi = 0.f;

    int s = g_rowptr[g], e = g_rowptr[g + 1];
    int p = s;
    for (; p + 3 < e; p += 4) {
        int ta = __ldg(&g_edge[p].x);
        int tb = __ldg(&g_edge[p + 1].x);
        int tc = __ldg(&g_edge[p + 2].x);
        int td = __ldg(&g_edge[p + 3].x);
        uint4 na = nrm4[(size_t)ta * 16 + l];
        uint4 nb = nrm4[(size_t)tb * 16 + l];
        uint4 nc = nrm4[(size_t)tc * 16 + l];
        uint4 nd = nrm4[(size_t)td * 16 + l];
        uint2 ea = ekh2[(size_t)ta * 16 + l];
        uint2 eb = ekh2[(size_t)tb * 16 + l];
        uint2 ec = ekh2[(size_t)tc * 16 + l];
        uint2 ed = ekh2[(size_t)td * 16 + l];

        float dga, dia, dgb, dib, dgc, dic, dgd, did;
        EDGE_DOT(na, dga, dia);
        EDGE_DOT(nb, dgb, dib);
        EDGE_DOT(nc, dgc, dic);
        EDGE_DOT(nd, dgd, did);
#pragma unroll
        for (int o = 8; o > 0; o >>= 1) {
            dga += __shfl_xor_sync(m, dga, o);
            dia += __shfl_xor_sync(m, dia, o);
            dgb += __shfl_xor_sync(m, dgb, o);
            dib += __shfl_xor_sync(m, dib, o);
            dgc += __shfl_xor_sync(m, dgc, o);
            dic += __shfl_xor_sync(m, dic, o);
            dgd += __shfl_xor_sync(m, dgd, o);
            did += __shfl_xor_sync(m, did, o);
        }
        float aga = (dga + 1.f) * 0.5f, aia = (dia + 1.f) * 0.5f;
        float agb = (dgb + 1.f) * 0.5f, aib = (dib + 1.f) * 0.5f;
        float agc = (dgc + 1.f) * 0.5f, aic = (dic + 1.f) * 0.5f;
        float agd = (dgd + 1.f) * 0.5f, aid = (did + 1.f) * 0.5f;
        EDGE_ACC(ea, aga, aia);
        EDGE_ACC(eb, agb, aib);
        EDGE_ACC(ec, agc, aic);
        EDGE_ACC(ed, agd, aid);
    }
    for (; p < e; p++) {
        int ta = __ldg(&g_edge[p].x);
        uint4 na = nrm4[(size_t)ta * 16 + l];
        uint2 ea = ekh2[(size_t)ta * 16 + l];
        float dga, dia;
        EDGE_DOT(na, dga, dia);
#pragma unroll
        for (int o = 8; o > 0; o >>= 1) {
            dga += __shfl_xor_sync(m, dga, o);
            dia += __shfl_xor_sync(m, dia, o);
        }
        float aga = (dga + 1.f) * 0.5f, aia = (dia + 1.f) * 0.5f;
        EDGE_ACC(ea, aga, aia);
    }
    float dg_inv = rsg > 0.f ? 1.f / rsg : 0.f;
    float di_inv = rsi > 0.f ? 1.f / rsi : 0.f;
    float4 gv = make_float4(AG.x * dg_inv, AG.y * dg_inv, AG.z * dg_inv, AG.w * dg_inv);
    float4 iv = make_float4(AI.x * di_inv, AI.y * di_inv, AI.z * di_inv, AI.w * di_inv);
    *(float4*)(gaa + ro) = gv;
    *(float4*)(iaa + ro) = iv;

    float4 hg0 = *(const float4*)(gnn + ro);
    float4 hi0 = *(const float4*)(itl + ro);
    float4 ekv = *(const float4*)(ekIn + ro);
    float4 en;
    en.x = hg0.x + hi0.x + gv.x + iv.x + ekv.x;
    en.y = hg0.y + hi0.y + gv.y + iv.y + ekv.y;
    en.z = hg0.z + hi0.z + gv.z + iv.z + ekv.z;
    en.w = hg0.w + hi0.w + gv.w + iv.w + ekv.w;
    float4 ac = *(const float4*)(g_accum + ro);
    ac.x += en.x; ac.y += en.y; ac.z += en.z; ac.w += en.w;
    if (finalOut) {
        *(float4*)(finalOut + ro) = ac;      // last layer: ekOut/accum never read again
    } else {
        *(float4*)(ekOut + ro) = en;
        __half2 h0 = __floats2half2_rn(en.x, en.y);
        __half2 h1 = __floats2half2_rn(en.z, en.w);
        uint2 u; u.x = *(unsigned*)&h0; u.y = *(unsigned*)&h1;
        ((uint2*)ekhOut)[(size_t)g * 16 + l] = u;
        *(float4*)(g_accum + ro) = ac;
    }
}

// ---------------- launch ----------------
extern "C" void kernel_launch(void* const* d_in, const int* in_sizes, int n_in,
                              void* d_out, int out_size) {
    const float* user_emb = (const float*)d_in[0];
    const float* item_emb = (const float*)d_in[1];
    const float* Wu       = (const float*)d_in[2];
    const float* Wi       = (const float*)d_in[3];
    const float* adj      = (const float*)d_in[4];
    const int*   h        = (const int*)d_in[5];
    const int*   t        = (const int*)d_in[6];
    (void)in_sizes; (void)n_in; (void)out_size;

    float* out = (float*)d_out;
    const size_t ND = (size_t)NN * DD;
    float* out_ua  = out;                    // [N*D] = ua | ia
    float* out_gnn = out + ND;               // [L][N][D]
    float* out_int = out_gnn + (size_t)LL * ND;
    float* out_gaa = out_int + (size_t)LL * ND;
    float* out_iaa = out_gaa + (size_t)LL * ND;

    cudaFuncSetAttribute(phase1_kernel, cudaFuncAttributeMaxDynamicSharedMemorySize, IT_SMEM_BYTES);

    const int TPB = 256;
    const int SCAN_NB = (NN + 1023) / 1024;  // 147
    init_ek_kernel<<<(NN * DD / 4 + TPB - 1) / TPB, TPB>>>((const float4*)user_emb,
                                                           (const float4*)item_emb);
    hist_kernel<<<(EE + TPB - 1) / TPB, TPB>>>(h);
    reduce_scan_kernel<<<SCAN_NB, 1024>>>();
    apply_scan_kernel<<<SCAN_NB, 1024>>>();
    scatter_kernel<<<(EE + TPB - 1) / TPB, TPB>>>(h, t, adj);

    const int NODE_BLOCKS = NN * 16 / TPB;   // 9375
    for (int l = 0; l < LL; l++) {
        float* gnn = out_gnn + (size_t)l * ND;
        float* itl = out_int + (size_t)l * ND;
        float* gaa = out_gaa + (size_t)l * ND;
        float* iaa = out_iaa + (size_t)l * ND;

        phase1_kernel<<<NB_I + NB_SP, TPB, IT_SMEM_BYTES>>>(l, Wu, Wi, gnn, itl);
        fused_alpha_kernel<<<NODE_BLOCKS, TPB>>>(l, gnn, itl, gaa, iaa,
                                                 (l == LL - 1) ? out_ua : nullptr);
    }
}

// round 10
// speedup vs baseline: 1.7240x; 1.0219x over previous
#include <cuda_runtime.h>
#include <cuda_fp16.h>
#include <mma.h>

using namespace nvcuda;

// ---------------- problem constants ----------------
#define UN  100000
#define INC 50000
#define NN  150000
#define DD  64
#define KK  128
#define EE  1250000
#define LL  2

typedef unsigned long long u64;

// ---------------- device scratch (static; no allocations) ----------------
__device__ float g_ekA[NN * DD];
__device__ float g_ekB[NN * DD];
__device__ __half g_ekhA[NN * DD];
__device__ __half g_ekhB[NN * DD];
__device__ float g_accum[NN * DD];
__device__ int   g_cnt[NN];
__device__ int   g_rowptr[NN + 1];
__device__ int   g_wp[NN];
__device__ int2  g_edge[EE];        // {tail, adj-as-int} in CSR order
// packed normalized vectors: per node 16 chunks of 16B; chunk c = {gnn̂[4c..4c+3], itl̂[4c..4c+3]} fp16
__device__ __half g_nrm[NN * 128];
__device__ int   g_bsum[160];
__device__ int   g_boff[160];
__device__ int   g_done;

// ---------------- init (ek fp32+fp16, accum, cnt=0, done=0) ----------------
__global__ void init_ek_kernel(const float4* __restrict__ ue, const float4* __restrict__ ie) {
    int i = blockIdx.x * blockDim.x + threadIdx.x;
    const int TOT = NN * DD / 4, UD4 = UN * DD / 4;
    if (i == 0) g_done = 0;
    if (i < NN) g_cnt[i] = 0;
    if (i >= TOT) return;
    float4 v = (i < UD4) ? ue[i] : ie[i - UD4];
    ((float4*)g_ekA)[i]   = v;
    ((float4*)g_accum)[i] = v;
    __half2 h0 = __floats2half2_rn(v.x, v.y);
    __half2 h1 = __floats2half2_rn(v.z, v.w);
    uint2 u; u.x = *(unsigned*)&h0; u.y = *(unsigned*)&h1;
    ((uint2*)g_ekhA)[i] = u;
}

// ---------------- CSR build ----------------
__global__ void hist_kernel(const int4* __restrict__ h4) {
    int i = blockIdx.x * blockDim.x + threadIdx.x;
    if (i >= EE / 4) return;
    int4 v = __ldg(h4 + i);
    atomicAdd(&g_cnt[v.x], 1);
    atomicAdd(&g_cnt[v.y], 1);
    atomicAdd(&g_cnt[v.z], 1);
    atomicAdd(&g_cnt[v.w], 1);
}

__global__ void reduce_scan_kernel() {
    __shared__ int s[1024];
    __shared__ bool amLast;
    int tid = threadIdx.x;
    int idx = blockIdx.x * 1024 + tid;
    s[tid] = (idx < NN) ? g_cnt[idx] : 0;
    __syncthreads();
    for (int o = 512; o > 0; o >>= 1) {
        if (tid < o) s[tid] += s[tid + o];
        __syncthreads();
    }
    if (tid == 0) {
        g_bsum[blockIdx.x] = s[0];
        __threadfence();
        amLast = (atomicAdd(&g_done, 1) == gridDim.x - 1);
    }
    __syncthreads();
    if (amLast) {
        int nblk = gridDim.x;
        int v = (tid < nblk) ? g_bsum[tid] : 0;
        s[tid] = v;
        __syncthreads();
        for (int off = 1; off < 1024; off <<= 1) {
            int t = (tid >= off) ? s[tid - off] : 0;
            __syncthreads();
            s[tid] += t;
            __syncthreads();
        }
        if (tid < nblk) g_boff[tid] = s[tid] - v;   // exclusive
    }
}

__global__ void apply_scan_kernel() {
    __shared__ int s[1024];
    int tid = threadIdx.x;
    int idx = blockIdx.x * 1024 + tid;
    int v = (idx < NN) ? g_cnt[idx] : 0;
    s[tid] = v;
    __syncthreads();
    for (int off = 1; off < 1024; off <<= 1) {
        int t = (tid >= off) ? s[tid - off] : 0;
        __syncthreads();
        s[tid] += t;
        __syncthreads();
    }
    int excl = s[tid] - v + g_boff[blockIdx.x];
    if (idx < NN) { g_rowptr[idx] = excl; g_wp[idx] = excl; }
    if (blockIdx.x == 0 && tid == 0) g_rowptr[NN] = EE;
}

__global__ void scatter_kernel(const int* __restrict__ h, const int* __restrict__ t,
                               const float* __restrict__ adj) {
    int e = blockIdx.x * blockDim.x + threadIdx.x;
    if (e >= EE) return;
    int hn = h[e];
    int p  = atomicAdd(&g_wp[hn], 1);
    g_edge[p] = make_int2(t[e], __float_as_int(adj[e]));
}

// ---------------- smem layout for tensor-core intent (TM=64) ----------------
#define TM 64
#define WH_LD 136
#define AH_LD 72
#define PH_LD 136
#define PS_LD 132
#define IT_SMEM_BYTES (17408 + 17408 + 33792)   // 68608

// ---------------- spmm body (16-lane group per node); fp16 gathers; gnn + fp16 gnn̂ ----------------
__device__ __forceinline__ void spmm_body(int layer, float* __restrict__ out, int bx) {
    const __half* __restrict__ ekhIn = layer ? g_ekhB : g_ekhA;
    const uint2* __restrict__ ekh2 = (const uint2*)ekhIn;
    int t0 = bx * 256 + threadIdx.x;
    int g = t0 >> 4;
    int l = threadIdx.x & 15;
    unsigned m = 0xFFFFu << (threadIdx.x & 16);
    int s = g_rowptr[g], e = g_rowptr[g + 1];
    float4 acc = make_float4(0.f, 0.f, 0.f, 0.f);

    int p = s;
    for (; p + 3 < e; p += 4) {
        int2 e0 = __ldg(g_edge + p);
        int2 e1 = __ldg(g_edge + p + 1);
        int2 e2 = __ldg(g_edge + p + 2);
        int2 e3 = __ldg(g_edge + p + 3);
        uint2 x0 = ekh2[(size_t)e0.x * 16 + l];
        uint2 x1 = ekh2[(size_t)e1.x * 16 + l];
        uint2 x2 = ekh2[(size_t)e2.x * 16 + l];
        uint2 x3 = ekh2[(size_t)e3.x * 16 + l];
        float v0 = __int_as_float(e0.y), v1 = __int_as_float(e1.y);
        float v2 = __int_as_float(e2.y), v3 = __int_as_float(e3.y);
        float2 a01, a23;
        a01 = __half22float2(*(__half2*)&x0.x); a23 = __half22float2(*(__half2*)&x0.y);
        acc.x = fmaf(v0, a01.x, acc.x); acc.y = fmaf(v0, a01.y, acc.y);
        acc.z = fmaf(v0, a23.x, acc.z); acc.w = fmaf(v0, a23.y, acc.w);
        a01 = __half22float2(*(__half2*)&x1.x); a23 = __half22float2(*(__half2*)&x1.y);
        acc.x = fmaf(v1, a01.x, acc.x); acc.y = fmaf(v1, a01.y, acc.y);
        acc.z = fmaf(v1, a23.x, acc.z); acc.w = fmaf(v1, a23.y, acc.w);
        a01 = __half22float2(*(__half2*)&x2.x); a23 = __half22float2(*(__half2*)&x2.y);
        acc.x = fmaf(v2, a01.x, acc.x); acc.y = fmaf(v2, a01.y, acc.y);
        acc.z = fmaf(v2, a23.x, acc.z); acc.w = fmaf(v2, a23.y, acc.w);
        a01 = __half22float2(*(__half2*)&x3.x); a23 = __half22float2(*(__half2*)&x3.y);
        acc.x = fmaf(v3, a01.x, acc.x); acc.y = fmaf(v3, a01.y, acc.y);
        acc.z = fmaf(v3, a23.x, acc.z); acc.w = fmaf(v3, a23.y, acc.w);
    }
    for (; p < e; p++) {
        int2 e0 = __ldg(g_edge + p);
        uint2 x0 = ekh2[(size_t)e0.x * 16 + l];
        float v0 = __int_as_float(e0.y);
        float2 a01 = __half22float2(*(__half2*)&x0.x);
        float2 a23 = __half22float2(*(__half2*)&x0.y);
        acc.x = fmaf(v0, a01.x, acc.x); acc.y = fmaf(v0, a01.y, acc.y);
        acc.z = fmaf(v0, a23.x, acc.z); acc.w = fmaf(v0, a23.y, acc.w);
    }
    *(float4*)(out + (size_t)g * DD + l * 4) = acc;
    float sg = acc.x * acc.x + acc.y * acc.y + acc.z * acc.z + acc.w * acc.w;
#pragma unroll
    for (int o = 8; o > 0; o >>= 1) sg += __shfl_xor_sync(m, sg, o);
    float inv = 1.f / fmaxf(sqrtf(sg), 1e-12f);
    __half2 h0 = __floats2half2_rn(acc.x * inv, acc.y * inv);
    __half2 h1 = __floats2half2_rn(acc.z * inv, acc.w * inv);
    uint2 u;
    u.x = *(unsigned*)&h0;
    u.y = *(unsigned*)&h1;
    ((uint2*)g_nrm)[(size_t)g * 32 + l * 2] = u;   // g-part of chunk l
}

// ---------------- intent body (tensor cores): softmax(ek@W)@W^T per 64-row tile ----------------
__device__ __forceinline__ void intent_body(int layer, const float* __restrict__ W,
                                            float* __restrict__ outIntl,
                                            int nodeBase, int nodeCount, int bx) {
    const __half* __restrict__ ekhIn = layer ? g_ekhB : g_ekhA;
    extern __shared__ char smc[];
    __half* Wh = (__half*)smc;                  // [64][136]
    __half* Ah = (__half*)(smc + 17408);        // [64][72]  (dead after GEMM1)
    __half* Ph = (__half*)(smc + 17408);        // [64][136] (overlays Ah)
    float*  Ps = (float*)(smc + 34816);         // [64][132]

    int tid = threadIdx.x;
    int warp = tid >> 5, lane = tid & 31;
    int rowTile = bx * TM;

    // load W (fp32 -> fp16) into Wh: 2048 float4s, 8 per thread
#pragma unroll
    for (int it = 0; it < 8; it++) {
        int i = tid + it * 256;                  // float4 index
        float4 v = __ldg((const float4*)W + i);
        int d  = i >> 5;
        int k4 = (i & 31) * 4;
        __half2 h0 = __floats2half2_rn(v.x, v.y);
        __half2 h1 = __floats2half2_rn(v.z, v.w);
        uint2 u; u.x = *(unsigned*)&h0; u.y = *(unsigned*)&h1;
        *(uint2*)(Wh + d * WH_LD + k4) = u;
    }
    // load A rows from fp16 ek: 64 rows x 128B; 4 threads per row, 32B each
    {
        int row = tid >> 2;
        int seg = tid & 3;
        uint4 z0 = make_uint4(0, 0, 0, 0), z1 = make_uint4(0, 0, 0, 0);
        int r = rowTile + row;
        if (r < nodeCount) {
            const uint4* src = (const uint4*)(ekhIn + (size_t)(nodeBase + r) * DD) + seg * 2;
            z0 = src[0]; z1 = src[1];
        }
        uint4* dst = (uint4*)(Ah + row * AH_LD + seg * 16);
        dst[0] = z0; dst[1] = z1;
    }
    __syncthreads();

    // GEMM1: logits[64][128] = A[64][64] @ W[64][128]   (warp grid 4M x 2N)
    {
        int wm = warp >> 1, wn = warp & 1;
        wmma::fragment<wmma::matrix_a, 16, 16, 16, __half, wmma::row_major> a[4];
#pragma unroll
        for (int kt = 0; kt < 4; kt++)
            wmma::load_matrix_sync(a[kt], Ah + wm * 16 * AH_LD + kt * 16, AH_LD);
#pragma unroll
        for (int nt = 0; nt < 4; nt++) {
            wmma::fragment<wmma::accumulator, 16, 16, 16, float> c;
            wmma::fill_fragment(c, 0.f);
#pragma unroll
            for (int kt = 0; kt < 4; kt++) {
                wmma::fragment<wmma::matrix_b, 16, 16, 16, __half, wmma::row_major> b;
                wmma::load_matrix_sync(b, Wh + kt * 16 * WH_LD + wn * 64 + nt * 16, WH_LD);
                wmma::mma_sync(c, a[kt], b, c);
            }
            wmma::store_matrix_sync(Ps + wm * 16 * PS_LD + wn * 64 + nt * 16, c, PS_LD,
                                    wmma::mem_row_major);
        }
    }
    __syncthreads();

    // row softmax on Ps (fp32), write probs fp16 to Ph
    for (int rr = warp; rr < TM; rr += 8) {
        float4 v = *(float4*)(Ps + rr * PS_LD + lane * 4);
        float mx = fmaxf(fmaxf(v.x, v.y), fmaxf(v.z, v.w));
#pragma unroll
        for (int o = 16; o > 0; o >>= 1) mx = fmaxf(mx, __shfl_xor_sync(0xffffffffu, mx, o));
        float e0 = __expf(v.x - mx), e1 = __expf(v.y - mx);
        float e2 = __expf(v.z - mx), e3 = __expf(v.w - mx);
        float sum = e0 + e1 + e2 + e3;
#pragma unroll
        for (int o = 16; o > 0; o >>= 1) sum += __shfl_xor_sync(0xffffffffu, sum, o);
        float inv = 1.0f / sum;
        __half2 h0 = __floats2half2_rn(e0 * inv, e1 * inv);
        __half2 h1 = __floats2half2_rn(e2 * inv, e3 * inv);
        uint2 u; u.x = *(unsigned*)&h0; u.y = *(unsigned*)&h1;
        *(uint2*)(Ph + rr * PH_LD + lane * 4) = u;
    }
    __syncthreads();

    // GEMM2: out[64][64] = P[64][128] @ W^T[128][64]  (B = Wh col-major; warp grid 4M x 2N)
    {
        int wm = warp >> 1, wn = warp & 1;
#pragma unroll
        for (int nt = 0; nt < 2; nt++) {
            wmma::fragment<wmma::accumulator, 16, 16, 16, float> c;
            wmma::fill_fragment(c, 0.f);
#pragma unroll
            for (int kt = 0; kt < 8; kt++) {
                wmma::fragment<wmma::matrix_a, 16, 16, 16, __half, wmma::row_major> a;
                wmma::fragment<wmma::matrix_b, 16, 16, 16, __half, wmma::col_major> b;
                wmma::load_matrix_sync(a, Ph + wm * 16 * PH_LD + kt * 16, PH_LD);
                wmma::load_matrix_sync(b, Wh + (wn * 32 + nt * 16) * WH_LD + kt * 16, WH_LD);
                wmma::mma_sync(c, a, b, c);
            }
            wmma::store_matrix_sync(Ps + wm * 16 * PS_LD + wn * 32 + nt * 16, c, PS_LD,
                                    wmma::mem_row_major);
        }
    }
    __syncthreads();

    // epilogue: store itl (fp32) + row norms + g_nrm i-part (fp16)
    for (int rr = warp; rr < TM; rr += 8) {
        float2 v = *(float2*)(Ps + rr * PS_LD + lane * 2);
        float ns = v.x * v.x + v.y * v.y;
#pragma unroll
        for (int o = 16; o > 0; o >>= 1) ns += __shfl_xor_sync(0xffffffffu, ns, o);
        float inv = 1.f / fmaxf(sqrtf(ns), 1e-12f);
        __half2 hv = __floats2half2_rn(v.x * inv, v.y * inv);
        unsigned lo = *(unsigned*)&hv;
        unsigned hi = __shfl_down_sync(0xffffffffu, lo, 1);
        int r = rowTile + rr;
        if (r < nodeCount) {
            *(float2*)(outIntl + (size_t)(nodeBase + r) * DD + lane * 2) = v;
            if ((lane & 1) == 0) {
                uint2 u; u.x = lo; u.y = hi;
                ((uint2*)g_nrm)[(size_t)(nodeBase + r) * 32 + (lane >> 1) * 2 + 1] = u;
            }
        }
    }
}

// ---------------- merged phase-1 kernel: interleaved intent/spmm dispatch ----------------
#define NB_IU ((UN + TM - 1) / TM)      // 1563
#define NB_II ((INC + TM - 1) / TM)     // 782
#define NB_I  (NB_IU + NB_II)           // 2345
#define NB_SP (NN * 16 / 256)           // 9375

__global__ void __launch_bounds__(256)
phase1_kernel(int layer, const float* __restrict__ Wu, const float* __restrict__ Wi,
              float* __restrict__ gnn, float* __restrict__ itl) {
    int bx = blockIdx.x;
    int k = bx >> 2;
    if ((bx & 3) == 0 && k < NB_I) {
        if (k < NB_IU) intent_body(layer, Wu, itl, 0, UN, k);
        else           intent_body(layer, Wi, itl, UN, INC, k - NB_IU);
    } else {
        int before = (bx >> 2) + 1;
        if (before > NB_I) before = NB_I;
        spmm_body(layer, gnn, bx - before);
    }
}

// ---------------- fused alpha + spmm2 + combine (16-lane group per node) ----------------
#define EDGE_DOT(na_, dg_, di_)                                               \
    {                                                                         \
        __half2 pg = __hfma2(hgy, *(__half2*)&(na_).y,                        \
                             __hmul2(hgx, *(__half2*)&(na_).x));              \
        __half2 pi = __hfma2(hiy, *(__half2*)&(na_).w,                        \
                             __hmul2(hix, *(__half2*)&(na_).z));              \
        float2 pgf = __half22float2(pg);                                      \
        float2 pif = __half22float2(pi);                                      \
        dg_ = pgf.x + pgf.y;                                                  \
        di_ = pif.x + pif.y;                                                  \
    }

#define EDGE_ACC(ea_, a_g, a_i)                                               \
    {                                                                         \
        float2 k01 = __half22float2(*(__half2*)&(ea_).x);                     \
        float2 k23 = __half22float2(*(__half2*)&(ea_).y);                     \
        AG.x = fmaf(a_g, k01.x, AG.x); AG.y = fmaf(a_g, k01.y, AG.y);         \
        AG.z = fmaf(a_g, k23.x, AG.z); AG.w = fmaf(a_g, k23.y, AG.w);         \
        AI.x = fmaf(a_i, k01.x, AI.x); AI.y = fmaf(a_i, k01.y, AI.y);         \
        AI.z = fmaf(a_i, k23.x, AI.z); AI.w = fmaf(a_i, k23.y, AI.w);         \
        rsg += a_g; rsi += a_i;                                               \
    }

__global__ void __launch_bounds__(256)
fused_alpha_kernel(int layer,
                   const float* __restrict__ gnn, const float* __restrict__ itl,
                   float* __restrict__ gaa, float* __restrict__ iaa,
                   float* __restrict__ finalOut) {
    const float*  __restrict__ ekIn   = layer ? g_ekB : g_ekA;
    const __half* __restrict__ ekhIn  = layer ? g_ekhB : g_ekhA;
    float*        __restrict__ ekOut  = layer ? g_ekA : g_ekB;
    __half*       __restrict__ ekhOut = layer ? g_ekhA : g_ekhB;
    int t0 = blockIdx.x * blockDim.x + threadIdx.x;
    int g = t0 >> 4;
    int l = threadIdx.x & 15;
    unsigned m = 0xFFFFu << (threadIdx.x & 16);
    size_t ro = (size_t)g * DD + l * 4;
    const uint4* __restrict__ nrm4 = (const uint4*)g_nrm;
    const uint2* __restrict__ ekh2 = (const uint2*)ekhIn;

    uint4 hn = nrm4[(size_t)g * 16 + l];
    __half2 hgx = *(__half2*)&hn.x, hgy = *(__half2*)&hn.y;
    __half2 hix = *(__half2*)&hn.z, hiy = *(__half2*)&hn.w;

    float4 AG = make_float4(0.f, 0.f, 0.f, 0.f);
    float4 AI = make_float4(0.f, 0.f, 0.f, 0.f);
    float rsg = 0.f, rsi = 0.f;

    int s = g_rowptr[g], e = g_rowptr[g + 1];
    int p = s;
    for (; p + 3 < e; p += 4) {
        int ta = __ldg(&g_edge[p].x);
        int tb = __ldg(&g_edge[p + 1].x);
        int tc = __ldg(&g_edge[p + 2].x);
        int td = __ldg(&g_edge[p + 3].x);
        uint4 na = nrm4[(size_t)ta * 16 + l];
        uint4 nb = nrm4[(size_t)tb * 16 + l];
        uint4 nc = nrm4[(size_t)tc * 16 + l];
        uint4 nd = nrm4[(size_t)td * 16 + l];
        uint2 ea = ekh2[(size_t)ta * 16 + l];
        uint2 eb = ekh2[(size_t)tb * 16 + l];
        uint2 ec = ekh2[(size_t)tc * 16 + l];
        uint2 ed = ekh2[(size_t)td * 16 + l];

        float dga, dia, dgb, dib, dgc, dic, dgd, did;
        EDGE_DOT(na, dga, dia);
        EDGE_DOT(nb, dgb, dib);
        EDGE_DOT(nc, dgc, dic);
        EDGE_DOT(nd, dgd, did);
#pragma unroll
        for (int o = 8; o > 0; o >>= 1) {
            dga += __shfl_xor_sync(m, dga, o);
            dia += __shfl_xor_sync(m, dia, o);
            dgb += __shfl_xor_sync(m, dgb, o);
            dib += __shfl_xor_sync(m, dib, o);
            dgc += __shfl_xor_sync(m, dgc, o);
            dic += __shfl_xor_sync(m, dic, o);
            dgd += __shfl_xor_sync(m, dgd, o);
            did += __shfl_xor_sync(m, did, o);
        }
        float aga = (dga + 1.f) * 0.5f, aia = (dia + 1.f) * 0.5f;
        float agb = (dgb + 1.f) * 0.5f, aib = (dib + 1.f) * 0.5f;
        float agc = (dgc + 1.f) * 0.5f, aic = (dic + 1.f) * 0.5f;
        float agd = (dgd + 1.f) * 0.5f, aid = (did + 1.f) * 0.5f;
        EDGE_ACC(ea, aga, aia);
        EDGE_ACC(eb, agb, aib);
        EDGE_ACC(ec, agc, aic);
        EDGE_ACC(ed, agd, aid);
    }
    for (; p < e; p++) {
        int ta = __ldg(&g_edge[p].x);
        uint4 na = nrm4[(size_t)ta * 16 + l];
        uint2 ea = ekh2[(size_t)ta * 16 + l];
        float dga, dia;
        EDGE_DOT(na, dga, dia);
#pragma unroll
        for (int o = 8; o > 0; o >>= 1) {
            dga += __shfl_xor_sync(m, dga, o);
            dia += __shfl_xor_sync(m, dia, o);
        }
        float aga = (dga + 1.f) * 0.5f, aia = (dia + 1.f) * 0.5f;
        EDGE_ACC(ea, aga, aia);
    }
    float dg_inv = rsg > 0.f ? 1.f / rsg : 0.f;
    float di_inv = rsi > 0.f ? 1.f / rsi : 0.f;
    float4 gv = make_float4(AG.x * dg_inv, AG.y * dg_inv, AG.z * dg_inv, AG.w * dg_inv);
    float4 iv = make_float4(AI.x * di_inv, AI.y * di_inv, AI.z * di_inv, AI.w * di_inv);
    *(float4*)(gaa + ro) = gv;
    *(float4*)(iaa + ro) = iv;

    float4 hg0 = *(const float4*)(gnn + ro);
    float4 hi0 = *(const float4*)(itl + ro);
    float4 ekv = *(const float4*)(ekIn + ro);
    float4 en;
    en.x = hg0.x + hi0.x + gv.x + iv.x + ekv.x;
    en.y = hg0.y + hi0.y + gv.y + iv.y + ekv.y;
    en.z = hg0.z + hi0.z + gv.z + iv.z + ekv.z;
    en.w = hg0.w + hi0.w + gv.w + iv.w + ekv.w;
    float4 ac = *(const float4*)(g_accum + ro);
    ac.x += en.x; ac.y += en.y; ac.z += en.z; ac.w += en.w;
    if (finalOut) {
        *(float4*)(finalOut + ro) = ac;      // last layer: ekOut/accum never read again
    } else {
        *(float4*)(ekOut + ro) = en;
        __half2 h0 = __floats2half2_rn(en.x, en.y);
        __half2 h1 = __floats2half2_rn(en.z, en.w);
        uint2 u; u.x = *(unsigned*)&h0; u.y = *(unsigned*)&h1;
        ((uint2*)ekhOut)[(size_t)g * 16 + l] = u;
        *(float4*)(g_accum + ro) = ac;
    }
}

// ---------------- launch ----------------
extern "C" void kernel_launch(void* const* d_in, const int* in_sizes, int n_in,
                              void* d_out, int out_size) {
    const float* user_emb = (const float*)d_in[0];
    const float* item_emb = (const float*)d_in[1];
    const float* Wu       = (const float*)d_in[2];
    const float* Wi       = (const float*)d_in[3];
    const float* adj      = (const float*)d_in[4];
    const int*   h        = (const int*)d_in[5];
    const int*   t        = (const int*)d_in[6];
    (void)in_sizes; (void)n_in; (void)out_size;

    float* out = (float*)d_out;
    const size_t ND = (size_t)NN * DD;
    float* out_ua  = out;                    // [N*D] = ua | ia
    float* out_gnn = out + ND;               // [L][N][D]
    float* out_int = out_gnn + (size_t)LL * ND;
    float* out_gaa = out_int + (size_t)LL * ND;
    float* out_iaa = out_gaa + (size_t)LL * ND;

    cudaFuncSetAttribute(phase1_kernel, cudaFuncAttributeMaxDynamicSharedMemorySize, IT_SMEM_BYTES);

    const int TPB = 256;
    const int SCAN_NB = (NN + 1023) / 1024;  // 147
    init_ek_kernel<<<(NN * DD / 4 + TPB - 1) / TPB, TPB>>>((const float4*)user_emb,
                                                           (const float4*)item_emb);
    hist_kernel<<<(EE / 4 + TPB - 1) / TPB, TPB>>>((const int4*)h);
    reduce_scan_kernel<<<SCAN_NB, 1024>>>();
    apply_scan_kernel<<<SCAN_NB, 1024>>>();
    scatter_kernel<<<(EE + TPB - 1) / TPB, TPB>>>(h, t, adj);

    const int NODE_BLOCKS = NN * 16 / TPB;   // 9375
    for (int l = 0; l < LL; l++) {
        float* gnn = out_gnn + (size_t)l * ND;
        float* itl = out_int + (size_t)l * ND;
        float* gaa = out_gaa + (size_t)l * ND;
        float* iaa = out_iaa + (size_t)l * ND;

        phase1_kernel<<<NB_I + NB_SP, TPB, IT_SMEM_BYTES>>>(l, Wu, Wi, gnn, itl);
        fused_alpha_kernel<<<NODE_BLOCKS, TPB>>>(l, gnn, itl, gaa, iaa,
                                                 (l == LL - 1) ? out_ua : nullptr);
    }
}

// round 11
// speedup vs baseline: 1.7832x; 1.0343x over previous
#include <cuda_runtime.h>
#include <cuda_fp16.h>
#include <mma.h>

using namespace nvcuda;

// ---------------- problem constants ----------------
#define UN  100000
#define INC 50000
#define NN  150000
#define DD  64
#define KK  128
#define EE  1250000
#define LL  2

typedef unsigned long long u64;

// ---------------- device scratch (static; no allocations) ----------------
__device__ __half g_ekhA[NN * DD];    // e0 (layer0 in), preserved through layer1
__device__ __half g_ekhB[NN * DD];    // e1 (layer1 in)
__device__ int   g_cnt[NN];
__device__ int   g_rowptr[NN + 1];
__device__ int   g_wp[NN];
__device__ int2  g_edge[EE];        // {tail, adj-as-int} in CSR order
// packed normalized vectors: per node 16 chunks of 16B; chunk c = {gnn̂[4c..4c+3], itl̂[4c..4c+3]} fp16
__device__ __half g_nrm[NN * 128];
__device__ int   g_bsum[160];
__device__ int   g_boff[160];
__device__ int   g_done;

// ---------------- init (ek fp16, cnt=0, done=0) ----------------
__global__ void init_ek_kernel(const float4* __restrict__ ue, const float4* __restrict__ ie) {
    int i = blockIdx.x * blockDim.x + threadIdx.x;
    const int TOT = NN * DD / 4, UD4 = UN * DD / 4;
    if (i == 0) g_done = 0;
    if (i < NN) g_cnt[i] = 0;
    if (i >= TOT) return;
    float4 v = (i < UD4) ? ue[i] : ie[i - UD4];
    __half2 h0 = __floats2half2_rn(v.x, v.y);
    __half2 h1 = __floats2half2_rn(v.z, v.w);
    uint2 u; u.x = *(unsigned*)&h0; u.y = *(unsigned*)&h1;
    ((uint2*)g_ekhA)[i] = u;
}

// ---------------- CSR build ----------------
__global__ void hist_kernel(const int4* __restrict__ h4) {
    int i = blockIdx.x * blockDim.x + threadIdx.x;
    if (i >= EE / 4) return;
    int4 v = __ldg(h4 + i);
    atomicAdd(&g_cnt[v.x], 1);
    atomicAdd(&g_cnt[v.y], 1);
    atomicAdd(&g_cnt[v.z], 1);
    atomicAdd(&g_cnt[v.w], 1);
}

__global__ void reduce_scan_kernel() {
    __shared__ int s[1024];
    __shared__ bool amLast;
    int tid = threadIdx.x;
    int idx = blockIdx.x * 1024 + tid;
    s[tid] = (idx < NN) ? g_cnt[idx] : 0;
    __syncthreads();
    for (int o = 512; o > 0; o >>= 1) {
        if (tid < o) s[tid] += s[tid + o];
        __syncthreads();
    }
    if (tid == 0) {
        g_bsum[blockIdx.x] = s[0];
        __threadfence();
        amLast = (atomicAdd(&g_done, 1) == gridDim.x - 1);
    }
    __syncthreads();
    if (amLast) {
        int nblk = gridDim.x;
        int v = (tid < nblk) ? g_bsum[tid] : 0;
        s[tid] = v;
        __syncthreads();
        for (int off = 1; off < 1024; off <<= 1) {
            int t = (tid >= off) ? s[tid - off] : 0;
            __syncthreads();
            s[tid] += t;
            __syncthreads();
        }
        if (tid < nblk) g_boff[tid] = s[tid] - v;   // exclusive
    }
}

__global__ void apply_scan_kernel() {
    __shared__ int s[1024];
    int tid = threadIdx.x;
    int idx = blockIdx.x * 1024 + tid;
    int v = (idx < NN) ? g_cnt[idx] : 0;
    s[tid] = v;
    __syncthreads();
    for (int off = 1; off < 1024; off <<= 1) {
        int t = (tid >= off) ? s[tid - off] : 0;
        __syncthreads();
        s[tid] += t;
        __syncthreads();
    }
    int excl = s[tid] - v + g_boff[blockIdx.x];
    if (idx < NN) { g_rowptr[idx] = excl; g_wp[idx] = excl; }
    if (blockIdx.x == 0 && tid == 0) g_rowptr[NN] = EE;
}

__global__ void scatter_kernel(const int* __restrict__ h, const int* __restrict__ t,
                               const float* __restrict__ adj) {
    int e = blockIdx.x * blockDim.x + threadIdx.x;
    if (e >= EE) return;
    int hn = h[e];
    int p  = atomicAdd(&g_wp[hn], 1);
    g_edge[p] = make_int2(t[e], __float_as_int(adj[e]));
}

// ---------------- smem layout for tensor-core intent (TM=64) ----------------
#define TM 64
#define WH_LD 136
#define AH_LD 72
#define PH_LD 136
#define PS_LD 132
#define IT_SMEM_BYTES (17408 + 17408 + 33792)   // 68608

// ---------------- spmm body (16-lane group per node); fp16 gathers; gnn + fp16 gnn̂ ----------------
__device__ __forceinline__ void spmm_body(int layer, float* __restrict__ out, int bx) {
    const __half* __restrict__ ekhIn = layer ? g_ekhB : g_ekhA;
    const uint2* __restrict__ ekh2 = (const uint2*)ekhIn;
    int t0 = bx * 256 + threadIdx.x;
    int g = t0 >> 4;
    int l = threadIdx.x & 15;
    unsigned m = 0xFFFFu << (threadIdx.x & 16);
    int s = g_rowptr[g], e = g_rowptr[g + 1];
    float4 acc = make_float4(0.f, 0.f, 0.f, 0.f);

    int p = s;
    for (; p + 3 < e; p += 4) {
        int2 e0 = __ldg(g_edge + p);
        int2 e1 = __ldg(g_edge + p + 1);
        int2 e2 = __ldg(g_edge + p + 2);
        int2 e3 = __ldg(g_edge + p + 3);
        uint2 x0 = ekh2[(size_t)e0.x * 16 + l];
        uint2 x1 = ekh2[(size_t)e1.x * 16 + l];
        uint2 x2 = ekh2[(size_t)e2.x * 16 + l];
        uint2 x3 = ekh2[(size_t)e3.x * 16 + l];
        float v0 = __int_as_float(e0.y), v1 = __int_as_float(e1.y);
        float v2 = __int_as_float(e2.y), v3 = __int_as_float(e3.y);
        float2 a01, a23;
        a01 = __half22float2(*(__half2*)&x0.x); a23 = __half22float2(*(__half2*)&x0.y);
        acc.x = fmaf(v0, a01.x, acc.x); acc.y = fmaf(v0, a01.y, acc.y);
        acc.z = fmaf(v0, a23.x, acc.z); acc.w = fmaf(v0, a23.y, acc.w);
        a01 = __half22float2(*(__half2*)&x1.x); a23 = __half22float2(*(__half2*)&x1.y);
        acc.x = fmaf(v1, a01.x, acc.x); acc.y = fmaf(v1, a01.y, acc.y);
        acc.z = fmaf(v1, a23.x, acc.z); acc.w = fmaf(v1, a23.y, acc.w);
        a01 = __half22float2(*(__half2*)&x2.x); a23 = __half22float2(*(__half2*)&x2.y);
        acc.x = fmaf(v2, a01.x, acc.x); acc.y = fmaf(v2, a01.y, acc.y);
        acc.z = fmaf(v2, a23.x, acc.z); acc.w = fmaf(v2, a23.y, acc.w);
        a01 = __half22float2(*(__half2*)&x3.x); a23 = __half22float2(*(__half2*)&x3.y);
        acc.x = fmaf(v3, a01.x, acc.x); acc.y = fmaf(v3, a01.y, acc.y);
        acc.z = fmaf(v3, a23.x, acc.z); acc.w = fmaf(v3, a23.y, acc.w);
    }
    for (; p < e; p++) {
        int2 e0 = __ldg(g_edge + p);
        uint2 x0 = ekh2[(size_t)e0.x * 16 + l];
        float v0 = __int_as_float(e0.y);
        float2 a01 = __half22float2(*(__half2*)&x0.x);
        float2 a23 = __half22float2(*(__half2*)&x0.y);
        acc.x = fmaf(v0, a01.x, acc.x); acc.y = fmaf(v0, a01.y, acc.y);
        acc.z = fmaf(v0, a23.x, acc.z); acc.w = fmaf(v0, a23.y, acc.w);
    }
    *(float4*)(out + (size_t)g * DD + l * 4) = acc;
    float sg = acc.x * acc.x + acc.y * acc.y + acc.z * acc.z + acc.w * acc.w;
#pragma unroll
    for (int o = 8; o > 0; o >>= 1) sg += __shfl_xor_sync(m, sg, o);
    float inv = 1.f / fmaxf(sqrtf(sg), 1e-12f);
    __half2 h0 = __floats2half2_rn(acc.x * inv, acc.y * inv);
    __half2 h1 = __floats2half2_rn(acc.z * inv, acc.w * inv);
    uint2 u;
    u.x = *(unsigned*)&h0;
    u.y = *(unsigned*)&h1;
    ((uint2*)g_nrm)[(size_t)g * 32 + l * 2] = u;   // g-part of chunk l
}

// ---------------- intent body (tensor cores): softmax(ek@W)@W^T per 64-row tile ----------------
__device__ __forceinline__ void intent_body(int layer, const float* __restrict__ W,
                                            float* __restrict__ outIntl,
                                            int nodeBase, int nodeCount, int bx) {
    const __half* __restrict__ ekhIn = layer ? g_ekhB : g_ekhA;
    extern __shared__ char smc[];
    __half* Wh = (__half*)smc;                  // [64][136]
    __half* Ah = (__half*)(smc + 17408);        // [64][72]  (dead after GEMM1)
    __half* Ph = (__half*)(smc + 17408);        // [64][136] (overlays Ah)
    float*  Ps = (float*)(smc + 34816);         // [64][132]

    int tid = threadIdx.x;
    int warp = tid >> 5, lane = tid & 31;
    int rowTile = bx * TM;

    // load W (fp32 -> fp16) into Wh
#pragma unroll
    for (int it = 0; it < 8; it++) {
        int i = tid + it * 256;                  // float4 index
        float4 v = __ldg((const float4*)W + i);
        int d  = i >> 5;
        int k4 = (i & 31) * 4;
        __half2 h0 = __floats2half2_rn(v.x, v.y);
        __half2 h1 = __floats2half2_rn(v.z, v.w);
        uint2 u; u.x = *(unsigned*)&h0; u.y = *(unsigned*)&h1;
        *(uint2*)(Wh + d * WH_LD + k4) = u;
    }
    // load A rows from fp16 ek
    {
        int row = tid >> 2;
        int seg = tid & 3;
        uint4 z0 = make_uint4(0, 0, 0, 0), z1 = make_uint4(0, 0, 0, 0);
        int r = rowTile + row;
        if (r < nodeCount) {
            const uint4* src = (const uint4*)(ekhIn + (size_t)(nodeBase + r) * DD) + seg * 2;
            z0 = src[0]; z1 = src[1];
        }
        uint4* dst = (uint4*)(Ah + row * AH_LD + seg * 16);
        dst[0] = z0; dst[1] = z1;
    }
    __syncthreads();

    // GEMM1: logits[64][128] = A[64][64] @ W[64][128]
    {
        int wm = warp >> 1, wn = warp & 1;
        wmma::fragment<wmma::matrix_a, 16, 16, 16, __half, wmma::row_major> a[4];
#pragma unroll
        for (int kt = 0; kt < 4; kt++)
            wmma::load_matrix_sync(a[kt], Ah + wm * 16 * AH_LD + kt * 16, AH_LD);
#pragma unroll
        for (int nt = 0; nt < 4; nt++) {
            wmma::fragment<wmma::accumulator, 16, 16, 16, float> c;
            wmma::fill_fragment(c, 0.f);
#pragma unroll
            for (int kt = 0; kt < 4; kt++) {
                wmma::fragment<wmma::matrix_b, 16, 16, 16, __half, wmma::row_major> b;
                wmma::load_matrix_sync(b, Wh + kt * 16 * WH_LD + wn * 64 + nt * 16, WH_LD);
                wmma::mma_sync(c, a[kt], b, c);
            }
            wmma::store_matrix_sync(Ps + wm * 16 * PS_LD + wn * 64 + nt * 16, c, PS_LD,
                                    wmma::mem_row_major);
        }
    }
    __syncthreads();

    // row softmax on Ps (fp32), write probs fp16 to Ph
    for (int rr = warp; rr < TM; rr += 8) {
        float4 v = *(float4*)(Ps + rr * PS_LD + lane * 4);
        float mx = fmaxf(fmaxf(v.x, v.y), fmaxf(v.z, v.w));
#pragma unroll
        for (int o = 16; o > 0; o >>= 1) mx = fmaxf(mx, __shfl_xor_sync(0xffffffffu, mx, o));
        float e0 = __expf(v.x - mx), e1 = __expf(v.y - mx);
        float e2 = __expf(v.z - mx), e3 = __expf(v.w - mx);
        float sum = e0 + e1 + e2 + e3;
#pragma unroll
        for (int o = 16; o > 0; o >>= 1) sum += __shfl_xor_sync(0xffffffffu, sum, o);
        float inv = 1.0f / sum;
        __half2 h0 = __floats2half2_rn(e0 * inv, e1 * inv);
        __half2 h1 = __floats2half2_rn(e2 * inv, e3 * inv);
        uint2 u; u.x = *(unsigned*)&h0; u.y = *(unsigned*)&h1;
        *(uint2*)(Ph + rr * PH_LD + lane * 4) = u;
    }
    __syncthreads();

    // GEMM2: out[64][64] = P[64][128] @ W^T[128][64]
    {
        int wm = warp >> 1, wn = warp & 1;
#pragma unroll
        for (int nt = 0; nt < 2; nt++) {
            wmma::fragment<wmma::accumulator, 16, 16, 16, float> c;
            wmma::fill_fragment(c, 0.f);
#pragma unroll
            for (int kt = 0; kt < 8; kt++) {
                wmma::fragment<wmma::matrix_a, 16, 16, 16, __half, wmma::row_major> a;
                wmma::fragment<wmma::matrix_b, 16, 16, 16, __half, wmma::col_major> b;
                wmma::load_matrix_sync(a, Ph + wm * 16 * PH_LD + kt * 16, PH_LD);
                wmma::load_matrix_sync(b, Wh + (wn * 32 + nt * 16) * WH_LD + kt * 16, WH_LD);
                wmma::mma_sync(c, a, b, c);
            }
            wmma::store_matrix_sync(Ps + wm * 16 * PS_LD + wn * 32 + nt * 16, c, PS_LD,
                                    wmma::mem_row_major);
        }
    }
    __syncthreads();

    // epilogue: store itl (fp32) + row norms + g_nrm i-part (fp16)
    for (int rr = warp; rr < TM; rr += 8) {
        float2 v = *(float2*)(Ps + rr * PS_LD + lane * 2);
        float ns = v.x * v.x + v.y * v.y;
#pragma unroll
        for (int o = 16; o > 0; o >>= 1) ns += __shfl_xor_sync(0xffffffffu, ns, o);
        float inv = 1.f / fmaxf(sqrtf(ns), 1e-12f);
        __half2 hv = __floats2half2_rn(v.x * inv, v.y * inv);
        unsigned lo = *(unsigned*)&hv;
        unsigned hi = __shfl_down_sync(0xffffffffu, lo, 1);
        int r = rowTile + rr;
        if (r < nodeCount) {
            *(float2*)(outIntl + (size_t)(nodeBase + r) * DD + lane * 2) = v;
            if ((lane & 1) == 0) {
                uint2 u; u.x = lo; u.y = hi;
                ((uint2*)g_nrm)[(size_t)(nodeBase + r) * 32 + (lane >> 1) * 2 + 1] = u;
            }
        }
    }
}

// ---------------- merged phase-1 kernel: interleaved intent/spmm dispatch ----------------
#define NB_IU ((UN + TM - 1) / TM)      // 1563
#define NB_II ((INC + TM - 1) / TM)     // 782
#define NB_I  (NB_IU + NB_II)           // 2345
#define NB_SP (NN * 16 / 256)           // 9375

__global__ void __launch_bounds__(256)
phase1_kernel(int layer, const float* __restrict__ Wu, const float* __restrict__ Wi,
              float* __restrict__ gnn, float* __restrict__ itl) {
    int bx = blockIdx.x;
    int k = bx >> 2;
    if ((bx & 3) == 0 && k < NB_I) {
        if (k < NB_IU) intent_body(layer, Wu, itl, 0, UN, k);
        else           intent_body(layer, Wi, itl, UN, INC, k - NB_IU);
    } else {
        int before = (bx >> 2) + 1;
        if (before > NB_I) before = NB_I;
        spmm_body(layer, gnn, bx - before);
    }
}

// ---------------- fused alpha + spmm2 + combine (16-lane group per node) ----------------
#define EDGE_DOT(na_, dg_, di_)                                               \
    {                                                                         \
        __half2 pg = __hfma2(hgy, *(__half2*)&(na_).y,                        \
                             __hmul2(hgx, *(__half2*)&(na_).x));              \
        __half2 pi = __hfma2(hiy, *(__half2*)&(na_).w,                        \
                             __hmul2(hix, *(__half2*)&(na_).z));              \
        float2 pgf = __half22float2(pg);                                      \
        float2 pif = __half22float2(pi);                                      \
        dg_ = pgf.x + pgf.y;                                                  \
        di_ = pif.x + pif.y;                                                  \
    }

#define EDGE_ACC(ea_, a_g, a_i)                                               \
    {                                                                         \
        float2 k01 = __half22float2(*(__half2*)&(ea_).x);                     \
        float2 k23 = __half22float2(*(__half2*)&(ea_).y);                     \
        AG.x = fmaf(a_g, k01.x, AG.x); AG.y = fmaf(a_g, k01.y, AG.y);         \
        AG.z = fmaf(a_g, k23.x, AG.z); AG.w = fmaf(a_g, k23.y, AG.w);         \
        AI.x = fmaf(a_i, k01.x, AI.x); AI.y = fmaf(a_i, k01.y, AI.y);         \
        AI.z = fmaf(a_i, k23.x, AI.z); AI.w = fmaf(a_i, k23.y, AI.w);         \
        rsg += a_g; rsi += a_i;                                               \
    }

__global__ void __launch_bounds__(256)
fused_alpha_kernel(int layer,
                   const float* __restrict__ gnn, const float* __restrict__ itl,
                   float* __restrict__ gaa, float* __restrict__ iaa,
                   float* __restrict__ finalOut) {
    const __half* __restrict__ ekhIn  = layer ? g_ekhB : g_ekhA;
    __half*       __restrict__ ekhOut = layer ? g_ekhA : g_ekhB;
    int t0 = blockIdx.x * blockDim.x + threadIdx.x;
    int g = t0 >> 4;
    int l = threadIdx.x & 15;
    unsigned m = 0xFFFFu << (threadIdx.x & 16);
    size_t ro = (size_t)g * DD + l * 4;
    const uint4* __restrict__ nrm4 = (const uint4*)g_nrm;
    const uint2* __restrict__ ekh2 = (const uint2*)ekhIn;

    uint4 hn = nrm4[(size_t)g * 16 + l];
    __half2 hgx = *(__half2*)&hn.x, hgy = *(__half2*)&hn.y;
    __half2 hix = *(__half2*)&hn.z, hiy = *(__half2*)&hn.w;

    float4 AG = make_float4(0.f, 0.f, 0.f, 0.f);
    float4 AI = make_float4(0.f, 0.f, 0.f, 0.f);
    float rsg = 0.f, rsi = 0.f;

    int s = g_rowptr[g], e = g_rowptr[g + 1];
    int p = s;
    for (; p + 3 < e; p += 4) {
        int ta = __ldg(&g_edge[p].x);
        int tb = __ldg(&g_edge[p + 1].x);
        int tc = __ldg(&g_edge[p + 2].x);
        int td = __ldg(&g_edge[p + 3].x);
        uint4 na = nrm4[(size_t)ta * 16 + l];
        uint4 nb = nrm4[(size_t)tb * 16 + l];
        uint4 nc = nrm4[(size_t)tc * 16 + l];
        uint4 nd = nrm4[(size_t)td * 16 + l];
        uint2 ea = ekh2[(size_t)ta * 16 + l];
        uint2 eb = ekh2[(size_t)tb * 16 + l];
        uint2 ec = ekh2[(size_t)tc * 16 + l];
        uint2 ed = ekh2[(size_t)td * 16 + l];

        float dga, dia, dgb, dib, dgc, dic, dgd, did;
        EDGE_DOT(na, dga, dia);
        EDGE_DOT(nb, dgb, dib);
        EDGE_DOT(nc, dgc, dic);
        EDGE_DOT(nd, dgd, did);
#pragma unroll
        for (int o = 8; o > 0; o >>= 1) {
            dga += __shfl_xor_sync(m, dga, o);
            dia += __shfl_xor_sync(m, dia, o);
            dgb += __shfl_xor_sync(m, dgb, o);
            dib += __shfl_xor_sync(m, dib, o);
            dgc += __shfl_xor_sync(m, dgc, o);
            dic += __shfl_xor_sync(m, dic, o);
            dgd += __shfl_xor_sync(m, dgd, o);
            did += __shfl_xor_sync(m, did, o);
        }
        float aga = (dga + 1.f) * 0.5f, aia = (dia + 1.f) * 0.5f;
        float agb = (dgb + 1.f) * 0.5f, aib = (dib + 1.f) * 0.5f;
        float agc = (dgc + 1.f) * 0.5f, aic = (dic + 1.f) * 0.5f;
        float agd = (dgd + 1.f) * 0.5f, aid = (did + 1.f) * 0.5f;
        EDGE_ACC(ea, aga, aia);
        EDGE_ACC(eb, agb, aib);
        EDGE_ACC(ec, agc, aic);
        EDGE_ACC(ed, agd, aid);
    }
    for (; p < e; p++) {
        int ta = __ldg(&g_edge[p].x);
        uint4 na = nrm4[(size_t)ta * 16 + l];
        uint2 ea = ekh2[(size_t)ta * 16 + l];
        float dga, dia;
        EDGE_DOT(na, dga, dia);
#pragma unroll
        for (int o = 8; o > 0; o >>= 1) {
            dga += __shfl_xor_sync(m, dga, o);
            dia += __shfl_xor_sync(m, dia, o);
        }
        float aga = (dga + 1.f) * 0.5f, aia = (dia + 1.f) * 0.5f;
        EDGE_ACC(ea, aga, aia);
    }
    float dg_inv = rsg > 0.f ? 1.f / rsg : 0.f;
    float di_inv = rsi > 0.f ? 1.f / rsi : 0.f;
    float4 gv = make_float4(AG.x * dg_inv, AG.y * dg_inv, AG.z * dg_inv, AG.w * dg_inv);
    float4 iv = make_float4(AI.x * di_inv, AI.y * di_inv, AI.z * di_inv, AI.w * di_inv);
    *(float4*)(gaa + ro) = gv;
    *(float4*)(iaa + ro) = iv;

    // combine: e_{l+1} = gnn + intl + gaa + iaa + ek (ek from fp16)
    float4 hg0 = *(const float4*)(gnn + ro);
    float4 hi0 = *(const float4*)(itl + ro);
    uint2 ekc = ekh2[(size_t)g * 16 + l];
    float2 ek01 = __half22float2(*(__half2*)&ekc.x);
    float2 ek23 = __half22float2(*(__half2*)&ekc.y);
    float4 en;
    en.x = hg0.x + hi0.x + gv.x + iv.x + ek01.x;
    en.y = hg0.y + hi0.y + gv.y + iv.y + ek01.y;
    en.z = hg0.z + hi0.z + gv.z + iv.z + ek23.x;
    en.w = hg0.w + hi0.w + gv.w + iv.w + ek23.y;
    if (finalOut) {
        // final = e0 + e1 + e2 ; e0 lives in g_ekhA, e1 = ekhIn (=g_ekhB)
        uint2 e0c = ((const uint2*)g_ekhA)[(size_t)g * 16 + l];
        float2 z01 = __half22float2(*(__half2*)&e0c.x);
        float2 z23 = __half22float2(*(__half2*)&e0c.y);
        float4 ac;
        ac.x = z01.x + ek01.x + en.x;
        ac.y = z01.y + ek01.y + en.y;
        ac.z = z23.x + ek23.x + en.z;
        ac.w = z23.y + ek23.y + en.w;
        *(float4*)(finalOut + ro) = ac;
    } else {
        __half2 h0 = __floats2half2_rn(en.x, en.y);
        __half2 h1 = __floats2half2_rn(en.z, en.w);
        uint2 u; u.x = *(unsigned*)&h0; u.y = *(unsigned*)&h1;
        ((uint2*)ekhOut)[(size_t)g * 16 + l] = u;
    }
}

// ---------------- launch ----------------
extern "C" void kernel_launch(void* const* d_in, const int* in_sizes, int n_in,
                              void* d_out, int out_size) {
    const float* user_emb = (const float*)d_in[0];
    const float* item_emb = (const float*)d_in[1];
    const float* Wu       = (const float*)d_in[2];
    const float* Wi       = (const float*)d_in[3];
    const float* adj      = (const float*)d_in[4];
    const int*   h        = (const int*)d_in[5];
    const int*   t        = (const int*)d_in[6];
    (void)in_sizes; (void)n_in; (void)out_size;

    float* out = (float*)d_out;
    const size_t ND = (size_t)NN * DD;
    float* out_ua  = out;                    // [N*D] = ua | ia
    float* out_gnn = out + ND;               // [L][N][D]
    float* out_int = out_gnn + (size_t)LL * ND;
    float* out_gaa = out_int + (size_t)LL * ND;
    float* out_iaa = out_gaa + (size_t)LL * ND;

    cudaFuncSetAttribute(phase1_kernel, cudaFuncAttributeMaxDynamicSharedMemorySize, IT_SMEM_BYTES);

    const int TPB = 256;
    const int SCAN_NB = (NN + 1023) / 1024;  // 147
    init_ek_kernel<<<(NN * DD / 4 + TPB - 1) / TPB, TPB>>>((const float4*)user_emb,
                                                           (const float4*)item_emb);
    hist_kernel<<<(EE / 4 + TPB - 1) / TPB, TPB>>>((const int4*)h);
    reduce_scan_kernel<<<SCAN_NB, 1024>>>();
    apply_scan_kernel<<<SCAN_NB, 1024>>>();
    scatter_kernel<<<(EE + TPB - 1) / TPB, TPB>>>(h, t, adj);

    const int NODE_BLOCKS = NN * 16 / TPB;   // 9375
    for (int l = 0; l < LL; l++) {
        float* gnn = out_gnn + (size_t)l * ND;
        float* itl = out_int + (size_t)l * ND;
        float* gaa = out_gaa + (size_t)l * ND;
        float* iaa = out_iaa + (size_t)l * ND;

        phase1_kernel<<<NB_I + NB_SP, TPB, IT_SMEM_BYTES>>>(l, Wu, Wi, gnn, itl);
        fused_alpha_kernel<<<NODE_BLOCKS, TPB>>>(l, gnn, itl, gaa, iaa,
                                                 (l == LL - 1) ? out_ua : nullptr);
    }
}

// round 12
// speedup vs baseline: 1.8294x; 1.0259x over previous
#include <cuda_runtime.h>
#include <cuda_fp16.h>
#include <mma.h>

using namespace nvcuda;

// ---------------- problem constants ----------------
#define UN  100000
#define INC 50000
#define NN  150000
#define DD  64
#define KK  128
#define EE  1250000
#define LL  2

typedef unsigned long long u64;

// ---------------- device scratch (static; no allocations) ----------------
__device__ __half g_ekhA[NN * DD];    // e0 (layer0 in), preserved through layer1
__device__ __half g_ekhB[NN * DD];    // e1 (layer1 in)
__device__ int   g_cnt[NN];
__device__ int   g_rowptr[NN + 1];
__device__ int   g_wp[NN];
__device__ int2  g_edge[EE];        // {tail, adj-as-int} in CSR order
// packed normalized vectors: per node 16 chunks of 16B; chunk c = {gnn̂[4c..4c+3], itl̂[4c..4c+3]} fp16
__device__ __half g_nrm[NN * 128];
__device__ int   g_bsum[160];
__device__ int   g_boff[160];
__device__ int   g_done;

// ---------------- init (ek fp16, cnt=0, done=0) ----------------
__global__ void init_ek_kernel(const float4* __restrict__ ue, const float4* __restrict__ ie) {
    int i = blockIdx.x * blockDim.x + threadIdx.x;
    const int TOT = NN * DD / 4, UD4 = UN * DD / 4;
    if (i == 0) g_done = 0;
    if (i < NN) g_cnt[i] = 0;
    if (i >= TOT) return;
    float4 v = (i < UD4) ? ue[i] : ie[i - UD4];
    __half2 h0 = __floats2half2_rn(v.x, v.y);
    __half2 h1 = __floats2half2_rn(v.z, v.w);
    uint2 u; u.x = *(unsigned*)&h0; u.y = *(unsigned*)&h1;
    ((uint2*)g_ekhA)[i] = u;
}

// ---------------- CSR build ----------------
__global__ void hist_kernel(const int4* __restrict__ h4) {
    int i = blockIdx.x * blockDim.x + threadIdx.x;
    if (i >= EE / 4) return;
    int4 v = __ldg(h4 + i);
    atomicAdd(&g_cnt[v.x], 1);
    atomicAdd(&g_cnt[v.y], 1);
    atomicAdd(&g_cnt[v.z], 1);
    atomicAdd(&g_cnt[v.w], 1);
}

__global__ void reduce_scan_kernel() {
    __shared__ int s[1024];
    __shared__ bool amLast;
    int tid = threadIdx.x;
    int idx = blockIdx.x * 1024 + tid;
    s[tid] = (idx < NN) ? g_cnt[idx] : 0;
    __syncthreads();
    for (int o = 512; o > 0; o >>= 1) {
        if (tid < o) s[tid] += s[tid + o];
        __syncthreads();
    }
    if (tid == 0) {
        g_bsum[blockIdx.x] = s[0];
        __threadfence();
        amLast = (atomicAdd(&g_done, 1) == gridDim.x - 1);
    }
    __syncthreads();
    if (amLast) {
        int nblk = gridDim.x;
        int v = (tid < nblk) ? g_bsum[tid] : 0;
        s[tid] = v;
        __syncthreads();
        for (int off = 1; off < 1024; off <<= 1) {
            int t = (tid >= off) ? s[tid - off] : 0;
            __syncthreads();
            s[tid] += t;
            __syncthreads();
        }
        if (tid < nblk) g_boff[tid] = s[tid] - v;   // exclusive
    }
}

__global__ void apply_scan_kernel() {
    __shared__ int s[1024];
    int tid = threadIdx.x;
    int idx = blockIdx.x * 1024 + tid;
    int v = (idx < NN) ? g_cnt[idx] : 0;
    s[tid] = v;
    __syncthreads();
    for (int off = 1; off < 1024; off <<= 1) {
        int t = (tid >= off) ? s[tid - off] : 0;
        __syncthreads();
        s[tid] += t;
        __syncthreads();
    }
    int excl = s[tid] - v + g_boff[blockIdx.x];
    if (idx < NN) { g_rowptr[idx] = excl; g_wp[idx] = excl; }
    if (blockIdx.x == 0 && tid == 0) g_rowptr[NN] = EE;
}

__global__ void scatter_kernel(const int4* __restrict__ h4, const int4* __restrict__ t4,
                               const float4* __restrict__ adj4) {
    int i = blockIdx.x * blockDim.x + threadIdx.x;
    if (i >= EE / 4) return;
    int4  hv = __ldg(h4 + i);
    int4  tv = __ldg(t4 + i);
    float4 av = __ldg(adj4 + i);
    int p0 = atomicAdd(&g_wp[hv.x], 1);
    int p1 = atomicAdd(&g_wp[hv.y], 1);
    int p2 = atomicAdd(&g_wp[hv.z], 1);
    int p3 = atomicAdd(&g_wp[hv.w], 1);
    g_edge[p0] = make_int2(tv.x, __float_as_int(av.x));
    g_edge[p1] = make_int2(tv.y, __float_as_int(av.y));
    g_edge[p2] = make_int2(tv.z, __float_as_int(av.z));
    g_edge[p3] = make_int2(tv.w, __float_as_int(av.w));
}

// ---------------- smem layout for tensor-core intent (TM=64) ----------------
#define TM 64
#define WH_LD 136
#define AH_LD 72
#define PH_LD 136
#define PS_LD 132
#define IT_SMEM_BYTES (17408 + 17408 + 33792)   // 68608

// ---------------- spmm body (16-lane group per node); fp16 gathers; gnn + fp16 gnn̂ ----------------
__device__ __forceinline__ void spmm_body(int layer, float* __restrict__ out, int bx) {
    const __half* __restrict__ ekhIn = layer ? g_ekhB : g_ekhA;
    const uint2* __restrict__ ekh2 = (const uint2*)ekhIn;
    int t0 = bx * 256 + threadIdx.x;
    int g = t0 >> 4;
    int l = threadIdx.x & 15;
    unsigned m = 0xFFFFu << (threadIdx.x & 16);
    int s = g_rowptr[g], e = g_rowptr[g + 1];
    float4 acc = make_float4(0.f, 0.f, 0.f, 0.f);

    int p = s;
    for (; p + 3 < e; p += 4) {
        int2 e0 = __ldg(g_edge + p);
        int2 e1 = __ldg(g_edge + p + 1);
        int2 e2 = __ldg(g_edge + p + 2);
        int2 e3 = __ldg(g_edge + p + 3);
        uint2 x0 = ekh2[(size_t)e0.x * 16 + l];
        uint2 x1 = ekh2[(size_t)e1.x * 16 + l];
        uint2 x2 = ekh2[(size_t)e2.x * 16 + l];
        uint2 x3 = ekh2[(size_t)e3.x * 16 + l];
        float v0 = __int_as_float(e0.y), v1 = __int_as_float(e1.y);
        float v2 = __int_as_float(e2.y), v3 = __int_as_float(e3.y);
        float2 a01, a23;
        a01 = __half22float2(*(__half2*)&x0.x); a23 = __half22float2(*(__half2*)&x0.y);
        acc.x = fmaf(v0, a01.x, acc.x); acc.y = fmaf(v0, a01.y, acc.y);
        acc.z = fmaf(v0, a23.x, acc.z); acc.w = fmaf(v0, a23.y, acc.w);
        a01 = __half22float2(*(__half2*)&x1.x); a23 = __half22float2(*(__half2*)&x1.y);
        acc.x = fmaf(v1, a01.x, acc.x); acc.y = fmaf(v1, a01.y, acc.y);
        acc.z = fmaf(v1, a23.x, acc.z); acc.w = fmaf(v1, a23.y, acc.w);
        a01 = __half22float2(*(__half2*)&x2.x); a23 = __half22float2(*(__half2*)&x2.y);
        acc.x = fmaf(v2, a01.x, acc.x); acc.y = fmaf(v2, a01.y, acc.y);
        acc.z = fmaf(v2, a23.x, acc.z); acc.w = fmaf(v2, a23.y, acc.w);
        a01 = __half22float2(*(__half2*)&x3.x); a23 = __half22float2(*(__half2*)&x3.y);
        acc.x = fmaf(v3, a01.x, acc.x); acc.y = fmaf(v3, a01.y, acc.y);
        acc.z = fmaf(v3, a23.x, acc.z); acc.w = fmaf(v3, a23.y, acc.w);
    }
    for (; p < e; p++) {
        int2 e0 = __ldg(g_edge + p);
        uint2 x0 = ekh2[(size_t)e0.x * 16 + l];
        float v0 = __int_as_float(e0.y);
        float2 a01 = __half22float2(*(__half2*)&x0.x);
        float2 a23 = __half22float2(*(__half2*)&x0.y);
        acc.x = fmaf(v0, a01.x, acc.x); acc.y = fmaf(v0, a01.y, acc.y);
        acc.z = fmaf(v0, a23.x, acc.z); acc.w = fmaf(v0, a23.y, acc.w);
    }
    *(float4*)(out + (size_t)g * DD + l * 4) = acc;
    float sg = acc.x * acc.x + acc.y * acc.y + acc.z * acc.z + acc.w * acc.w;
#pragma unroll
    for (int o = 8; o > 0; o >>= 1) sg += __shfl_xor_sync(m, sg, o);
    float inv = 1.f / fmaxf(sqrtf(sg), 1e-12f);
    __half2 h0 = __floats2half2_rn(acc.x * inv, acc.y * inv);
    __half2 h1 = __floats2half2_rn(acc.z * inv, acc.w * inv);
    uint2 u;
    u.x = *(unsigned*)&h0;
    u.y = *(unsigned*)&h1;
    ((uint2*)g_nrm)[(size_t)g * 32 + l * 2] = u;   // g-part of chunk l
}

// ---------------- intent body (tensor cores): softmax(ek@W)@W^T per 64-row tile ----------------
__device__ __forceinline__ void intent_body(int layer, const float* __restrict__ W,
                                            float* __restrict__ outIntl,
                                            int nodeBase, int nodeCount, int bx) {
    const __half* __restrict__ ekhIn = layer ? g_ekhB : g_ekhA;
    extern __shared__ char smc[];
    __half* Wh = (__half*)smc;                  // [64][136]
    __half* Ah = (__half*)(smc + 17408);        // [64][72]  (dead after GEMM1)
    __half* Ph = (__half*)(smc + 17408);        // [64][136] (overlays Ah)
    float*  Ps = (float*)(smc + 34816);         // [64][132]

    int tid = threadIdx.x;
    int warp = tid >> 5, lane = tid & 31;
    int rowTile = bx * TM;

    // load W (fp32 -> fp16) into Wh
#pragma unroll
    for (int it = 0; it < 8; it++) {
        int i = tid + it * 256;                  // float4 index
        float4 v = __ldg((const float4*)W + i);
        int d  = i >> 5;
        int k4 = (i & 31) * 4;
        __half2 h0 = __floats2half2_rn(v.x, v.y);
        __half2 h1 = __floats2half2_rn(v.z, v.w);
        uint2 u; u.x = *(unsigned*)&h0; u.y = *(unsigned*)&h1;
        *(uint2*)(Wh + d * WH_LD + k4) = u;
    }
    // load A rows from fp16 ek
    {
        int row = tid >> 2;
        int seg = tid & 3;
        uint4 z0 = make_uint4(0, 0, 0, 0), z1 = make_uint4(0, 0, 0, 0);
        int r = rowTile + row;
        if (r < nodeCount) {
            const uint4* src = (const uint4*)(ekhIn + (size_t)(nodeBase + r) * DD) + seg * 2;
            z0 = src[0]; z1 = src[1];
        }
        uint4* dst = (uint4*)(Ah + row * AH_LD + seg * 16);
        dst[0] = z0; dst[1] = z1;
    }
    __syncthreads();

    // GEMM1: logits[64][128] = A[64][64] @ W[64][128]
    {
        int wm = warp >> 1, wn = warp & 1;
        wmma::fragment<wmma::matrix_a, 16, 16, 16, __half, wmma::row_major> a[4];
#pragma unroll
        for (int kt = 0; kt < 4; kt++)
            wmma::load_matrix_sync(a[kt], Ah + wm * 16 * AH_LD + kt * 16, AH_LD);
#pragma unroll
        for (int nt = 0; nt < 4; nt++) {
            wmma::fragment<wmma::accumulator, 16, 16, 16, float> c;
            wmma::fill_fragment(c, 0.f);
#pragma unroll
            for (int kt = 0; kt < 4; kt++) {
                wmma::fragment<wmma::matrix_b, 16, 16, 16, __half, wmma::row_major> b;
                wmma::load_matrix_sync(b, Wh + kt * 16 * WH_LD + wn * 64 + nt * 16, WH_LD);
                wmma::mma_sync(c, a[kt], b, c);
            }
            wmma::store_matrix_sync(Ps + wm * 16 * PS_LD + wn * 64 + nt * 16, c, PS_LD,
                                    wmma::mem_row_major);
        }
    }
    __syncthreads();

    // row softmax on Ps (fp32), write probs fp16 to Ph
    for (int rr = warp; rr < TM; rr += 8) {
        float4 v = *(float4*)(Ps + rr * PS_LD + lane * 4);
        float mx = fmaxf(fmaxf(v.x, v.y), fmaxf(v.z, v.w));
#pragma unroll
        for (int o = 16; o > 0; o >>= 1) mx = fmaxf(mx, __shfl_xor_sync(0xffffffffu, mx, o));
        float e0 = __expf(v.x - mx), e1 = __expf(v.y - mx);
        float e2 = __expf(v.z - mx), e3 = __expf(v.w - mx);
        float sum = e0 + e1 + e2 + e3;
#pragma unroll
        for (int o = 16; o > 0; o >>= 1) sum += __shfl_xor_sync(0xffffffffu, sum, o);
        float inv = 1.0f / sum;
        __half2 h0 = __floats2half2_rn(e0 * inv, e1 * inv);
        __half2 h1 = __floats2half2_rn(e2 * inv, e3 * inv);
        uint2 u; u.x = *(unsigned*)&h0; u.y = *(unsigned*)&h1;
        *(uint2*)(Ph + rr * PH_LD + lane * 4) = u;
    }
    __syncthreads();

    // GEMM2: out[64][64] = P[64][128] @ W^T[128][64]
    {
        int wm = warp >> 1, wn = warp & 1;
#pragma unroll
        for (int nt = 0; nt < 2; nt++) {
            wmma::fragment<wmma::accumulator, 16, 16, 16, float> c;
            wmma::fill_fragment(c, 0.f);
#pragma unroll
            for (int kt = 0; kt < 8; kt++) {
                wmma::fragment<wmma::matrix_a, 16, 16, 16, __half, wmma::row_major> a;
                wmma::fragment<wmma::matrix_b, 16, 16, 16, __half, wmma::col_major> b;
                wmma::load_matrix_sync(a, Ph + wm * 16 * PH_LD + kt * 16, PH_LD);
                wmma::load_matrix_sync(b, Wh + (wn * 32 + nt * 16) * WH_LD + kt * 16, WH_LD);
                wmma::mma_sync(c, a, b, c);
            }
            wmma::store_matrix_sync(Ps + wm * 16 * PS_LD + wn * 32 + nt * 16, c, PS_LD,
                                    wmma::mem_row_major);
        }
    }
    __syncthreads();

    // epilogue: store itl (fp32) + row norms + g_nrm i-part (fp16)
    for (int rr = warp; rr < TM; rr += 8) {
        float2 v = *(float2*)(Ps + rr * PS_LD + lane * 2);
        float ns = v.x * v.x + v.y * v.y;
#pragma unroll
        for (int o = 16; o > 0; o >>= 1) ns += __shfl_xor_sync(0xffffffffu, ns, o);
        float inv = 1.f / fmaxf(sqrtf(ns), 1e-12f);
        __half2 hv = __floats2half2_rn(v.x * inv, v.y * inv);
        unsigned lo = *(unsigned*)&hv;
        unsigned hi = __shfl_down_sync(0xffffffffu, lo, 1);
        int r = rowTile + rr;
        if (r < nodeCount) {
            *(float2*)(outIntl + (size_t)(nodeBase + r) * DD + lane * 2) = v;
            if ((lane & 1) == 0) {
                uint2 u; u.x = lo; u.y = hi;
                ((uint2*)g_nrm)[(size_t)(nodeBase + r) * 32 + (lane >> 1) * 2 + 1] = u;
            }
        }
    }
}

// ---------------- merged phase-1 kernel: interleaved intent/spmm dispatch ----------------
#define NB_IU ((UN + TM - 1) / TM)      // 1563
#define NB_II ((INC + TM - 1) / TM)     // 782
#define NB_I  (NB_IU + NB_II)           // 2345
#define NB_SP (NN * 16 / 256)           // 9375

__global__ void __launch_bounds__(256)
phase1_kernel(int layer, const float* __restrict__ Wu, const float* __restrict__ Wi,
              float* __restrict__ gnn, float* __restrict__ itl) {
    int bx = blockIdx.x;
    int k = bx >> 2;
    if ((bx & 3) == 0 && k < NB_I) {
        if (k < NB_IU) intent_body(layer, Wu, itl, 0, UN, k);
        else           intent_body(layer, Wi, itl, UN, INC, k - NB_IU);
    } else {
        int before = (bx >> 2) + 1;
        if (before > NB_I) before = NB_I;
        spmm_body(layer, gnn, bx - before);
    }
}

// ---------------- fused alpha + spmm2 + combine (16-lane group per node) ----------------
// per-edge alpha via half2 dots; packed (dg, di) half2 butterfly reduction
#define EDGE_DOT_P(na_, dd_)                                                  \
    {                                                                         \
        __half2 pg = __hfma2(hgy, *(__half2*)&(na_).y,                        \
                             __hmul2(hgx, *(__half2*)&(na_).x));              \
        __half2 pi = __hfma2(hiy, *(__half2*)&(na_).w,                        \
                             __hmul2(hix, *(__half2*)&(na_).z));              \
        dd_ = __halves2half2(__hadd(__low2half(pg), __high2half(pg)),         \
                             __hadd(__low2half(pi), __high2half(pi)));        \
    }

#define H2SHFL(dd_, o_)                                                       \
    {                                                                         \
        unsigned _w = *(unsigned*)&(dd_);                                     \
        unsigned _r = __shfl_xor_sync(m, _w, o_);                             \
        dd_ = __hadd2(dd_, *(__half2*)&_r);                                   \
    }

#define EDGE_ACC(ea_, a_g, a_i)                                               \
    {                                                                         \
        float2 k01 = __half22float2(*(__half2*)&(ea_).x);                     \
        float2 k23 = __half22float2(*(__half2*)&(ea_).y);                     \
        AG.x = fmaf(a_g, k01.x, AG.x); AG.y = fmaf(a_g, k01.y, AG.y);         \
        AG.z = fmaf(a_g, k23.x, AG.z); AG.w = fmaf(a_g, k23.y, AG.w);         \
        AI.x = fmaf(a_i, k01.x, AI.x); AI.y = fmaf(a_i, k01.y, AI.y);         \
        AI.z = fmaf(a_i, k23.x, AI.z); AI.w = fmaf(a_i, k23.y, AI.w);         \
        rsg += a_g; rsi += a_i;                                               \
    }

__global__ void __launch_bounds__(256)
fused_alpha_kernel(int layer,
                   const float* __restrict__ gnn, const float* __restrict__ itl,
                   float* __restrict__ gaa, float* __restrict__ iaa,
                   float* __restrict__ finalOut) {
    const __half* __restrict__ ekhIn  = layer ? g_ekhB : g_ekhA;
    __half*       __restrict__ ekhOut = layer ? g_ekhA : g_ekhB;
    int t0 = blockIdx.x * blockDim.x + threadIdx.x;
    int g = t0 >> 4;
    int l = threadIdx.x & 15;
    unsigned m = 0xFFFFu << (threadIdx.x & 16);
    size_t ro = (size_t)g * DD + l * 4;
    const uint4* __restrict__ nrm4 = (const uint4*)g_nrm;
    const uint2* __restrict__ ekh2 = (const uint2*)ekhIn;

    uint4 hn = nrm4[(size_t)g * 16 + l];
    __half2 hgx = *(__half2*)&hn.x, hgy = *(__half2*)&hn.y;
    __half2 hix = *(__half2*)&hn.z, hiy = *(__half2*)&hn.w;

    float4 AG = make_float4(0.f, 0.f, 0.f, 0.f);
    float4 AI = make_float4(0.f, 0.f, 0.f, 0.f);
    float rsg = 0.f, rsi = 0.f;

    int s = g_rowptr[g], e = g_rowptr[g + 1];
    int p = s;
    for (; p + 3 < e; p += 4) {
        int ta = __ldg(&g_edge[p].x);
        int tb = __ldg(&g_edge[p + 1].x);
        int tc = __ldg(&g_edge[p + 2].x);
        int td = __ldg(&g_edge[p + 3].x);
        uint4 na = nrm4[(size_t)ta * 16 + l];
        uint4 nb = nrm4[(size_t)tb * 16 + l];
        uint4 nc = nrm4[(size_t)tc * 16 + l];
        uint4 nd = nrm4[(size_t)td * 16 + l];
        uint2 ea = ekh2[(size_t)ta * 16 + l];
        uint2 eb = ekh2[(size_t)tb * 16 + l];
        uint2 ec = ekh2[(size_t)tc * 16 + l];
        uint2 ed = ekh2[(size_t)td * 16 + l];

        __half2 dda, ddb, ddc, ddd;
        EDGE_DOT_P(na, dda);
        EDGE_DOT_P(nb, ddb);
        EDGE_DOT_P(nc, ddc);
        EDGE_DOT_P(nd, ddd);
#pragma unroll
        for (int o = 8; o > 0; o >>= 1) {
            H2SHFL(dda, o);
            H2SHFL(ddb, o);
            H2SHFL(ddc, o);
            H2SHFL(ddd, o);
        }
        float2 dfa = __half22float2(dda);
        float2 dfb = __half22float2(ddb);
        float2 dfc = __half22float2(ddc);
        float2 dfd = __half22float2(ddd);
        float aga = (dfa.x + 1.f) * 0.5f, aia = (dfa.y + 1.f) * 0.5f;
        float agb = (dfb.x + 1.f) * 0.5f, aib = (dfb.y + 1.f) * 0.5f;
        float agc = (dfc.x + 1.f) * 0.5f, aic = (dfc.y + 1.f) * 0.5f;
        float agd = (dfd.x + 1.f) * 0.5f, aid = (dfd.y + 1.f) * 0.5f;
        EDGE_ACC(ea, aga, aia);
        EDGE_ACC(eb, agb, aib);
        EDGE_ACC(ec, agc, aic);
        EDGE_ACC(ed, agd, aid);
    }
    for (; p < e; p++) {
        int ta = __ldg(&g_edge[p].x);
        uint4 na = nrm4[(size_t)ta * 16 + l];
        uint2 ea = ekh2[(size_t)ta * 16 + l];
        __half2 dda;
        EDGE_DOT_P(na, dda);
#pragma unroll
        for (int o = 8; o > 0; o >>= 1) H2SHFL(dda, o);
        float2 dfa = __half22float2(dda);
        float aga = (dfa.x + 1.f) * 0.5f, aia = (dfa.y + 1.f) * 0.5f;
        EDGE_ACC(ea, aga, aia);
    }
    float dg_inv = rsg > 0.f ? 1.f / rsg : 0.f;
    float di_inv = rsi > 0.f ? 1.f / rsi : 0.f;
    float4 gv = make_float4(AG.x * dg_inv, AG.y * dg_inv, AG.z * dg_inv, AG.w * dg_inv);
    float4 iv = make_float4(AI.x * di_inv, AI.y * di_inv, AI.z * di_inv, AI.w * di_inv);
    *(float4*)(gaa + ro) = gv;
    *(float4*)(iaa + ro) = iv;

    // combine: e_{l+1} = gnn + intl + gaa + iaa + ek (ek from fp16)
    float4 hg0 = *(const float4*)(gnn + ro);
    float4 hi0 = *(const float4*)(itl + ro);
    uint2 ekc = ekh2[(size_t)g * 16 + l];
    float2 ek01 = __half22float2(*(__half2*)&ekc.x);
    float2 ek23 = __half22float2(*(__half2*)&ekc.y);
    float4 en;
    en.x = hg0.x + hi0.x + gv.x + iv.x + ek01.x;
    en.y = hg0.y + hi0.y + gv.y + iv.y + ek01.y;
    en.z = hg0.z + hi0.z + gv.z + iv.z + ek23.x;
    en.w = hg0.w + hi0.w + gv.w + iv.w + ek23.y;
    if (finalOut) {
        // final = e0 + e1 + e2 ; e0 lives in g_ekhA, e1 = ekhIn (=g_ekhB)
        uint2 e0c = ((const uint2*)g_ekhA)[(size_t)g * 16 + l];
        float2 z01 = __half22float2(*(__half2*)&e0c.x);
        float2 z23 = __half22float2(*(__half2*)&e0c.y);
        float4 ac;
        ac.x = z01.x + ek01.x + en.x;
        ac.y = z01.y + ek01.y + en.y;
        ac.z = z23.x + ek23.x + en.z;
        ac.w = z23.y + ek23.y + en.w;
        *(float4*)(finalOut + ro) = ac;
    } else {
        __half2 h0 = __floats2half2_rn(en.x, en.y);
        __half2 h1 = __floats2half2_rn(en.z, en.w);
        uint2 u; u.x = *(unsigned*)&h0; u.y = *(unsigned*)&h1;
        ((uint2*)ekhOut)[(size_t)g * 16 + l] = u;
    }
}

// ---------------- launch ----------------
extern "C" void kernel_launch(void* const* d_in, const int* in_sizes, int n_in,
                              void* d_out, int out_size) {
    const float* user_emb = (const float*)d_in[0];
    const float* item_emb = (const float*)d_in[1];
    const float* Wu       = (const float*)d_in[2];
    const float* Wi       = (const float*)d_in[3];
    const float* adj      = (const float*)d_in[4];
    const int*   h        = (const int*)d_in[5];
    const int*   t        = (const int*)d_in[6];
    (void)in_sizes; (void)n_in; (void)out_size;

    float* out = (float*)d_out;
    const size_t ND = (size_t)NN * DD;
    float* out_ua  = out;                    // [N*D] = ua | ia
    float* out_gnn = out + ND;               // [L][N][D]
    float* out_int = out_gnn + (size_t)LL * ND;
    float* out_gaa = out_int + (size_t)LL * ND;
    float* out_iaa = out_gaa + (size_t)LL * ND;

    cudaFuncSetAttribute(phase1_kernel, cudaFuncAttributeMaxDynamicSharedMemorySize, IT_SMEM_BYTES);

    const int TPB = 256;
    const int SCAN_NB = (NN + 1023) / 1024;  // 147
    init_ek_kernel<<<(NN * DD / 4 + TPB - 1) / TPB, TPB>>>((const float4*)user_emb,
                                                           (const float4*)item_emb);
    hist_kernel<<<(EE / 4 + TPB - 1) / TPB, TPB>>>((const int4*)h);
    reduce_scan_kernel<<<SCAN_NB, 1024>>>();
    apply_scan_kernel<<<SCAN_NB, 1024>>>();
    scatter_kernel<<<(EE / 4 + TPB - 1) / TPB, TPB>>>((const int4*)h, (const int4*)t,
                                                      (const float4*)adj);

    const int NODE_BLOCKS = NN * 16 / TPB;   // 9375
    for (int l = 0; l < LL; l++) {
        float* gnn = out_gnn + (size_t)l * ND;
        float* itl = out_int + (size_t)l * ND;
        float* gaa = out_gaa + (size_t)l * ND;
        float* iaa = out_iaa + (size_t)l * ND;

        phase1_kernel<<<NB_I + NB_SP, TPB, IT_SMEM_BYTES>>>(l, Wu, Wi, gnn, itl);
        fused_alpha_kernel<<<NODE_BLOCKS, TPB>>>(l, gnn, itl, gaa, iaa,
                                                 (l == LL - 1) ? out_ua : nullptr);
    }
}

// round 13
// speedup vs baseline: 1.8661x; 1.0201x over previous
#include <cuda_runtime.h>
#include <cuda_fp16.h>
#include <mma.h>

using namespace nvcuda;

// ---------------- problem constants ----------------
#define UN  100000
#define INC 50000
#define NN  150000
#define DD  64
#define KK  128
#define EE  1250000
#define LL  2

typedef unsigned long long u64;

// ---------------- device scratch (static; no allocations) ----------------
__device__ __half g_ekhA[NN * DD];    // e0 (layer0 in), preserved through layer1
__device__ __half g_ekhB[NN * DD];    // e1 (layer1 in)
__device__ int   g_cnt[NN];           // zeroed by scatter of PREVIOUS call (BSS-zero first call)
__device__ int   g_rowptr[NN + 1];
__device__ int   g_wp[NN];
__device__ int2  g_edge[EE];          // {tail, adj-as-int} in CSR order
// packed normalized vectors: per node 16 chunks of 16B; chunk c = {gnn̂[4c..4c+3], itl̂[4c..4c+3]} fp16
__device__ __half g_nrm[NN * 128];
__device__ float g_normg[NN];         // |gnn| per node
__device__ float g_normi[NN];         // |itl| per node
__device__ int   g_bsum[160];
__device__ int   g_boff[160];
__device__ int   g_done;              // reset by reduce_scan's last block (BSS-zero first call)

// ---------------- fused init_ek ∥ hist (disjoint writes; block-split) ----------------
#define NB_INIT (NN * DD / 4 / 256)        // 9375
#define NB_HIST ((EE / 4 + 255) / 256)     // 1221

__global__ void init_hist_kernel(const float4* __restrict__ ue, const float4* __restrict__ ie,
                                 const int4* __restrict__ h4) {
    int bx = blockIdx.x;
    if (bx < NB_INIT) {
        int i = bx * 256 + threadIdx.x;
        const int UD4 = UN * DD / 4;
        float4 v = (i < UD4) ? ue[i] : ie[i - UD4];
        __half2 h0 = __floats2half2_rn(v.x, v.y);
        __half2 h1 = __floats2half2_rn(v.z, v.w);
        uint2 u; u.x = *(unsigned*)&h0; u.y = *(unsigned*)&h1;
        ((uint2*)g_ekhA)[i] = u;
    } else {
        int i = (bx - NB_INIT) * 256 + threadIdx.x;
        if (i >= EE / 4) return;
        int4 v = __ldg(h4 + i);
        atomicAdd(&g_cnt[v.x], 1);
        atomicAdd(&g_cnt[v.y], 1);
        atomicAdd(&g_cnt[v.z], 1);
        atomicAdd(&g_cnt[v.w], 1);
    }
}

__global__ void reduce_scan_kernel() {
    __shared__ int s[1024];
    __shared__ bool amLast;
    int tid = threadIdx.x;
    int idx = blockIdx.x * 1024 + tid;
    s[tid] = (idx < NN) ? g_cnt[idx] : 0;
    __syncthreads();
    for (int o = 512; o > 0; o >>= 1) {
        if (tid < o) s[tid] += s[tid + o];
        __syncthreads();
    }
    if (tid == 0) {
        g_bsum[blockIdx.x] = s[0];
        __threadfence();
        amLast = (atomicAdd(&g_done, 1) == gridDim.x - 1);
    }
    __syncthreads();
    if (amLast) {
        int nblk = gridDim.x;
        int v = (tid < nblk) ? g_bsum[tid] : 0;
        s[tid] = v;
        __syncthreads();
        for (int off = 1; off < 1024; off <<= 1) {
            int t = (tid >= off) ? s[tid - off] : 0;
            __syncthreads();
            s[tid] += t;
            __syncthreads();
        }
        if (tid < nblk) g_boff[tid] = s[tid] - v;   // exclusive
        if (tid == 0) g_done = 0;                    // reset for next replay
    }
}

__global__ void apply_scan_kernel() {
    __shared__ int s[1024];
    int tid = threadIdx.x;
    int idx = blockIdx.x * 1024 + tid;
    int v = (idx < NN) ? g_cnt[idx] : 0;
    s[tid] = v;
    __syncthreads();
    for (int off = 1; off < 1024; off <<= 1) {
        int t = (tid >= off) ? s[tid - off] : 0;
        __syncthreads();
        s[tid] += t;
        __syncthreads();
    }
    int excl = s[tid] - v + g_boff[blockIdx.x];
    if (idx < NN) { g_rowptr[idx] = excl; g_wp[idx] = excl; }
    if (blockIdx.x == 0 && tid == 0) g_rowptr[NN] = EE;
}

__global__ void scatter_kernel(const int4* __restrict__ h4, const int4* __restrict__ t4,
                               const float4* __restrict__ adj4) {
    int i = blockIdx.x * blockDim.x + threadIdx.x;
    if (i < NN) g_cnt[i] = 0;          // pre-zero for NEXT replay's hist
    if (i >= EE / 4) return;
    int4  hv = __ldg(h4 + i);
    int4  tv = __ldg(t4 + i);
    float4 av = __ldg(adj4 + i);
    int p0 = atomicAdd(&g_wp[hv.x], 1);
    int p1 = atomicAdd(&g_wp[hv.y], 1);
    int p2 = atomicAdd(&g_wp[hv.z], 1);
    int p3 = atomicAdd(&g_wp[hv.w], 1);
    g_edge[p0] = make_int2(tv.x, __float_as_int(av.x));
    g_edge[p1] = make_int2(tv.y, __float_as_int(av.y));
    g_edge[p2] = make_int2(tv.z, __float_as_int(av.z));
    g_edge[p3] = make_int2(tv.w, __float_as_int(av.w));
}

// ---------------- smem layout for tensor-core intent (TM=64) ----------------
#define TM 64
#define WH_LD 136
#define AH_LD 72
#define PH_LD 136
#define PS_LD 132
#define IT_SMEM_BYTES (17408 + 17408 + 33792)   // 68608

// ---------------- spmm body (16-lane group per node); fp16 gathers; gnn + gnn̂ + |gnn| ----------------
__device__ __forceinline__ void spmm_body(int layer, float* __restrict__ out, int bx) {
    const __half* __restrict__ ekhIn = layer ? g_ekhB : g_ekhA;
    const uint2* __restrict__ ekh2 = (const uint2*)ekhIn;
    int t0 = bx * 256 + threadIdx.x;
    int g = t0 >> 4;
    int l = threadIdx.x & 15;
    unsigned m = 0xFFFFu << (threadIdx.x & 16);
    int s = g_rowptr[g], e = g_rowptr[g + 1];
    float4 acc = make_float4(0.f, 0.f, 0.f, 0.f);

    int p = s;
    for (; p + 3 < e; p += 4) {
        int2 e0 = __ldg(g_edge + p);
        int2 e1 = __ldg(g_edge + p + 1);
        int2 e2 = __ldg(g_edge + p + 2);
        int2 e3 = __ldg(g_edge + p + 3);
        uint2 x0 = ekh2[(size_t)e0.x * 16 + l];
        uint2 x1 = ekh2[(size_t)e1.x * 16 + l];
        uint2 x2 = ekh2[(size_t)e2.x * 16 + l];
        uint2 x3 = ekh2[(size_t)e3.x * 16 + l];
        float v0 = __int_as_float(e0.y), v1 = __int_as_float(e1.y);
        float v2 = __int_as_float(e2.y), v3 = __int_as_float(e3.y);
        float2 a01, a23;
        a01 = __half22float2(*(__half2*)&x0.x); a23 = __half22float2(*(__half2*)&x0.y);
        acc.x = fmaf(v0, a01.x, acc.x); acc.y = fmaf(v0, a01.y, acc.y);
        acc.z = fmaf(v0, a23.x, acc.z); acc.w = fmaf(v0, a23.y, acc.w);
        a01 = __half22float2(*(__half2*)&x1.x); a23 = __half22float2(*(__half2*)&x1.y);
        acc.x = fmaf(v1, a01.x, acc.x); acc.y = fmaf(v1, a01.y, acc.y);
        acc.z = fmaf(v1, a23.x, acc.z); acc.w = fmaf(v1, a23.y, acc.w);
        a01 = __half22float2(*(__half2*)&x2.x); a23 = __half22float2(*(__half2*)&x2.y);
        acc.x = fmaf(v2, a01.x, acc.x); acc.y = fmaf(v2, a01.y, acc.y);
        acc.z = fmaf(v2, a23.x, acc.z); acc.w = fmaf(v2, a23.y, acc.w);
        a01 = __half22float2(*(__half2*)&x3.x); a23 = __half22float2(*(__half2*)&x3.y);
        acc.x = fmaf(v3, a01.x, acc.x); acc.y = fmaf(v3, a01.y, acc.y);
        acc.z = fmaf(v3, a23.x, acc.z); acc.w = fmaf(v3, a23.y, acc.w);
    }
    for (; p < e; p++) {
        int2 e0 = __ldg(g_edge + p);
        uint2 x0 = ekh2[(size_t)e0.x * 16 + l];
        float v0 = __int_as_float(e0.y);
        float2 a01 = __half22float2(*(__half2*)&x0.x);
        float2 a23 = __half22float2(*(__half2*)&x0.y);
        acc.x = fmaf(v0, a01.x, acc.x); acc.y = fmaf(v0, a01.y, acc.y);
        acc.z = fmaf(v0, a23.x, acc.z); acc.w = fmaf(v0, a23.y, acc.w);
    }
    *(float4*)(out + (size_t)g * DD + l * 4) = acc;
    float sg = acc.x * acc.x + acc.y * acc.y + acc.z * acc.z + acc.w * acc.w;
#pragma unroll
    for (int o = 8; o > 0; o >>= 1) sg += __shfl_xor_sync(m, sg, o);
    float rt  = fmaxf(sqrtf(sg), 1e-12f);
    float inv = 1.f / rt;
    if (l == 0) g_normg[g] = rt;
    __half2 h0 = __floats2half2_rn(acc.x * inv, acc.y * inv);
    __half2 h1 = __floats2half2_rn(acc.z * inv, acc.w * inv);
    uint2 u;
    u.x = *(unsigned*)&h0;
    u.y = *(unsigned*)&h1;
    ((uint2*)g_nrm)[(size_t)g * 32 + l * 2] = u;   // g-part of chunk l
}

// ---------------- intent body (tensor cores): softmax(ek@W)@W^T per 64-row tile ----------------
__device__ __forceinline__ void intent_body(int layer, const float* __restrict__ W,
                                            float* __restrict__ outIntl,
                                            int nodeBase, int nodeCount, int bx) {
    const __half* __restrict__ ekhIn = layer ? g_ekhB : g_ekhA;
    extern __shared__ char smc[];
    __half* Wh = (__half*)smc;                  // [64][136]
    __half* Ah = (__half*)(smc + 17408);        // [64][72]  (dead after GEMM1)
    __half* Ph = (__half*)(smc + 17408);        // [64][136] (overlays Ah)
    float*  Ps = (float*)(smc + 34816);         // [64][132]

    int tid = threadIdx.x;
    int warp = tid >> 5, lane = tid & 31;
    int rowTile = bx * TM;

    // load W (fp32 -> fp16) into Wh
#pragma unroll
    for (int it = 0; it < 8; it++) {
        int i = tid + it * 256;                  // float4 index
        float4 v = __ldg((const float4*)W + i);
        int d  = i >> 5;
        int k4 = (i & 31) * 4;
        __half2 h0 = __floats2half2_rn(v.x, v.y);
        __half2 h1 = __floats2half2_rn(v.z, v.w);
        uint2 u; u.x = *(unsigned*)&h0; u.y = *(unsigned*)&h1;
        *(uint2*)(Wh + d * WH_LD + k4) = u;
    }
    // load A rows from fp16 ek
    {
        int row = tid >> 2;
        int seg = tid & 3;
        uint4 z0 = make_uint4(0, 0, 0, 0), z1 = make_uint4(0, 0, 0, 0);
        int r = rowTile + row;
        if (r < nodeCount) {
            const uint4* src = (const uint4*)(ekhIn + (size_t)(nodeBase + r) * DD) + seg * 2;
            z0 = src[0]; z1 = src[1];
        }
        uint4* dst = (uint4*)(Ah + row * AH_LD + seg * 16);
        dst[0] = z0; dst[1] = z1;
    }
    __syncthreads();

    // GEMM1: logits[64][128] = A[64][64] @ W[64][128]
    {
        int wm = warp >> 1, wn = warp & 1;
        wmma::fragment<wmma::matrix_a, 16, 16, 16, __half, wmma::row_major> a[4];
#pragma unroll
        for (int kt = 0; kt < 4; kt++)
            wmma::load_matrix_sync(a[kt], Ah + wm * 16 * AH_LD + kt * 16, AH_LD);
#pragma unroll
        for (int nt = 0; nt < 4; nt++) {
            wmma::fragment<wmma::accumulator, 16, 16, 16, float> c;
            wmma::fill_fragment(c, 0.f);
#pragma unroll
            for (int kt = 0; kt < 4; kt++) {
                wmma::fragment<wmma::matrix_b, 16, 16, 16, __half, wmma::row_major> b;
                wmma::load_matrix_sync(b, Wh + kt * 16 * WH_LD + wn * 64 + nt * 16, WH_LD);
                wmma::mma_sync(c, a[kt], b, c);
            }
            wmma::store_matrix_sync(Ps + wm * 16 * PS_LD + wn * 64 + nt * 16, c, PS_LD,
                                    wmma::mem_row_major);
        }
    }
    __syncthreads();

    // row softmax on Ps (fp32), write probs fp16 to Ph
    for (int rr = warp; rr < TM; rr += 8) {
        float4 v = *(float4*)(Ps + rr * PS_LD + lane * 4);
        float mx = fmaxf(fmaxf(v.x, v.y), fmaxf(v.z, v.w));
#pragma unroll
        for (int o = 16; o > 0; o >>= 1) mx = fmaxf(mx, __shfl_xor_sync(0xffffffffu, mx, o));
        float e0 = __expf(v.x - mx), e1 = __expf(v.y - mx);
        float e2 = __expf(v.z - mx), e3 = __expf(v.w - mx);
        float sum = e0 + e1 + e2 + e3;
#pragma unroll
        for (int o = 16; o > 0; o >>= 1) sum += __shfl_xor_sync(0xffffffffu, sum, o);
        float inv = 1.0f / sum;
        __half2 h0 = __floats2half2_rn(e0 * inv, e1 * inv);
        __half2 h1 = __floats2half2_rn(e2 * inv, e3 * inv);
        uint2 u; u.x = *(unsigned*)&h0; u.y = *(unsigned*)&h1;
        *(uint2*)(Ph + rr * PH_LD + lane * 4) = u;
    }
    __syncthreads();

    // GEMM2: out[64][64] = P[64][128] @ W^T[128][64]
    {
        int wm = warp >> 1, wn = warp & 1;
#pragma unroll
        for (int nt = 0; nt < 2; nt++) {
            wmma::fragment<wmma::accumulator, 16, 16, 16, float> c;
            wmma::fill_fragment(c, 0.f);
#pragma unroll
            for (int kt = 0; kt < 8; kt++) {
                wmma::fragment<wmma::matrix_a, 16, 16, 16, __half, wmma::row_major> a;
                wmma::fragment<wmma::matrix_b, 16, 16, 16, __half, wmma::col_major> b;
                wmma::load_matrix_sync(a, Ph + wm * 16 * PH_LD + kt * 16, PH_LD);
                wmma::load_matrix_sync(b, Wh + (wn * 32 + nt * 16) * WH_LD + kt * 16, WH_LD);
                wmma::mma_sync(c, a, b, c);
            }
            wmma::store_matrix_sync(Ps + wm * 16 * PS_LD + wn * 32 + nt * 16, c, PS_LD,
                                    wmma::mem_row_major);
        }
    }
    __syncthreads();

    // epilogue: store itl (fp32) + row norms (|itl| to g_normi) + g_nrm i-part (fp16)
    for (int rr = warp; rr < TM; rr += 8) {
        float2 v = *(float2*)(Ps + rr * PS_LD + lane * 2);
        float ns = v.x * v.x + v.y * v.y;
#pragma unroll
        for (int o = 16; o > 0; o >>= 1) ns += __shfl_xor_sync(0xffffffffu, ns, o);
        float rt  = fmaxf(sqrtf(ns), 1e-12f);
        float inv = 1.f / rt;
        __half2 hv = __floats2half2_rn(v.x * inv, v.y * inv);
        unsigned lo = *(unsigned*)&hv;
        unsigned hi = __shfl_down_sync(0xffffffffu, lo, 1);
        int r = rowTile + rr;
        if (r < nodeCount) {
            *(float2*)(outIntl + (size_t)(nodeBase + r) * DD + lane * 2) = v;
            if (lane == 0) g_normi[nodeBase + r] = rt;
            if ((lane & 1) == 0) {
                uint2 u; u.x = lo; u.y = hi;
                ((uint2*)g_nrm)[(size_t)(nodeBase + r) * 32 + (lane >> 1) * 2 + 1] = u;
            }
        }
    }
}

// ---------------- merged phase-1 kernel: interleaved intent/spmm dispatch ----------------
#define NB_IU ((UN + TM - 1) / TM)      // 1563
#define NB_II ((INC + TM - 1) / TM)     // 782
#define NB_I  (NB_IU + NB_II)           // 2345
#define NB_SP (NN * 16 / 256)           // 9375

__global__ void __launch_bounds__(256)
phase1_kernel(int layer, const float* __restrict__ Wu, const float* __restrict__ Wi,
              float* __restrict__ gnn, float* __restrict__ itl) {
    int bx = blockIdx.x;
    int k = bx >> 2;
    if ((bx & 3) == 0 && k < NB_I) {
        if (k < NB_IU) intent_body(layer, Wu, itl, 0, UN, k);
        else           intent_body(layer, Wi, itl, UN, INC, k - NB_IU);
    } else {
        int before = (bx >> 2) + 1;
        if (before > NB_I) before = NB_I;
        spmm_body(layer, gnn, bx - before);
    }
}

// ---------------- fused alpha + spmm2 + combine (16-lane group per node) ----------------
#define EDGE_DOT_P(na_, dd_)                                                  \
    {                                                                         \
        __half2 pg = __hfma2(hgy, *(__half2*)&(na_).y,                        \
                             __hmul2(hgx, *(__half2*)&(na_).x));              \
        __half2 pi = __hfma2(hiy, *(__half2*)&(na_).w,                        \
                             __hmul2(hix, *(__half2*)&(na_).z));              \
        dd_ = __halves2half2(__hadd(__low2half(pg), __high2half(pg)),         \
                             __hadd(__low2half(pi), __high2half(pi)));        \
    }

#define H2SHFL(dd_, o_)                                                       \
    {                                                                         \
        unsigned _w = *(unsigned*)&(dd_);                                     \
        unsigned _r = __shfl_xor_sync(m, _w, o_);                             \
        dd_ = __hadd2(dd_, *(__half2*)&_r);                                   \
    }

#define EDGE_ACC(ea_, a_g, a_i)                                               \
    {                                                                         \
        float2 k01 = __half22float2(*(__half2*)&(ea_).x);                     \
        float2 k23 = __half22float2(*(__half2*)&(ea_).y);                     \
        AG.x = fmaf(a_g, k01.x, AG.x); AG.y = fmaf(a_g, k01.y, AG.y);         \
        AG.z = fmaf(a_g, k23.x, AG.z); AG.w = fmaf(a_g, k23.y, AG.w);         \
        AI.x = fmaf(a_i, k01.x, AI.x); AI.y = fmaf(a_i, k01.y, AI.y);         \
        AI.z = fmaf(a_i, k23.x, AI.z); AI.w = fmaf(a_i, k23.y, AI.w);         \
        rsg += a_g; rsi += a_i;                                               \
    }

__global__ void __launch_bounds__(256)
fused_alpha_kernel(int layer,
                   float* __restrict__ gaa, float* __restrict__ iaa,
                   float* __restrict__ finalOut) {
    const __half* __restrict__ ekhIn  = layer ? g_ekhB : g_ekhA;
    __half*       __restrict__ ekhOut = layer ? g_ekhA : g_ekhB;
    int t0 = blockIdx.x * blockDim.x + threadIdx.x;
    int g = t0 >> 4;
    int l = threadIdx.x & 15;
    unsigned m = 0xFFFFu << (threadIdx.x & 16);
    size_t ro = (size_t)g * DD + l * 4;
    const uint4* __restrict__ nrm4 = (const uint4*)g_nrm;
    const uint2* __restrict__ ekh2 = (const uint2*)ekhIn;

    uint4 hn = nrm4[(size_t)g * 16 + l];
    __half2 hgx = *(__half2*)&hn.x, hgy = *(__half2*)&hn.y;
    __half2 hix = *(__half2*)&hn.z, hiy = *(__half2*)&hn.w;
    float ng = g_normg[g], ni = g_normi[g];

    float4 AG = make_float4(0.f, 0.f, 0.f, 0.f);
    float4 AI = make_float4(0.f, 0.f, 0.f, 0.f);
    float rsg = 0.f, rsi = 0.f;

    int s = g_rowptr[g], e = g_rowptr[g + 1];
    int p = s;
    for (; p + 3 < e; p += 4) {
        int ta = __ldg(&g_edge[p].x);
        int tb = __ldg(&g_edge[p + 1].x);
        int tc = __ldg(&g_edge[p + 2].x);
        int td = __ldg(&g_edge[p + 3].x);
        uint4 na = nrm4[(size_t)ta * 16 + l];
        uint4 nb = nrm4[(size_t)tb * 16 + l];
        uint4 nc = nrm4[(size_t)tc * 16 + l];
        uint4 nd = nrm4[(size_t)td * 16 + l];
        uint2 ea = ekh2[(size_t)ta * 16 + l];
        uint2 eb = ekh2[(size_t)tb * 16 + l];
        uint2 ec = ekh2[(size_t)tc * 16 + l];
        uint2 ed = ekh2[(size_t)td * 16 + l];

        __half2 dda, ddb, ddc, ddd;
        EDGE_DOT_P(na, dda);
        EDGE_DOT_P(nb, ddb);
        EDGE_DOT_P(nc, ddc);
        EDGE_DOT_P(nd, ddd);
#pragma unroll
        for (int o = 8; o > 0; o >>= 1) {
            H2SHFL(dda, o);
            H2SHFL(ddb, o);
            H2SHFL(ddc, o);
            H2SHFL(ddd, o);
        }
        float2 dfa = __half22float2(dda);
        float2 dfb = __half22float2(ddb);
        float2 dfc = __half22float2(ddc);
        float2 dfd = __half22float2(ddd);
        float aga = (dfa.x + 1.f) * 0.5f, aia = (dfa.y + 1.f) * 0.5f;
        float agb = (dfb.x + 1.f) * 0.5f, aib = (dfb.y + 1.f) * 0.5f;
        float agc = (dfc.x + 1.f) * 0.5f, aic = (dfc.y + 1.f) * 0.5f;
        float agd = (dfd.x + 1.f) * 0.5f, aid = (dfd.y + 1.f) * 0.5f;
        EDGE_ACC(ea, aga, aia);
        EDGE_ACC(eb, agb, aib);
        EDGE_ACC(ec, agc, aic);
        EDGE_ACC(ed, agd, aid);
    }
    for (; p < e; p++) {
        int ta = __ldg(&g_edge[p].x);
        uint4 na = nrm4[(size_t)ta * 16 + l];
        uint2 ea = ekh2[(size_t)ta * 16 + l];
        __half2 dda;
        EDGE_DOT_P(na, dda);
#pragma unroll
        for (int o = 8; o > 0; o >>= 1) H2SHFL(dda, o);
        float2 dfa = __half22float2(dda);
        float aga = (dfa.x + 1.f) * 0.5f, aia = (dfa.y + 1.f) * 0.5f;
        EDGE_ACC(ea, aga, aia);
    }
    float dg_inv = rsg > 0.f ? 1.f / rsg : 0.f;
    float di_inv = rsi > 0.f ? 1.f / rsi : 0.f;
    float4 gv = make_float4(AG.x * dg_inv, AG.y * dg_inv, AG.z * dg_inv, AG.w * dg_inv);
    float4 iv = make_float4(AI.x * di_inv, AI.y * di_inv, AI.z * di_inv, AI.w * di_inv);
    *(float4*)(gaa + ro) = gv;
    *(float4*)(iaa + ro) = iv;

    // combine: e_{l+1} = gnn + intl + gaa + iaa + ek
    // gnn/itl rows reconstructed from registers: |gnn|·ĝ, |itl|·î
    float2 hg01 = __half22float2(hgx), hg23 = __half22float2(hgy);
    float2 hi01 = __half22float2(hix), hi23 = __half22float2(hiy);
    uint2 ekc = ekh2[(size_t)g * 16 + l];
    float2 ek01 = __half22float2(*(__half2*)&ekc.x);
    float2 ek23 = __half22float2(*(__half2*)&ekc.y);
    float4 en;
    en.x = fmaf(ng, hg01.x, fmaf(ni, hi01.x, gv.x + iv.x + ek01.x));
    en.y = fmaf(ng, hg01.y, fmaf(ni, hi01.y, gv.y + iv.y + ek01.y));
    en.z = fmaf(ng, hg23.x, fmaf(ni, hi23.x, gv.z + iv.z + ek23.x));
    en.w = fmaf(ng, hg23.y, fmaf(ni, hi23.y, gv.w + iv.w + ek23.y));
    if (finalOut) {
        // final = e0 + e1 + e2 ; e0 lives in g_ekhA, e1 = ekhIn (=g_ekhB)
        uint2 e0c = ((const uint2*)g_ekhA)[(size_t)g * 16 + l];
        float2 z01 = __half22float2(*(__half2*)&e0c.x);
        float2 z23 = __half22float2(*(__half2*)&e0c.y);
        float4 ac;
        ac.x = z01.x + ek01.x + en.x;
        ac.y = z01.y + ek01.y + en.y;
        ac.z = z23.x + ek23.x + en.z;
        ac.w = z23.y + ek23.y + en.w;
        *(float4*)(finalOut + ro) = ac;
    } else {
        __half2 h0 = __floats2half2_rn(en.x, en.y);
        __half2 h1 = __floats2half2_rn(en.z, en.w);
        uint2 u; u.x = *(unsigned*)&h0; u.y = *(unsigned*)&h1;
        ((uint2*)ekhOut)[(size_t)g * 16 + l] = u;
    }
}

// ---------------- launch ----------------
extern "C" void kernel_launch(void* const* d_in, const int* in_sizes, int n_in,
                              void* d_out, int out_size) {
    const float* user_emb = (const float*)d_in[0];
    const float* item_emb = (const float*)d_in[1];
    const float* Wu       = (const float*)d_in[2];
    const float* Wi       = (const float*)d_in[3];
    const float* adj      = (const float*)d_in[4];
    const int*   h        = (const int*)d_in[5];
    const int*   t        = (const int*)d_in[6];
    (void)in_sizes; (void)n_in; (void)out_size;

    float* out = (float*)d_out;
    const size_t ND = (size_t)NN * DD;
    float* out_ua  = out;                    // [N*D] = ua | ia
    float* out_gnn = out + ND;               // [L][N][D]
    float* out_int = out_gnn + (size_t)LL * ND;
    float* out_gaa = out_int + (size_t)LL * ND;
    float* out_iaa = out_gaa + (size_t)LL * ND;

    cudaFuncSetAttribute(phase1_kernel, cudaFuncAttributeMaxDynamicSharedMemorySize, IT_SMEM_BYTES);

    const int TPB = 256;
    const int SCAN_NB = (NN + 1023) / 1024;  // 147
    init_hist_kernel<<<NB_INIT + NB_HIST, TPB>>>((const float4*)user_emb,
                                                 (const float4*)item_emb,
                                                 (const int4*)h);
    reduce_scan_kernel<<<SCAN_NB, 1024>>>();
    apply_scan_kernel<<<SCAN_NB, 1024>>>();
    scatter_kernel<<<(EE / 4 + TPB - 1) / TPB, TPB>>>((const int4*)h, (const int4*)t,
                                                      (const float4*)adj);

    const int NODE_BLOCKS = NN * 16 / TPB;   // 9375
    for (int l = 0; l < LL; l++) {
        float* gnn = out_gnn + (size_t)l * ND;
        float* itl = out_int + (size_t)l * ND;
        float* gaa = out_gaa + (size_t)l * ND;
        float* iaa = out_iaa + (size_t)l * ND;

        phase1_kernel<<<NB_I + NB_SP, TPB, IT_SMEM_BYTES>>>(l, Wu, Wi, gnn, itl);
        fused_alpha_kernel<<<NODE_BLOCKS, TPB>>>(l, gaa, iaa,
                                                 (l == LL - 1) ? out_ua : nullptr);
    }
}